// round 12
// baseline (speedup 1.0000x reference)
#include <cuda_runtime.h>
#include <cuda_bf16.h>
#include <math.h>
#include <stdint.h>

#define Bb     512
#define Ss     64
#define Dd     128
#define Vv     256
#define NHs    4
#define HDs    32
#define INNERc 256
#define NHMc   4
#define DHMc   64
#define NBc    64
#define Kc     4
#define FFc    128
#define Tt     (Bb*Ss)   /* 32768 tokens */

// ---------------- workspaces (static device globals; no allocation) ----------
__device__ float g_h[Tt*Dd];            // residual stream
__device__ float g_big[Tt*2*INNERc];    // slstm gx [t][512]  OR  mlstm up out [t][512]
__device__ float g_ffn[Tt*2*FFc];       // ffn up output
__device__ float g_xconv[Tt*INNERc];
__device__ float g_q[Tt*INNERc];        // q, later reused as mlstm combine buffer
__device__ float g_k[Tt*INNERc];
__device__ float g_v[Tt*INNERc];
__device__ float g_ig[Bb*NHMc*Ss];
__device__ float g_fg[Bb*NHMc*Ss];

// all GEMM weights, transposed+split [N][K]
#define W_SGX(i)  ((i)*262144 + 0)
#define W_SFU(i)  ((i)*262144 + 65536)
#define W_SFD(i)  ((i)*262144 + 98304)
#define W_MUP(i)  ((i)*262144 + 114688)
#define W_MDN(i)  ((i)*262144 + 180224)
#define W_MFU(i)  ((i)*262144 + 212992)
#define W_MFD(i)  ((i)*262144 + 245760)
#define W_HEAD    (524288)
#define W_TOTAL   (557056)
__device__ __nv_bfloat16 g_wt_hi[W_TOTAL];
__device__ __nv_bfloat16 g_wt_lo[W_TOTAL];
__device__ float g_gw_eff[2*4096];      // folded gate weights [L][4][256][4]

// ---------------- device math helpers ---------------------------------------
__device__ __forceinline__ float sigf(float x){ return 1.0f/(1.0f+expf(-x)); }
__device__ __forceinline__ float logsigf(float x){ return fminf(x,0.0f) - log1pf(expf(-fabsf(x))); }
__device__ __forceinline__ float geluf(float x){
    float x3 = x*x*x;
    return 0.5f*x*(1.0f+tanhf(0.7978845608028654f*(x+0.044715f*x3)));
}
__device__ __forceinline__ uint32_t smem_u32(const void* p){
    uint32_t a;
    asm("{ .reg .u64 t; cvta.to.shared.u64 t, %1; cvt.u32.u64 %0, t; }" : "=r"(a) : "l"(p));
    return a;
}
__device__ __forceinline__ void split2(float a, float b, uint32_t &hi, uint32_t &lo){
    __nv_bfloat162 h = __floats2bfloat162_rn(a, b);
    float ra = a - __bfloat162float(h.x);
    float rb = b - __bfloat162float(h.y);
    __nv_bfloat162 l = __floats2bfloat162_rn(ra, rb);
    hi = *(uint32_t*)&h; lo = *(uint32_t*)&l;
}

#define LDM4(r0,r1,r2,r3,addr) \
    asm volatile("ldmatrix.sync.aligned.m8n8.x4.shared.b16 {%0,%1,%2,%3}, [%4];" \
        : "=r"(r0),"=r"(r1),"=r"(r2),"=r"(r3) : "r"(addr))

#define MMA16816(d,a,b) \
    asm volatile("mma.sync.aligned.m16n8k16.row.col.f32.bf16.bf16.f32 " \
        "{%0,%1,%2,%3}, {%4,%5,%6,%7}, {%8,%9}, {%0,%1,%2,%3};" \
        : "+f"((d)[0]),"+f"((d)[1]),"+f"((d)[2]),"+f"((d)[3]) \
        : "r"((a)[0]),"r"((a)[1]),"r"((a)[2]),"r"((a)[3]), "r"((b)[0]),"r"((b)[1]))

// smem layout: A tiles 128x136 bf16 (hi/lo), B tiles 64x136 bf16 (hi/lo)
#define MG_STRIDE 136
#define MG_AH 0
#define MG_AL (128*MG_STRIDE*2)
#define MG_BH (2*128*MG_STRIDE*2)
#define MG_BL (MG_BH + 64*MG_STRIDE*2)
#define MG_SMEM (MG_BL + 64*MG_STRIDE*2)   /* 104448 B */

// ---------------- tensor-core GEMM: C[M,N] (+)= f(A)[M,K] @ Wt^T (+bias) -----
// NB>1 requires K==128: A is staged ONCE, then NB 64-wide B sub-tiles are
// processed in a loop reusing the staged A. NB==1 keeps the multi-k-chunk path.
template<bool ADD, bool BIAS, bool LN, bool GLU, int NB>
__global__ void __launch_bounds__(256,2) k_mgemm(
        const float* __restrict__ A, float* __restrict__ C,
        const float* __restrict__ bias, const float* __restrict__ lnw,
        int woff, int N, int K){
    extern __shared__ char smem[];
    const int tid = threadIdx.x, w = tid>>5, lane = tid&31;
    const int bm = blockIdx.y*128;
    const int wm = w & 3, wn = w >> 2;
    const int gID = lane >> 2, qid = lane & 3;

    const int a_row = lane & 15;
    const int a_koff = (lane >> 4) * 8;
    const int b_noff = (lane & 7) + ((lane >> 4) & 1) * 8;
    const int b_koff = ((lane >> 3) & 1) * 8;

    const uint32_t sb = smem_u32(smem);

    auto stageA = [&](int kc){
        #pragma unroll
        for (int it = 0; it < 8; it++){
            int g4 = tid + it*256;
            int row = g4 >> 4, kg = g4 & 15;
            float4 v0, v1;
            if (GLU){
                const float* ap = A + (size_t)(bm+row)*256 + kg*8;
                float4 gg0 = *(const float4*)ap,      gg1 = *(const float4*)(ap+4);
                float4 uu0 = *(const float4*)(ap+128), uu1 = *(const float4*)(ap+132);
                v0.x = geluf(gg0.x)*uu0.x; v0.y = geluf(gg0.y)*uu0.y;
                v0.z = geluf(gg0.z)*uu0.z; v0.w = geluf(gg0.w)*uu0.w;
                v1.x = geluf(gg1.x)*uu1.x; v1.y = geluf(gg1.y)*uu1.y;
                v1.z = geluf(gg1.z)*uu1.z; v1.w = geluf(gg1.w)*uu1.w;
            } else {
                const float4* ap = (const float4*)(A + (size_t)(bm+row)*K + kc*128 + kg*8);
                v0 = ap[0]; v1 = ap[1];
            }
            if (LN){
                float s  = v0.x+v0.y+v0.z+v0.w + v1.x+v1.y+v1.z+v1.w;
                float ss = v0.x*v0.x+v0.y*v0.y+v0.z*v0.z+v0.w*v0.w
                         + v1.x*v1.x+v1.y*v1.y+v1.z*v1.z+v1.w*v1.w;
                #pragma unroll
                for (int o = 1; o < 16; o <<= 1){
                    s  += __shfl_xor_sync(~0u, s,  o);
                    ss += __shfl_xor_sync(~0u, ss, o);
                }
                float mu  = s*(1.0f/128.0f);
                float var = ss*(1.0f/128.0f) - mu*mu;
                float rr  = rsqrtf(var + 1e-5f);
                float4 w0 = *(const float4*)&lnw[kg*8];
                float4 w1 = *(const float4*)&lnw[kg*8+4];
                v0.x = (v0.x-mu)*rr*w0.x; v0.y = (v0.y-mu)*rr*w0.y;
                v0.z = (v0.z-mu)*rr*w0.z; v0.w = (v0.w-mu)*rr*w0.w;
                v1.x = (v1.x-mu)*rr*w1.x; v1.y = (v1.y-mu)*rr*w1.y;
                v1.z = (v1.z-mu)*rr*w1.z; v1.w = (v1.w-mu)*rr*w1.w;
            }
            uint32_t h0,h1,h2,h3, l0,l1,l2,l3;
            split2(v0.x, v0.y, h0, l0);
            split2(v0.z, v0.w, h1, l1);
            split2(v1.x, v1.y, h2, l2);
            split2(v1.z, v1.w, h3, l3);
            uint32_t off = (uint32_t)(row*(MG_STRIDE*2) + kg*16);
            *(uint4*)(smem + MG_AH + off) = make_uint4(h0,h1,h2,h3);
            *(uint4*)(smem + MG_AL + off) = make_uint4(l0,l1,l2,l3);
        }
    };
    auto stageB = [&](int bn, int kc){
        #pragma unroll
        for (int it = 0; it < 4; it++){
            int g4 = tid + it*256;
            int n = g4 >> 4, kg = g4 & 15;
            size_t gi = (size_t)woff + (size_t)(bn+n)*K + kc*128 + kg*8;
            uint4 hv = *(const uint4*)(g_wt_hi + gi);
            uint4 lv = *(const uint4*)(g_wt_lo + gi);
            uint32_t off = (uint32_t)(n*(MG_STRIDE*2) + kg*16);
            *(uint4*)(smem + MG_BH + off) = hv;
            *(uint4*)(smem + MG_BL + off) = lv;
        }
    };
    auto compute = [&](float (&acc)[2][4][4]){
        #pragma unroll
        for (int ks = 0; ks < 8; ks++){
            uint32_t ah[2][4], al[2][4];
            #pragma unroll
            for (int mt = 0; mt < 2; mt++){
                uint32_t aoff = (uint32_t)((wm*32 + mt*16 + a_row)*(MG_STRIDE*2)
                                           + (ks*16 + a_koff)*2);
                LDM4(ah[mt][0],ah[mt][1],ah[mt][2],ah[mt][3], sb + MG_AH + aoff);
                LDM4(al[mt][0],al[mt][1],al[mt][2],al[mt][3], sb + MG_AL + aoff);
            }
            uint32_t bh[4][2], bl[4][2];
            #pragma unroll
            for (int ng = 0; ng < 2; ng++){
                uint32_t boff = (uint32_t)((wn*32 + ng*16 + b_noff)*(MG_STRIDE*2)
                                           + (ks*16 + b_koff)*2);
                uint32_t r0,r1,r2,r3;
                LDM4(r0,r1,r2,r3, sb + MG_BH + boff);
                bh[ng*2][0]=r0; bh[ng*2][1]=r1; bh[ng*2+1][0]=r2; bh[ng*2+1][1]=r3;
                LDM4(r0,r1,r2,r3, sb + MG_BL + boff);
                bl[ng*2][0]=r0; bl[ng*2][1]=r1; bl[ng*2+1][0]=r2; bl[ng*2+1][1]=r3;
            }
            #pragma unroll
            for (int mt = 0; mt < 2; mt++)
                #pragma unroll
                for (int nt = 0; nt < 4; nt++){
                    MMA16816(acc[mt][nt], ah[mt], bh[nt]);
                    MMA16816(acc[mt][nt], ah[mt], bl[nt]);
                    MMA16816(acc[mt][nt], al[mt], bh[nt]);
                }
        }
    };
    auto epilogue = [&](float (&acc)[2][4][4], int bn){
        #pragma unroll
        for (int mt = 0; mt < 2; mt++){
            #pragma unroll
            for (int nt = 0; nt < 4; nt++){
                int row0 = bm + wm*32 + mt*16 + gID;
                int col  = bn + wn*32 + nt*8 + qid*2;
                float2 v0 = make_float2(acc[mt][nt][0], acc[mt][nt][1]);
                float2 v1 = make_float2(acc[mt][nt][2], acc[mt][nt][3]);
                if (BIAS){
                    float2 bv = *(const float2*)&bias[col];
                    v0.x += bv.x; v0.y += bv.y;
                    v1.x += bv.x; v1.y += bv.y;
                }
                float* p0 = C + (size_t)row0*N + col;
                float* p1 = C + (size_t)(row0+8)*N + col;
                if (ADD){
                    float2 o0 = *(const float2*)p0, o1 = *(const float2*)p1;
                    v0.x += o0.x; v0.y += o0.y;
                    v1.x += o1.x; v1.y += o1.y;
                }
                *(float2*)p0 = v0;
                *(float2*)p1 = v1;
            }
        }
    };

    if constexpr (NB == 1){
        const int bn = blockIdx.x*64;
        float acc[2][4][4] = {};
        const int nchunk = K >> 7;
        for (int kc = 0; kc < nchunk; kc++){
            stageA(kc);
            stageB(bn, kc);
            __syncthreads();
            compute(acc);
            __syncthreads();
        }
        epilogue(acc, bn);
    } else {
        const int bn0 = blockIdx.x*64*NB;
        stageA(0);
        #pragma unroll
        for (int sub = 0; sub < NB; sub++){
            stageB(bn0 + sub*64, 0);
            __syncthreads();
            float acc[2][4][4] = {};
            compute(acc);
            epilogue(acc, bn0 + sub*64);
            __syncthreads();
        }
    }
}

// ---------------- one-shot weight prep: transposes + densify + gate folding --
__global__ void __launch_bounds__(256) k_prep(
    const float* sgw0, const float* sgw1,
    const float* sfu0, const float* sfd0, const float* mup0, const float* mdn0,
    const float* mfu0, const float* mfd0,
    const float* sfu1, const float* sfd1, const float* mup1, const float* mdn1,
    const float* mfu1, const float* mfd1,
    const float* headw,
    const float* qkvw, const float* igw, const float* fgw){
    int bx = blockIdx.x, tid = threadIdx.x;
    if (bx < 416){
        const int cum[13]  = {32,48,112,144,176,192,224,240,304,336,368,384,416};
        const float* srcs[13] = {sfu0,sfd0,mup0,mdn0,mfu0,mfd0,sfu1,sfd1,mup1,mdn1,mfu1,mfd1,headw};
        const int Ks[13]   = {128,128,128,256,128,128,128,128,128,256,128,128,128};
        const int Ns[13]   = {256,128,512,128,256,128,256,128,512,128,256,128,256};
        const int dsts[13] = {W_SFU(0),W_SFD(0),W_MUP(0),W_MDN(0),W_MFU(0),W_MFD(0),
                              W_SFU(1),W_SFD(1),W_MUP(1),W_MDN(1),W_MFU(1),W_MFD(1),W_HEAD};
        int j = 0;
        while (bx >= cum[j]) j++;
        int tile = bx - (j ? cum[j-1] : 0);
        const float* src = srcs[j];
        int K = Ks[j], N = Ns[j], dst = dsts[j];
        int tilesN = N >> 5;
        int bk = (tile / tilesN)*32, bn = (tile % tilesN)*32;
        __shared__ float t[32][33];
        int tx = tid & 31, ty = tid >> 5;
        #pragma unroll
        for (int r = 0; r < 32; r += 8)
            t[ty+r][tx] = src[(size_t)(bk+ty+r)*N + bn+tx];
        __syncthreads();
        #pragma unroll
        for (int r = 0; r < 32; r += 8){
            float v = t[tx][ty+r];
            __nv_bfloat16 h = __float2bfloat16(v);
            size_t o = (size_t)dst + (size_t)(bn+ty+r)*K + bk+tx;
            g_wt_hi[o] = h;
            g_wt_lo[o] = __float2bfloat16(v - __bfloat162float(h));
        }
    } else if (bx < 544){
        int bx2 = bx - 416;
        int L = bx2 >> 6, blk = bx2 & 63;
        const float* gw = L ? sgw1 : sgw0;
        #pragma unroll
        for (int u = 0; u < 4; u++){
            int idx = blk*1024 + u*256 + tid;     // over 128*512
            int d = idx >> 9;
            int o = idx & 511;
            int g = o >> 7;
            int ne = o & 127;
            int n = ne >> 5, e = ne & 31;
            float wv = 0.0f;
            if ((d >> 5) == n) wv = gw[(((g*NHs + n)*HDs + e)*HDs) + (d & 31)];
            __nv_bfloat16 h = __float2bfloat16(wv);
            size_t oo = (size_t)W_SGX(L) + (size_t)o*Dd + d;
            g_wt_hi[oo] = h;
            g_wt_lo[oo] = __float2bfloat16(wv - __bfloat162float(h));
        }
    } else {
        int L = bx - 544;
        const float* qw  = qkvw + L*3072;
        const float* igp = igw  + L*3072;
        const float* fgp = fgw  + L*3072;
        int c = tid, n = c >> 2, i = c & 3;
        float aig[4]={0,0,0,0}, big_[4]={0,0,0,0}, afg[4]={0,0,0,0}, bfg_[4]={0,0,0,0};
        #pragma unroll
        for (int o = 0; o < 4; o++){
            float w0 = qw[n*16+o*4+i];
            float w1 = qw[1024+n*16+o*4+i];
            float w2 = qw[2048+n*16+o*4+i];
            int j0 = (n*4+o)*4, j1 = (256+n*4+o)*4, j2 = (512+n*4+o)*4;
            #pragma unroll
            for (int hm = 0; hm < 4; hm++){
                aig[hm]  += w0*igp[j0+hm] + w1*igp[j1+hm];
                big_[hm] += w2*igp[j2+hm];
                afg[hm]  += w0*fgp[j0+hm] + w1*fgp[j1+hm];
                bfg_[hm] += w2*fgp[j2+hm];
            }
        }
        #pragma unroll
        for (int hm = 0; hm < 4; hm++){
            g_gw_eff[L*4096 + 0*1024 + c*4 + hm] = aig[hm];
            g_gw_eff[L*4096 + 1*1024 + c*4 + hm] = big_[hm];
            g_gw_eff[L*4096 + 2*1024 + c*4 + hm] = afg[hm];
            g_gw_eff[L*4096 + 3*1024 + c*4 + hm] = bfg_[hm];
        }
    }
}

// ---------------- embedding --------------------------------------------------
__global__ void k_embed(const int* __restrict__ x, const float* __restrict__ emb){
    int t = blockIdx.x;
    g_h[t*Dd + threadIdx.x] = emb[x[t]*Dd + threadIdx.x];
}

// ---------------- sLSTM scan: 8 warps/block, 2 batches/warp ------------------
// Weight LDS amortized across the 2 batches (crossbar-bound kernel).
__global__ void __launch_bounds__(256) k_scan(const float* __restrict__ rec,
                                              const float* __restrict__ gn){
    int n  = blockIdx.x & 3;
    int bg = blockIdx.x >> 2;            // 0..31
    int w  = threadIdx.x >> 5;           // 0..7
    int e  = threadIdx.x & 31;
    int b0 = bg*16 + w*2, b1 = b0 + 1;
    __shared__ float rw[4][HDs][36];
    __shared__ float hs[16][HDs];
    for (int idx = threadIdx.x; idx < 4*HDs*HDs; idx += 256){
        int g = idx >> 10, rem = idx & 1023;
        int e2 = rem >> 5, d = rem & 31;
        rw[g][e2][d] = rec[((size_t)(g*NHs+n)*HDs + e2)*HDs + d];
    }
    hs[w*2][e] = 0.0f;
    hs[w*2+1][e] = 0.0f;
    __syncthreads();
    const int gb = n*HDs + e;
    const float gnw = gn[gb];
    const float* gxA = g_big + (size_t)(b0*Ss)*512 + gb;
    const float* gxB = g_big + (size_t)(b1*Ss)*512 + gb;
    float cA=0.f, nnA=0.f, mA=0.f;
    float cB=0.f, nnB=0.f, mB=0.f;
    float r0a = gxA[0], r1a = gxA[Dd], r2a = gxA[2*Dd], r3a = gxA[3*Dd];
    float r0b = gxB[0], r1b = gxB[Dd], r2b = gxB[2*Dd], r3b = gxB[3*Dd];
    for(int s=0;s<Ss;s++){
        float n0a=0.f,n1a=0.f,n2a=0.f,n3a=0.f, n0b=0.f,n1b=0.f,n2b=0.f,n3b=0.f;
        if (s+1 < Ss){
            const float* npA = gxA + (size_t)(s+1)*512;
            const float* npB = gxB + (size_t)(s+1)*512;
            n0a = npA[0]; n1a = npA[Dd]; n2a = npA[2*Dd]; n3a = npA[3*Dd];
            n0b = npB[0]; n1b = npB[Dd]; n2b = npB[2*Dd]; n3b = npB[3*Dd];
        }
        #pragma unroll
        for(int dq=0; dq<8; dq++){
            float4 w0 = *(const float4*)&rw[0][e][dq*4];
            float4 w1 = *(const float4*)&rw[1][e][dq*4];
            float4 w2 = *(const float4*)&rw[2][e][dq*4];
            float4 w3 = *(const float4*)&rw[3][e][dq*4];
            float4 ha = *(const float4*)&hs[w*2][dq*4];
            float4 hb = *(const float4*)&hs[w*2+1][dq*4];
            r0a += ha.x*w0.x + ha.y*w0.y + ha.z*w0.z + ha.w*w0.w;
            r1a += ha.x*w1.x + ha.y*w1.y + ha.z*w1.z + ha.w*w1.w;
            r2a += ha.x*w2.x + ha.y*w2.y + ha.z*w2.z + ha.w*w2.w;
            r3a += ha.x*w3.x + ha.y*w3.y + ha.z*w3.z + ha.w*w3.w;
            r0b += hb.x*w0.x + hb.y*w0.y + hb.z*w0.z + hb.w*w0.w;
            r1b += hb.x*w1.x + hb.y*w1.y + hb.z*w1.z + hb.w*w1.w;
            r2b += hb.x*w2.x + hb.y*w2.y + hb.z*w2.z + hb.w*w2.w;
            r3b += hb.x*w3.x + hb.y*w3.y + hb.z*w3.z + hb.w*w3.w;
        }
        float lfmA = mA + logsigf(r1a);
        float mnA  = fmaxf(r0a, lfmA);
        float iA   = expf(r0a-mnA);
        float fA   = expf(lfmA-mnA);
        cA  = fA*cA + iA*tanhf(r2a);
        nnA = fA*nnA + iA;
        float hA = sigf(r3a) * cA / nnA;
        mA = mnA;

        float lfmB = mB + logsigf(r1b);
        float mnB  = fmaxf(r0b, lfmB);
        float iB   = expf(r0b-mnB);
        float fB   = expf(lfmB-mnB);
        cB  = fB*cB + iB*tanhf(r2b);
        nnB = fB*nnB + iB;
        float hB = sigf(r3b) * cB / nnB;
        mB = mnB;

        // publish h for next step FIRST, then GN off the critical path
        __syncwarp();
        hs[w*2][e]   = hA;
        hs[w*2+1][e] = hB;
        __syncwarp();

        float s1 = hA, s2 = hA*hA, t1 = hB, t2 = hB*hB;
        #pragma unroll
        for(int o=16;o;o>>=1){
            s1 += __shfl_xor_sync(~0u,s1,o); s2 += __shfl_xor_sync(~0u,s2,o);
            t1 += __shfl_xor_sync(~0u,t1,o); t2 += __shfl_xor_sync(~0u,t2,o);
        }
        float muA = s1*(1.0f/HDs), varA = s2*(1.0f/HDs)-muA*muA;
        float muB = t1*(1.0f/HDs), varB = t2*(1.0f/HDs)-muB*muB;
        float rrA = rsqrtf(varA + 1e-5f);
        float rrB = rsqrtf(varB + 1e-5f);
        g_h[((size_t)(b0*Ss+s))*Dd + gb] += (hA-muA)*rrA*gnw;
        g_h[((size_t)(b1*Ss+s))*Dd + gb] += (hB-muB)*rrB*gnw;

        r0a = n0a; r1a = n1a; r2a = n2a; r3a = n3a;
        r0b = n0b; r1b = n1b; r2b = n2b; r3b = n3b;
    }
}

// ---------------- fused conv+silu+qkv+gates: 8 tokens per block --------------
__global__ void __launch_bounds__(256) k_cq(
        const float* __restrict__ cw, const float* __restrict__ cb,
        const float* __restrict__ qkvw, const float* __restrict__ gweff,
        const float* __restrict__ igb, const float* __restrict__ fgb){
    __shared__ float xms[11][256];
    __shared__ float xcv[8][256];
    __shared__ float4 Aig[256], Big[256], Afg[256], Bfg[256];
    int blk = blockIdx.x, b = blk>>3, sg = blk&7;
    int tid = threadIdx.x;
    int t0 = b*Ss + sg*8;

    Aig[tid] = *(const float4*)&gweff[0*1024 + tid*4];
    Big[tid] = *(const float4*)&gweff[1*1024 + tid*4];
    Afg[tid] = *(const float4*)&gweff[2*1024 + tid*4];
    Bfg[tid] = *(const float4*)&gweff[3*1024 + tid*4];

    for (int idx = tid; idx < 11*256; idx += 256){
        int r = idx >> 8, c = idx & 255;
        int s = sg*8 + r - 3;
        xms[r][c] = (s >= 0) ? g_big[(size_t)(b*Ss+s)*512 + c] : 0.0f;
    }
    int c = tid, n = c>>2, o = c&3;
    float cwv0=cw[c*4], cwv1=cw[c*4+1], cwv2=cw[c*4+2], cwv3=cw[c*4+3], cbv=cb[c];
    float wq[4], wk[4], wv[4];
    #pragma unroll
    for (int i2 = 0; i2 < 4; i2++){
        wq[i2] = qkvw[       n*16 + o*4 + i2];
        wk[i2] = qkvw[1024 + n*16 + o*4 + i2];
        wv[i2] = qkvw[2048 + n*16 + o*4 + i2];
    }
    __syncthreads();
    #pragma unroll
    for (int s = 0; s < 8; s++){
        float acc = cbv + xms[s][c]*cwv0 + xms[s+1][c]*cwv1 + xms[s+2][c]*cwv2 + xms[s+3][c]*cwv3;
        float xc = acc*sigf(acc);
        xcv[s][c] = xc;
        g_xconv[(size_t)(t0+s)*256 + c] = xc;
    }
    __syncthreads();
    #pragma unroll
    for (int s = 0; s < 8; s++){
        float q=0, k=0, v=0;
        #pragma unroll
        for (int i2 = 0; i2 < 4; i2++){
            float xc = xcv[s][n*4+i2];
            float xm = xms[s+3][n*4+i2];
            q += xc*wq[i2]; k += xc*wk[i2]; v += xm*wv[i2];
        }
        g_q[(size_t)(t0+s)*256 + c] = q;
        g_k[(size_t)(t0+s)*256 + c] = k;
        g_v[(size_t)(t0+s)*256 + c] = v;
    }
    int w = tid >> 5, lane = tid & 31;
    float4 ia = make_float4(0,0,0,0), fa = make_float4(0,0,0,0);
    for (int j = lane; j < 256; j += 32){
        float xc = xcv[w][j], xm = xms[w+3][j];
        float4 A = Aig[j], B = Big[j], A2 = Afg[j], B2 = Bfg[j];
        ia.x += xc*A.x + xm*B.x;  ia.y += xc*A.y + xm*B.y;
        ia.z += xc*A.z + xm*B.z;  ia.w += xc*A.w + xm*B.w;
        fa.x += xc*A2.x + xm*B2.x; fa.y += xc*A2.y + xm*B2.y;
        fa.z += xc*A2.z + xm*B2.z; fa.w += xc*A2.w + xm*B2.w;
    }
    #pragma unroll
    for (int o2=16;o2;o2>>=1){
        ia.x += __shfl_xor_sync(~0u,ia.x,o2); ia.y += __shfl_xor_sync(~0u,ia.y,o2);
        ia.z += __shfl_xor_sync(~0u,ia.z,o2); ia.w += __shfl_xor_sync(~0u,ia.w,o2);
        fa.x += __shfl_xor_sync(~0u,fa.x,o2); fa.y += __shfl_xor_sync(~0u,fa.y,o2);
        fa.z += __shfl_xor_sync(~0u,fa.z,o2); fa.w += __shfl_xor_sync(~0u,fa.w,o2);
    }
    if (lane == 0){
        int s_ = sg*8 + w;
        g_ig[(size_t)(b*NHMc+0)*Ss + s_] = ia.x + igb[0];
        g_ig[(size_t)(b*NHMc+1)*Ss + s_] = ia.y + igb[1];
        g_ig[(size_t)(b*NHMc+2)*Ss + s_] = ia.z + igb[2];
        g_ig[(size_t)(b*NHMc+3)*Ss + s_] = ia.w + igb[3];
        g_fg[(size_t)(b*NHMc+0)*Ss + s_] = fa.x + fgb[0];
        g_fg[(size_t)(b*NHMc+1)*Ss + s_] = fa.y + fgb[1];
        g_fg[(size_t)(b*NHMc+2)*Ss + s_] = fa.z + fgb[2];
        g_fg[(size_t)(b*NHMc+3)*Ss + s_] = fa.w + fgb[3];
    }
}

// ---------------- mLSTM attention + fused groupnorm/skip/silu combine --------
__global__ void __launch_bounds__(256) k_attn(const float* __restrict__ onw,
                                              const float* __restrict__ skip){
    int blk = blockIdx.x; int b = blk >> 2, hm = blk & 3;
    __shared__ float qs[Ss][DHMc+1], ks[Ss][DHMc+1], vs[Ss][DHMc+1];
    __shared__ float cldf[Ss+1], igs[Ss];
    __shared__ float cn[8][Ss];
    int tid = threadIdx.x;
    for(int l=tid; l<Ss*DHMc; l+=256){
        int j = l >> 6, d = l & 63;
        size_t base = ((size_t)(b*Ss+j))*INNERc + hm*DHMc + d;
        qs[j][d] = g_q[base];
        ks[j][d] = g_k[base];
        vs[j][d] = g_v[base];
    }
    if (tid < Ss){
        igs[tid] = g_ig[(size_t)(b*NHMc+hm)*Ss + tid];
        cldf[tid+1] = logsigf(g_fg[(size_t)(b*NHMc+hm)*Ss + tid]);
    }
    if (tid == 0) cldf[0] = 0.0f;
    __syncthreads();
    for (int off = 1; off < Ss; off <<= 1){
        float add = 0.0f;
        if (tid < Ss && tid >= off) add = cldf[tid+1-off];
        __syncthreads();
        if (tid < Ss && tid >= off) cldf[tid+1] += add;
        __syncthreads();
    }
    int w = tid >> 5, lane = tid & 31;
    int cg0 = hm*DHMc + lane, cg1 = cg0 + 32;
    float onw0 = onw[cg0], onw1 = onw[cg1];
    float sk0 = skip[cg0], sk1 = skip[cg1];
    for(int r=0;r<8;r++){
        int i = w*8 + r;
        int j1 = lane + 32;
        float dot0=0, dot1=0, ld0=-1e30f, ld1=-1e30f;
        if (lane <= i){
            #pragma unroll
            for(int d=0; d<DHMc; d++) dot0 += qs[i][d]*ks[lane][d];
            ld0 = cldf[i+1]-cldf[lane+1] + igs[lane];
        }
        if (j1 <= i){
            #pragma unroll
            for(int d=0; d<DHMc; d++) dot1 += qs[i][d]*ks[j1][d];
            ld1 = cldf[i+1]-cldf[j1+1] + igs[j1];
        }
        float mx = fmaxf(ld0, ld1);
        #pragma unroll
        for(int o=16;o;o>>=1) mx = fmaxf(mx, __shfl_xor_sync(~0u,mx,o));
        float cm0 = (lane <= i) ? dot0*0.125f*expf(ld0-mx) : 0.0f;
        float cm1 = (j1   <= i) ? dot1*0.125f*expf(ld1-mx) : 0.0f;
        float sm = cm0 + cm1;
        #pragma unroll
        for(int o=16;o;o>>=1) sm += __shfl_xor_sync(~0u,sm,o);
        float norm = fmaxf(fabsf(sm), expf(-mx)) + 1e-6f;
        cn[w][lane] = cm0/norm;
        cn[w][j1]   = cm1/norm;
        __syncwarp();
        float a0=0, a1=0;
        for(int j=0;j<=i;j++){
            float cc = cn[w][j];
            a0 += cc*vs[j][lane];
            a1 += cc*vs[j][lane+32];
        }
        float s1 = a0+a1, s2 = a0*a0+a1*a1;
        #pragma unroll
        for(int o=16;o;o>>=1){ s1 += __shfl_xor_sync(~0u,s1,o); s2 += __shfl_xor_sync(~0u,s2,o); }
        float mu = s1*(1.0f/DHMc), var = s2*(1.0f/DHMc)-mu*mu;
        float rr = rsqrtf(var + 1e-5f);
        size_t t = (size_t)(b*Ss+i);
        float z0 = g_big[t*512 + 256 + cg0], z1 = g_big[t*512 + 256 + cg1];
        float x0 = g_xconv[t*256 + cg0],     x1 = g_xconv[t*256 + cg1];
        g_q[t*256 + cg0] = ((a0-mu)*rr*onw0 + sk0*x0) * z0*sigf(z0);
        g_q[t*256 + cg1] = ((a1-mu)*rr*onw1 + sk1*x1) * z1*sigf(z1);
        __syncwarp();
    }
}

// ---------------- host-side --------------------------------------------------
static float* symf(const void* s){ void* p=nullptr; cudaGetSymbolAddress(&p, s); return (float*)p; }

extern "C" void kernel_launch(void* const* d_in, const int* in_sizes, int n_in,
                              void* d_out, int out_size){
    const int*   x         = (const int*)  d_in[0];
    const float* embed     = (const float*)d_in[1];
    const float* s_ln1     = (const float*)d_in[2];
    const float* s_gates_w = (const float*)d_in[3];
    const float* s_rec     = (const float*)d_in[4];
    const float* s_bias    = (const float*)d_in[5];
    const float* s_gn      = (const float*)d_in[6];
    const float* s_ln2     = (const float*)d_in[7];
    const float* s_ff_up   = (const float*)d_in[8];
    const float* s_ff_down = (const float*)d_in[9];
    const float* m_ln1     = (const float*)d_in[10];
    const float* m_up      = (const float*)d_in[11];
    const float* m_conv_w  = (const float*)d_in[12];
    const float* m_conv_b  = (const float*)d_in[13];
    const float* m_qkv_w   = (const float*)d_in[14];
    const float* m_ig_w    = (const float*)d_in[15];
    const float* m_ig_b    = (const float*)d_in[16];
    const float* m_fg_w    = (const float*)d_in[17];
    const float* m_fg_b    = (const float*)d_in[18];
    const float* m_skip    = (const float*)d_in[19];
    const float* m_onorm   = (const float*)d_in[20];
    const float* m_down    = (const float*)d_in[21];
    const float* m_ln2     = (const float*)d_in[22];
    const float* m_ff_up   = (const float*)d_in[23];
    const float* m_ff_down = (const float*)d_in[24];
    const float* post_ln   = (const float*)d_in[25];
    const float* head_w    = (const float*)d_in[26];
    const float* head_b    = (const float*)d_in[27];

    float* h    = symf(g_h);
    float* big  = symf(g_big);
    float* ffn  = symf(g_ffn);
    float* qb   = symf(g_q);
    float* gweff= symf(g_gw_eff);

    float* out = (float*)d_out;

    cudaFuncSetAttribute(k_mgemm<false,true ,true ,false,8>, cudaFuncAttributeMaxDynamicSharedMemorySize, MG_SMEM);
    cudaFuncSetAttribute(k_mgemm<false,false,true ,false,8>, cudaFuncAttributeMaxDynamicSharedMemorySize, MG_SMEM);
    cudaFuncSetAttribute(k_mgemm<false,false,true ,false,4>, cudaFuncAttributeMaxDynamicSharedMemorySize, MG_SMEM);
    cudaFuncSetAttribute(k_mgemm<true ,false,false,true ,2>, cudaFuncAttributeMaxDynamicSharedMemorySize, MG_SMEM);
    cudaFuncSetAttribute(k_mgemm<true ,false,false,false,1>, cudaFuncAttributeMaxDynamicSharedMemorySize, MG_SMEM);
    cudaFuncSetAttribute(k_mgemm<false,true ,true ,false,4>, cudaFuncAttributeMaxDynamicSharedMemorySize, MG_SMEM);

    k_prep<<<546,256>>>(
        s_gates_w, s_gates_w + (size_t)4*NHs*HDs*HDs,
        s_ff_up, s_ff_down, m_up, m_down, m_ff_up, m_ff_down,
        s_ff_up + (size_t)Dd*2*FFc, s_ff_down + (size_t)FFc*Dd,
        m_up + (size_t)Dd*2*INNERc, m_down + (size_t)INNERc*Dd,
        m_ff_up + (size_t)Dd*2*FFc, m_ff_down + (size_t)FFc*Dd,
        head_w, m_qkv_w, m_ig_w, m_fg_w);
    k_embed<<<Tt, Dd>>>(x, embed);

    for(int i=0;i<2;i++){
        // ---- sLSTM ----
        k_mgemm<false,true,true,false,8><<<dim3(1, Tt/128),256,MG_SMEM>>>(
            h, big, s_bias + i*4*Dd, s_ln1 + i*Dd, W_SGX(i), 4*Dd, Dd);
        k_scan<<<NHs*(Bb/16),256>>>(s_rec + (size_t)i*4*NHs*HDs*HDs, s_gn + i*Dd);

        // ---- FFN 1 ----
        k_mgemm<false,false,true,false,4><<<dim3(1, Tt/128),256,MG_SMEM>>>(
            h, ffn, nullptr, s_ln2 + i*Dd, W_SFU(i), 2*FFc, Dd);
        k_mgemm<true,false,false,true,2><<<dim3(1, Tt/128),256,MG_SMEM>>>(
            ffn, h, nullptr, nullptr, W_SFD(i), Dd, FFc);

        // ---- mLSTM ----
        k_mgemm<false,false,true,false,8><<<dim3(1, Tt/128),256,MG_SMEM>>>(
            h, big, nullptr, m_ln1 + i*Dd, W_MUP(i), 2*INNERc, Dd);
        k_cq<<<Bb*8,256>>>(m_conv_w + (size_t)i*INNERc*Kc, m_conv_b + i*INNERc,
                           m_qkv_w + (size_t)i*3072, gweff + i*4096,
                           m_ig_b + i*NHMc, m_fg_b + i*NHMc);
        k_attn<<<Bb*NHMc,256>>>(m_onorm + i*INNERc, m_skip + i*INNERc);
        k_mgemm<true,false,false,false,1><<<dim3(2, Tt/128),256,MG_SMEM>>>(
            qb, h, nullptr, nullptr, W_MDN(i), Dd, INNERc);

        // ---- FFN 2 ----
        k_mgemm<false,false,true,false,4><<<dim3(1, Tt/128),256,MG_SMEM>>>(
            h, ffn, nullptr, m_ln2 + i*Dd, W_MFU(i), 2*FFc, Dd);
        k_mgemm<true,false,false,true,2><<<dim3(1, Tt/128),256,MG_SMEM>>>(
            ffn, h, nullptr, nullptr, W_MFD(i), Dd, FFc);
    }

    // ---- final LN + head ----
    k_mgemm<false,true,true,false,4><<<dim3(1, Tt/128),256,MG_SMEM>>>(
        h, out, head_b, post_ln, W_HEAD, Vv, Dd);
}

// round 13
// speedup vs baseline: 1.0271x; 1.0271x over previous
#include <cuda_runtime.h>
#include <cuda_bf16.h>
#include <math.h>
#include <stdint.h>

#define Bb     512
#define Ss     64
#define Dd     128
#define Vv     256
#define NHs    4
#define HDs    32
#define INNERc 256
#define NHMc   4
#define DHMc   64
#define NBc    64
#define Kc     4
#define FFc    128
#define Tt     (Bb*Ss)   /* 32768 tokens */

// ---------------- workspaces (static device globals; no allocation) ----------
__device__ float g_h[Tt*Dd];            // residual stream
__device__ float g_big[Tt*2*INNERc];    // slstm gx [t][512]  OR  mlstm up out [t][512]
__device__ float g_ffn[Tt*2*FFc];       // ffn up output
__device__ float g_xconv[Tt*INNERc];
__device__ float g_q[Tt*INNERc];        // q, later reused as mlstm combine buffer
__device__ float g_k[Tt*INNERc];
__device__ float g_v[Tt*INNERc];
__device__ float g_ig[Bb*NHMc*Ss];
__device__ float g_fg[Bb*NHMc*Ss];

// all GEMM weights, transposed+split [N][K]
#define W_SGX(i)  ((i)*262144 + 0)
#define W_SFU(i)  ((i)*262144 + 65536)
#define W_SFD(i)  ((i)*262144 + 98304)
#define W_MUP(i)  ((i)*262144 + 114688)
#define W_MDN(i)  ((i)*262144 + 180224)
#define W_MFU(i)  ((i)*262144 + 212992)
#define W_MFD(i)  ((i)*262144 + 245760)
#define W_HEAD    (524288)
#define W_TOTAL   (557056)
__device__ __nv_bfloat16 g_wt_hi[W_TOTAL];
__device__ __nv_bfloat16 g_wt_lo[W_TOTAL];
__device__ float g_gw_eff[2*4096];      // folded gate weights [L][4][256][4]

// ---------------- device math helpers (fast-math intrinsics) -----------------
__device__ __forceinline__ float sigf(float x){
    return __fdividef(1.0f, 1.0f + __expf(-x));
}
__device__ __forceinline__ float logsigf(float x){
    return fminf(x, 0.0f) - __logf(1.0f + __expf(-fabsf(x)));
}
__device__ __forceinline__ float tanhfast(float x){
    float t = __expf(-2.0f*fabsf(x));
    float r = __fdividef(1.0f - t, 1.0f + t);
    return copysignf(r, x);
}
__device__ __forceinline__ float geluf(float x){
    float x3 = x*x*x;
    return 0.5f*x*(1.0f+tanhfast(0.7978845608028654f*(x+0.044715f*x3)));
}
__device__ __forceinline__ uint32_t smem_u32(const void* p){
    uint32_t a;
    asm("{ .reg .u64 t; cvta.to.shared.u64 t, %1; cvt.u32.u64 %0, t; }" : "=r"(a) : "l"(p));
    return a;
}
__device__ __forceinline__ void split2(float a, float b, uint32_t &hi, uint32_t &lo){
    __nv_bfloat162 h = __floats2bfloat162_rn(a, b);
    float ra = a - __bfloat162float(h.x);
    float rb = b - __bfloat162float(h.y);
    __nv_bfloat162 l = __floats2bfloat162_rn(ra, rb);
    hi = *(uint32_t*)&h; lo = *(uint32_t*)&l;
}

#define LDM4(r0,r1,r2,r3,addr) \
    asm volatile("ldmatrix.sync.aligned.m8n8.x4.shared.b16 {%0,%1,%2,%3}, [%4];" \
        : "=r"(r0),"=r"(r1),"=r"(r2),"=r"(r3) : "r"(addr))

#define MMA16816(d,a,b) \
    asm volatile("mma.sync.aligned.m16n8k16.row.col.f32.bf16.bf16.f32 " \
        "{%0,%1,%2,%3}, {%4,%5,%6,%7}, {%8,%9}, {%0,%1,%2,%3};" \
        : "+f"((d)[0]),"+f"((d)[1]),"+f"((d)[2]),"+f"((d)[3]) \
        : "r"((a)[0]),"r"((a)[1]),"r"((a)[2]),"r"((a)[3]), "r"((b)[0]),"r"((b)[1]))

// smem layout: A tiles 128x136 bf16 (hi/lo), B tiles 64x136 bf16 (hi/lo)
#define MG_STRIDE 136
#define MG_AH 0
#define MG_AL (128*MG_STRIDE*2)
#define MG_BH (2*128*MG_STRIDE*2)
#define MG_BL (MG_BH + 64*MG_STRIDE*2)
#define MG_SMEM (MG_BL + 64*MG_STRIDE*2)   /* 104448 B */

// ---------------- tensor-core GEMM: C[M,N] (+)= f(A)[M,K] @ Wt^T (+bias) -----
// NB>1 requires K==128: A is staged ONCE, then NB 64-wide B sub-tiles are
// processed in a loop reusing the staged A. NB==1 keeps the multi-k-chunk path.
template<bool ADD, bool BIAS, bool LN, bool GLU, int NB>
__global__ void __launch_bounds__(256,2) k_mgemm(
        const float* __restrict__ A, float* __restrict__ C,
        const float* __restrict__ bias, const float* __restrict__ lnw,
        int woff, int N, int K){
    extern __shared__ char smem[];
    const int tid = threadIdx.x, w = tid>>5, lane = tid&31;
    const int bm = blockIdx.y*128;
    const int wm = w & 3, wn = w >> 2;
    const int gID = lane >> 2, qid = lane & 3;

    const int a_row = lane & 15;
    const int a_koff = (lane >> 4) * 8;
    const int b_noff = (lane & 7) + ((lane >> 4) & 1) * 8;
    const int b_koff = ((lane >> 3) & 1) * 8;

    const uint32_t sb = smem_u32(smem);

    auto stageA = [&](int kc){
        #pragma unroll
        for (int it = 0; it < 8; it++){
            int g4 = tid + it*256;
            int row = g4 >> 4, kg = g4 & 15;
            float4 v0, v1;
            if (GLU){
                const float* ap = A + (size_t)(bm+row)*256 + kg*8;
                float4 gg0 = *(const float4*)ap,      gg1 = *(const float4*)(ap+4);
                float4 uu0 = *(const float4*)(ap+128), uu1 = *(const float4*)(ap+132);
                v0.x = geluf(gg0.x)*uu0.x; v0.y = geluf(gg0.y)*uu0.y;
                v0.z = geluf(gg0.z)*uu0.z; v0.w = geluf(gg0.w)*uu0.w;
                v1.x = geluf(gg1.x)*uu1.x; v1.y = geluf(gg1.y)*uu1.y;
                v1.z = geluf(gg1.z)*uu1.z; v1.w = geluf(gg1.w)*uu1.w;
            } else {
                const float4* ap = (const float4*)(A + (size_t)(bm+row)*K + kc*128 + kg*8);
                v0 = ap[0]; v1 = ap[1];
            }
            if (LN){
                float s  = v0.x+v0.y+v0.z+v0.w + v1.x+v1.y+v1.z+v1.w;
                float ss = v0.x*v0.x+v0.y*v0.y+v0.z*v0.z+v0.w*v0.w
                         + v1.x*v1.x+v1.y*v1.y+v1.z*v1.z+v1.w*v1.w;
                #pragma unroll
                for (int o = 1; o < 16; o <<= 1){
                    s  += __shfl_xor_sync(~0u, s,  o);
                    ss += __shfl_xor_sync(~0u, ss, o);
                }
                float mu  = s*(1.0f/128.0f);
                float var = ss*(1.0f/128.0f) - mu*mu;
                float rr  = rsqrtf(var + 1e-5f);
                float4 w0 = *(const float4*)&lnw[kg*8];
                float4 w1 = *(const float4*)&lnw[kg*8+4];
                v0.x = (v0.x-mu)*rr*w0.x; v0.y = (v0.y-mu)*rr*w0.y;
                v0.z = (v0.z-mu)*rr*w0.z; v0.w = (v0.w-mu)*rr*w0.w;
                v1.x = (v1.x-mu)*rr*w1.x; v1.y = (v1.y-mu)*rr*w1.y;
                v1.z = (v1.z-mu)*rr*w1.z; v1.w = (v1.w-mu)*rr*w1.w;
            }
            uint32_t h0,h1,h2,h3, l0,l1,l2,l3;
            split2(v0.x, v0.y, h0, l0);
            split2(v0.z, v0.w, h1, l1);
            split2(v1.x, v1.y, h2, l2);
            split2(v1.z, v1.w, h3, l3);
            uint32_t off = (uint32_t)(row*(MG_STRIDE*2) + kg*16);
            *(uint4*)(smem + MG_AH + off) = make_uint4(h0,h1,h2,h3);
            *(uint4*)(smem + MG_AL + off) = make_uint4(l0,l1,l2,l3);
        }
    };
    auto stageB = [&](int bn, int kc){
        #pragma unroll
        for (int it = 0; it < 4; it++){
            int g4 = tid + it*256;
            int n = g4 >> 4, kg = g4 & 15;
            size_t gi = (size_t)woff + (size_t)(bn+n)*K + kc*128 + kg*8;
            uint4 hv = *(const uint4*)(g_wt_hi + gi);
            uint4 lv = *(const uint4*)(g_wt_lo + gi);
            uint32_t off = (uint32_t)(n*(MG_STRIDE*2) + kg*16);
            *(uint4*)(smem + MG_BH + off) = hv;
            *(uint4*)(smem + MG_BL + off) = lv;
        }
    };
    auto compute = [&](float (&acc)[2][4][4]){
        #pragma unroll
        for (int ks = 0; ks < 8; ks++){
            uint32_t ah[2][4], al[2][4];
            #pragma unroll
            for (int mt = 0; mt < 2; mt++){
                uint32_t aoff = (uint32_t)((wm*32 + mt*16 + a_row)*(MG_STRIDE*2)
                                           + (ks*16 + a_koff)*2);
                LDM4(ah[mt][0],ah[mt][1],ah[mt][2],ah[mt][3], sb + MG_AH + aoff);
                LDM4(al[mt][0],al[mt][1],al[mt][2],al[mt][3], sb + MG_AL + aoff);
            }
            uint32_t bh[4][2], bl[4][2];
            #pragma unroll
            for (int ng = 0; ng < 2; ng++){
                uint32_t boff = (uint32_t)((wn*32 + ng*16 + b_noff)*(MG_STRIDE*2)
                                           + (ks*16 + b_koff)*2);
                uint32_t r0,r1,r2,r3;
                LDM4(r0,r1,r2,r3, sb + MG_BH + boff);
                bh[ng*2][0]=r0; bh[ng*2][1]=r1; bh[ng*2+1][0]=r2; bh[ng*2+1][1]=r3;
                LDM4(r0,r1,r2,r3, sb + MG_BL + boff);
                bl[ng*2][0]=r0; bl[ng*2][1]=r1; bl[ng*2+1][0]=r2; bl[ng*2+1][1]=r3;
            }
            #pragma unroll
            for (int mt = 0; mt < 2; mt++)
                #pragma unroll
                for (int nt = 0; nt < 4; nt++){
                    MMA16816(acc[mt][nt], ah[mt], bh[nt]);
                    MMA16816(acc[mt][nt], ah[mt], bl[nt]);
                    MMA16816(acc[mt][nt], al[mt], bh[nt]);
                }
        }
    };
    auto epilogue = [&](float (&acc)[2][4][4], int bn){
        #pragma unroll
        for (int mt = 0; mt < 2; mt++){
            #pragma unroll
            for (int nt = 0; nt < 4; nt++){
                int row0 = bm + wm*32 + mt*16 + gID;
                int col  = bn + wn*32 + nt*8 + qid*2;
                float2 v0 = make_float2(acc[mt][nt][0], acc[mt][nt][1]);
                float2 v1 = make_float2(acc[mt][nt][2], acc[mt][nt][3]);
                if (BIAS){
                    float2 bv = *(const float2*)&bias[col];
                    v0.x += bv.x; v0.y += bv.y;
                    v1.x += bv.x; v1.y += bv.y;
                }
                float* p0 = C + (size_t)row0*N + col;
                float* p1 = C + (size_t)(row0+8)*N + col;
                if (ADD){
                    float2 o0 = *(const float2*)p0, o1 = *(const float2*)p1;
                    v0.x += o0.x; v0.y += o0.y;
                    v1.x += o1.x; v1.y += o1.y;
                }
                *(float2*)p0 = v0;
                *(float2*)p1 = v1;
            }
        }
    };

    if constexpr (NB == 1){
        const int bn = blockIdx.x*64;
        float acc[2][4][4] = {};
        const int nchunk = K >> 7;
        for (int kc = 0; kc < nchunk; kc++){
            stageA(kc);
            stageB(bn, kc);
            __syncthreads();
            compute(acc);
            __syncthreads();
        }
        epilogue(acc, bn);
    } else {
        const int bn0 = blockIdx.x*64*NB;
        stageA(0);
        #pragma unroll
        for (int sub = 0; sub < NB; sub++){
            stageB(bn0 + sub*64, 0);
            __syncthreads();
            float acc[2][4][4] = {};
            compute(acc);
            epilogue(acc, bn0 + sub*64);
            __syncthreads();
        }
    }
}

// ---------------- one-shot weight prep: transposes + densify + gate folding --
__global__ void __launch_bounds__(256) k_prep(
    const float* sgw0, const float* sgw1,
    const float* sfu0, const float* sfd0, const float* mup0, const float* mdn0,
    const float* mfu0, const float* mfd0,
    const float* sfu1, const float* sfd1, const float* mup1, const float* mdn1,
    const float* mfu1, const float* mfd1,
    const float* headw,
    const float* qkvw, const float* igw, const float* fgw){
    int bx = blockIdx.x, tid = threadIdx.x;
    if (bx < 416){
        const int cum[13]  = {32,48,112,144,176,192,224,240,304,336,368,384,416};
        const float* srcs[13] = {sfu0,sfd0,mup0,mdn0,mfu0,mfd0,sfu1,sfd1,mup1,mdn1,mfu1,mfd1,headw};
        const int Ks[13]   = {128,128,128,256,128,128,128,128,128,256,128,128,128};
        const int Ns[13]   = {256,128,512,128,256,128,256,128,512,128,256,128,256};
        const int dsts[13] = {W_SFU(0),W_SFD(0),W_MUP(0),W_MDN(0),W_MFU(0),W_MFD(0),
                              W_SFU(1),W_SFD(1),W_MUP(1),W_MDN(1),W_MFU(1),W_MFD(1),W_HEAD};
        int j = 0;
        while (bx >= cum[j]) j++;
        int tile = bx - (j ? cum[j-1] : 0);
        const float* src = srcs[j];
        int K = Ks[j], N = Ns[j], dst = dsts[j];
        int tilesN = N >> 5;
        int bk = (tile / tilesN)*32, bn = (tile % tilesN)*32;
        __shared__ float t[32][33];
        int tx = tid & 31, ty = tid >> 5;
        #pragma unroll
        for (int r = 0; r < 32; r += 8)
            t[ty+r][tx] = src[(size_t)(bk+ty+r)*N + bn+tx];
        __syncthreads();
        #pragma unroll
        for (int r = 0; r < 32; r += 8){
            float v = t[tx][ty+r];
            __nv_bfloat16 h = __float2bfloat16(v);
            size_t o = (size_t)dst + (size_t)(bn+ty+r)*K + bk+tx;
            g_wt_hi[o] = h;
            g_wt_lo[o] = __float2bfloat16(v - __bfloat162float(h));
        }
    } else if (bx < 544){
        int bx2 = bx - 416;
        int L = bx2 >> 6, blk = bx2 & 63;
        const float* gw = L ? sgw1 : sgw0;
        #pragma unroll
        for (int u = 0; u < 4; u++){
            int idx = blk*1024 + u*256 + tid;     // over 128*512
            int d = idx >> 9;
            int o = idx & 511;
            int g = o >> 7;
            int ne = o & 127;
            int n = ne >> 5, e = ne & 31;
            float wv = 0.0f;
            if ((d >> 5) == n) wv = gw[(((g*NHs + n)*HDs + e)*HDs) + (d & 31)];
            __nv_bfloat16 h = __float2bfloat16(wv);
            size_t oo = (size_t)W_SGX(L) + (size_t)o*Dd + d;
            g_wt_hi[oo] = h;
            g_wt_lo[oo] = __float2bfloat16(wv - __bfloat162float(h));
        }
    } else {
        int L = bx - 544;
        const float* qw  = qkvw + L*3072;
        const float* igp = igw  + L*3072;
        const float* fgp = fgw  + L*3072;
        int c = tid, n = c >> 2, i = c & 3;
        float aig[4]={0,0,0,0}, big_[4]={0,0,0,0}, afg[4]={0,0,0,0}, bfg_[4]={0,0,0,0};
        #pragma unroll
        for (int o = 0; o < 4; o++){
            float w0 = qw[n*16+o*4+i];
            float w1 = qw[1024+n*16+o*4+i];
            float w2 = qw[2048+n*16+o*4+i];
            int j0 = (n*4+o)*4, j1 = (256+n*4+o)*4, j2 = (512+n*4+o)*4;
            #pragma unroll
            for (int hm = 0; hm < 4; hm++){
                aig[hm]  += w0*igp[j0+hm] + w1*igp[j1+hm];
                big_[hm] += w2*igp[j2+hm];
                afg[hm]  += w0*fgp[j0+hm] + w1*fgp[j1+hm];
                bfg_[hm] += w2*fgp[j2+hm];
            }
        }
        #pragma unroll
        for (int hm = 0; hm < 4; hm++){
            g_gw_eff[L*4096 + 0*1024 + c*4 + hm] = aig[hm];
            g_gw_eff[L*4096 + 1*1024 + c*4 + hm] = big_[hm];
            g_gw_eff[L*4096 + 2*1024 + c*4 + hm] = afg[hm];
            g_gw_eff[L*4096 + 3*1024 + c*4 + hm] = bfg_[hm];
        }
    }
}

// ---------------- embedding --------------------------------------------------
__global__ void k_embed(const int* __restrict__ x, const float* __restrict__ emb){
    int t = blockIdx.x;
    g_h[t*Dd + threadIdx.x] = emb[x[t]*Dd + threadIdx.x];
}

// ---------------- sLSTM scan: 8 warps/block, 2 batches/warp ------------------
__global__ void __launch_bounds__(256) k_scan(const float* __restrict__ rec,
                                              const float* __restrict__ gn){
    int n  = blockIdx.x & 3;
    int bg = blockIdx.x >> 2;            // 0..31
    int w  = threadIdx.x >> 5;           // 0..7
    int e  = threadIdx.x & 31;
    int b0 = bg*16 + w*2, b1 = b0 + 1;
    __shared__ float rw[4][HDs][36];
    __shared__ float hs[16][HDs];
    for (int idx = threadIdx.x; idx < 4*HDs*HDs; idx += 256){
        int g = idx >> 10, rem = idx & 1023;
        int e2 = rem >> 5, d = rem & 31;
        rw[g][e2][d] = rec[((size_t)(g*NHs+n)*HDs + e2)*HDs + d];
    }
    hs[w*2][e] = 0.0f;
    hs[w*2+1][e] = 0.0f;
    __syncthreads();
    const int gb = n*HDs + e;
    const float gnw = gn[gb];
    const float* gxA = g_big + (size_t)(b0*Ss)*512 + gb;
    const float* gxB = g_big + (size_t)(b1*Ss)*512 + gb;
    float cA=0.f, nnA=0.f, mA=0.f;
    float cB=0.f, nnB=0.f, mB=0.f;
    float r0a = gxA[0], r1a = gxA[Dd], r2a = gxA[2*Dd], r3a = gxA[3*Dd];
    float r0b = gxB[0], r1b = gxB[Dd], r2b = gxB[2*Dd], r3b = gxB[3*Dd];
    for(int s=0;s<Ss;s++){
        float n0a=0.f,n1a=0.f,n2a=0.f,n3a=0.f, n0b=0.f,n1b=0.f,n2b=0.f,n3b=0.f;
        if (s+1 < Ss){
            const float* npA = gxA + (size_t)(s+1)*512;
            const float* npB = gxB + (size_t)(s+1)*512;
            n0a = npA[0]; n1a = npA[Dd]; n2a = npA[2*Dd]; n3a = npA[3*Dd];
            n0b = npB[0]; n1b = npB[Dd]; n2b = npB[2*Dd]; n3b = npB[3*Dd];
        }
        #pragma unroll
        for(int dq=0; dq<8; dq++){
            float4 w0 = *(const float4*)&rw[0][e][dq*4];
            float4 w1 = *(const float4*)&rw[1][e][dq*4];
            float4 w2 = *(const float4*)&rw[2][e][dq*4];
            float4 w3 = *(const float4*)&rw[3][e][dq*4];
            float4 ha = *(const float4*)&hs[w*2][dq*4];
            float4 hb = *(const float4*)&hs[w*2+1][dq*4];
            r0a += ha.x*w0.x + ha.y*w0.y + ha.z*w0.z + ha.w*w0.w;
            r1a += ha.x*w1.x + ha.y*w1.y + ha.z*w1.z + ha.w*w1.w;
            r2a += ha.x*w2.x + ha.y*w2.y + ha.z*w2.z + ha.w*w2.w;
            r3a += ha.x*w3.x + ha.y*w3.y + ha.z*w3.z + ha.w*w3.w;
            r0b += hb.x*w0.x + hb.y*w0.y + hb.z*w0.z + hb.w*w0.w;
            r1b += hb.x*w1.x + hb.y*w1.y + hb.z*w1.z + hb.w*w1.w;
            r2b += hb.x*w2.x + hb.y*w2.y + hb.z*w2.z + hb.w*w2.w;
            r3b += hb.x*w3.x + hb.y*w3.y + hb.z*w3.z + hb.w*w3.w;
        }
        float lfmA = mA + logsigf(r1a);
        float mnA  = fmaxf(r0a, lfmA);
        float iA   = __expf(r0a-mnA);
        float fA   = __expf(lfmA-mnA);
        cA  = fA*cA + iA*tanhfast(r2a);
        nnA = fA*nnA + iA;
        float hA = sigf(r3a) * __fdividef(cA, nnA);
        mA = mnA;

        float lfmB = mB + logsigf(r1b);
        float mnB  = fmaxf(r0b, lfmB);
        float iB   = __expf(r0b-mnB);
        float fB   = __expf(lfmB-mnB);
        cB  = fB*cB + iB*tanhfast(r2b);
        nnB = fB*nnB + iB;
        float hB = sigf(r3b) * __fdividef(cB, nnB);
        mB = mnB;

        __syncwarp();
        hs[w*2][e]   = hA;
        hs[w*2+1][e] = hB;
        __syncwarp();

        float s1 = hA, s2 = hA*hA, t1 = hB, t2 = hB*hB;
        #pragma unroll
        for(int o=16;o;o>>=1){
            s1 += __shfl_xor_sync(~0u,s1,o); s2 += __shfl_xor_sync(~0u,s2,o);
            t1 += __shfl_xor_sync(~0u,t1,o); t2 += __shfl_xor_sync(~0u,t2,o);
        }
        float muA = s1*(1.0f/HDs), varA = s2*(1.0f/HDs)-muA*muA;
        float muB = t1*(1.0f/HDs), varB = t2*(1.0f/HDs)-muB*muB;
        float rrA = rsqrtf(varA + 1e-5f);
        float rrB = rsqrtf(varB + 1e-5f);
        g_h[((size_t)(b0*Ss+s))*Dd + gb] += (hA-muA)*rrA*gnw;
        g_h[((size_t)(b1*Ss+s))*Dd + gb] += (hB-muB)*rrB*gnw;

        r0a = n0a; r1a = n1a; r2a = n2a; r3a = n3a;
        r0b = n0b; r1b = n1b; r2b = n2b; r3b = n3b;
    }
}

// ---------------- fused conv+silu+qkv+gates: 8 tokens per block --------------
__global__ void __launch_bounds__(256) k_cq(
        const float* __restrict__ cw, const float* __restrict__ cb,
        const float* __restrict__ qkvw, const float* __restrict__ gweff,
        const float* __restrict__ igb, const float* __restrict__ fgb){
    __shared__ float xms[11][256];
    __shared__ float xcv[8][256];
    __shared__ float4 Aig[256], Big[256], Afg[256], Bfg[256];
    int blk = blockIdx.x, b = blk>>3, sg = blk&7;
    int tid = threadIdx.x;
    int t0 = b*Ss + sg*8;

    Aig[tid] = *(const float4*)&gweff[0*1024 + tid*4];
    Big[tid] = *(const float4*)&gweff[1*1024 + tid*4];
    Afg[tid] = *(const float4*)&gweff[2*1024 + tid*4];
    Bfg[tid] = *(const float4*)&gweff[3*1024 + tid*4];

    for (int idx = tid; idx < 11*256; idx += 256){
        int r = idx >> 8, c = idx & 255;
        int s = sg*8 + r - 3;
        xms[r][c] = (s >= 0) ? g_big[(size_t)(b*Ss+s)*512 + c] : 0.0f;
    }
    int c = tid, n = c>>2, o = c&3;
    float cwv0=cw[c*4], cwv1=cw[c*4+1], cwv2=cw[c*4+2], cwv3=cw[c*4+3], cbv=cb[c];
    float wq[4], wk[4], wv[4];
    #pragma unroll
    for (int i2 = 0; i2 < 4; i2++){
        wq[i2] = qkvw[       n*16 + o*4 + i2];
        wk[i2] = qkvw[1024 + n*16 + o*4 + i2];
        wv[i2] = qkvw[2048 + n*16 + o*4 + i2];
    }
    __syncthreads();
    #pragma unroll
    for (int s = 0; s < 8; s++){
        float acc = cbv + xms[s][c]*cwv0 + xms[s+1][c]*cwv1 + xms[s+2][c]*cwv2 + xms[s+3][c]*cwv3;
        float xc = acc*sigf(acc);
        xcv[s][c] = xc;
        g_xconv[(size_t)(t0+s)*256 + c] = xc;
    }
    __syncthreads();
    #pragma unroll
    for (int s = 0; s < 8; s++){
        float q=0, k=0, v=0;
        #pragma unroll
        for (int i2 = 0; i2 < 4; i2++){
            float xc = xcv[s][n*4+i2];
            float xm = xms[s+3][n*4+i2];
            q += xc*wq[i2]; k += xc*wk[i2]; v += xm*wv[i2];
        }
        g_q[(size_t)(t0+s)*256 + c] = q;
        g_k[(size_t)(t0+s)*256 + c] = k;
        g_v[(size_t)(t0+s)*256 + c] = v;
    }
    int w = tid >> 5, lane = tid & 31;
    float4 ia = make_float4(0,0,0,0), fa = make_float4(0,0,0,0);
    for (int j = lane; j < 256; j += 32){
        float xc = xcv[w][j], xm = xms[w+3][j];
        float4 A = Aig[j], B = Big[j], A2 = Afg[j], B2 = Bfg[j];
        ia.x += xc*A.x + xm*B.x;  ia.y += xc*A.y + xm*B.y;
        ia.z += xc*A.z + xm*B.z;  ia.w += xc*A.w + xm*B.w;
        fa.x += xc*A2.x + xm*B2.x; fa.y += xc*A2.y + xm*B2.y;
        fa.z += xc*A2.z + xm*B2.z; fa.w += xc*A2.w + xm*B2.w;
    }
    #pragma unroll
    for (int o2=16;o2;o2>>=1){
        ia.x += __shfl_xor_sync(~0u,ia.x,o2); ia.y += __shfl_xor_sync(~0u,ia.y,o2);
        ia.z += __shfl_xor_sync(~0u,ia.z,o2); ia.w += __shfl_xor_sync(~0u,ia.w,o2);
        fa.x += __shfl_xor_sync(~0u,fa.x,o2); fa.y += __shfl_xor_sync(~0u,fa.y,o2);
        fa.z += __shfl_xor_sync(~0u,fa.z,o2); fa.w += __shfl_xor_sync(~0u,fa.w,o2);
    }
    if (lane == 0){
        int s_ = sg*8 + w;
        g_ig[(size_t)(b*NHMc+0)*Ss + s_] = ia.x + igb[0];
        g_ig[(size_t)(b*NHMc+1)*Ss + s_] = ia.y + igb[1];
        g_ig[(size_t)(b*NHMc+2)*Ss + s_] = ia.z + igb[2];
        g_ig[(size_t)(b*NHMc+3)*Ss + s_] = ia.w + igb[3];
        g_fg[(size_t)(b*NHMc+0)*Ss + s_] = fa.x + fgb[0];
        g_fg[(size_t)(b*NHMc+1)*Ss + s_] = fa.y + fgb[1];
        g_fg[(size_t)(b*NHMc+2)*Ss + s_] = fa.z + fgb[2];
        g_fg[(size_t)(b*NHMc+3)*Ss + s_] = fa.w + fgb[3];
    }
}

// ---------------- mLSTM attention + fused groupnorm/skip/silu combine --------
__global__ void __launch_bounds__(256) k_attn(const float* __restrict__ onw,
                                              const float* __restrict__ skip){
    int blk = blockIdx.x; int b = blk >> 2, hm = blk & 3;
    __shared__ float qs[Ss][DHMc+1], ks[Ss][DHMc+1], vs[Ss][DHMc+1];
    __shared__ float cldf[Ss+1], igs[Ss];
    __shared__ float cn[8][Ss];
    int tid = threadIdx.x;
    for(int l=tid; l<Ss*DHMc; l+=256){
        int j = l >> 6, d = l & 63;
        size_t base = ((size_t)(b*Ss+j))*INNERc + hm*DHMc + d;
        qs[j][d] = g_q[base];
        ks[j][d] = g_k[base];
        vs[j][d] = g_v[base];
    }
    if (tid < Ss){
        igs[tid] = g_ig[(size_t)(b*NHMc+hm)*Ss + tid];
        cldf[tid+1] = logsigf(g_fg[(size_t)(b*NHMc+hm)*Ss + tid]);
    }
    if (tid == 0) cldf[0] = 0.0f;
    __syncthreads();
    for (int off = 1; off < Ss; off <<= 1){
        float add = 0.0f;
        if (tid < Ss && tid >= off) add = cldf[tid+1-off];
        __syncthreads();
        if (tid < Ss && tid >= off) cldf[tid+1] += add;
        __syncthreads();
    }
    int w = tid >> 5, lane = tid & 31;
    int cg0 = hm*DHMc + lane, cg1 = cg0 + 32;
    float onw0 = onw[cg0], onw1 = onw[cg1];
    float sk0 = skip[cg0], sk1 = skip[cg1];
    for(int r=0;r<8;r++){
        int i = w*8 + r;
        int j1 = lane + 32;
        float dot0=0, dot1=0, ld0=-1e30f, ld1=-1e30f;
        if (lane <= i){
            #pragma unroll
            for(int d=0; d<DHMc; d++) dot0 += qs[i][d]*ks[lane][d];
            ld0 = cldf[i+1]-cldf[lane+1] + igs[lane];
        }
        if (j1 <= i){
            #pragma unroll
            for(int d=0; d<DHMc; d++) dot1 += qs[i][d]*ks[j1][d];
            ld1 = cldf[i+1]-cldf[j1+1] + igs[j1];
        }
        float mx = fmaxf(ld0, ld1);
        #pragma unroll
        for(int o=16;o;o>>=1) mx = fmaxf(mx, __shfl_xor_sync(~0u,mx,o));
        float cm0 = (lane <= i) ? dot0*0.125f*__expf(ld0-mx) : 0.0f;
        float cm1 = (j1   <= i) ? dot1*0.125f*__expf(ld1-mx) : 0.0f;
        float sm = cm0 + cm1;
        #pragma unroll
        for(int o=16;o;o>>=1) sm += __shfl_xor_sync(~0u,sm,o);
        float norm = fmaxf(fabsf(sm), __expf(-mx)) + 1e-6f;
        float rnorm = __fdividef(1.0f, norm);
        cn[w][lane] = cm0*rnorm;
        cn[w][j1]   = cm1*rnorm;
        __syncwarp();
        float a0=0, a1=0;
        for(int j=0;j<=i;j++){
            float cc = cn[w][j];
            a0 += cc*vs[j][lane];
            a1 += cc*vs[j][lane+32];
        }
        float s1 = a0+a1, s2 = a0*a0+a1*a1;
        #pragma unroll
        for(int o=16;o;o>>=1){ s1 += __shfl_xor_sync(~0u,s1,o); s2 += __shfl_xor_sync(~0u,s2,o); }
        float mu = s1*(1.0f/DHMc), var = s2*(1.0f/DHMc)-mu*mu;
        float rr = rsqrtf(var + 1e-5f);
        size_t t = (size_t)(b*Ss+i);
        float z0 = g_big[t*512 + 256 + cg0], z1 = g_big[t*512 + 256 + cg1];
        float x0 = g_xconv[t*256 + cg0],     x1 = g_xconv[t*256 + cg1];
        g_q[t*256 + cg0] = ((a0-mu)*rr*onw0 + sk0*x0) * z0*sigf(z0);
        g_q[t*256 + cg1] = ((a1-mu)*rr*onw1 + sk1*x1) * z1*sigf(z1);
        __syncwarp();
    }
}

// ---------------- host-side --------------------------------------------------
static float* symf(const void* s){ void* p=nullptr; cudaGetSymbolAddress(&p, s); return (float*)p; }

extern "C" void kernel_launch(void* const* d_in, const int* in_sizes, int n_in,
                              void* d_out, int out_size){
    const int*   x         = (const int*)  d_in[0];
    const float* embed     = (const float*)d_in[1];
    const float* s_ln1     = (const float*)d_in[2];
    const float* s_gates_w = (const float*)d_in[3];
    const float* s_rec     = (const float*)d_in[4];
    const float* s_bias    = (const float*)d_in[5];
    const float* s_gn      = (const float*)d_in[6];
    const float* s_ln2     = (const float*)d_in[7];
    const float* s_ff_up   = (const float*)d_in[8];
    const float* s_ff_down = (const float*)d_in[9];
    const float* m_ln1     = (const float*)d_in[10];
    const float* m_up      = (const float*)d_in[11];
    const float* m_conv_w  = (const float*)d_in[12];
    const float* m_conv_b  = (const float*)d_in[13];
    const float* m_qkv_w   = (const float*)d_in[14];
    const float* m_ig_w    = (const float*)d_in[15];
    const float* m_ig_b    = (const float*)d_in[16];
    const float* m_fg_w    = (const float*)d_in[17];
    const float* m_fg_b    = (const float*)d_in[18];
    const float* m_skip    = (const float*)d_in[19];
    const float* m_onorm   = (const float*)d_in[20];
    const float* m_down    = (const float*)d_in[21];
    const float* m_ln2     = (const float*)d_in[22];
    const float* m_ff_up   = (const float*)d_in[23];
    const float* m_ff_down = (const float*)d_in[24];
    const float* post_ln   = (const float*)d_in[25];
    const float* head_w    = (const float*)d_in[26];
    const float* head_b    = (const float*)d_in[27];

    float* h    = symf(g_h);
    float* big  = symf(g_big);
    float* ffn  = symf(g_ffn);
    float* qb   = symf(g_q);
    float* gweff= symf(g_gw_eff);

    float* out = (float*)d_out;

    cudaFuncSetAttribute(k_mgemm<false,true ,true ,false,8>, cudaFuncAttributeMaxDynamicSharedMemorySize, MG_SMEM);
    cudaFuncSetAttribute(k_mgemm<false,false,true ,false,8>, cudaFuncAttributeMaxDynamicSharedMemorySize, MG_SMEM);
    cudaFuncSetAttribute(k_mgemm<false,false,true ,false,4>, cudaFuncAttributeMaxDynamicSharedMemorySize, MG_SMEM);
    cudaFuncSetAttribute(k_mgemm<true ,false,false,true ,2>, cudaFuncAttributeMaxDynamicSharedMemorySize, MG_SMEM);
    cudaFuncSetAttribute(k_mgemm<true ,false,false,false,1>, cudaFuncAttributeMaxDynamicSharedMemorySize, MG_SMEM);
    cudaFuncSetAttribute(k_mgemm<false,true ,true ,false,4>, cudaFuncAttributeMaxDynamicSharedMemorySize, MG_SMEM);

    k_prep<<<546,256>>>(
        s_gates_w, s_gates_w + (size_t)4*NHs*HDs*HDs,
        s_ff_up, s_ff_down, m_up, m_down, m_ff_up, m_ff_down,
        s_ff_up + (size_t)Dd*2*FFc, s_ff_down + (size_t)FFc*Dd,
        m_up + (size_t)Dd*2*INNERc, m_down + (size_t)INNERc*Dd,
        m_ff_up + (size_t)Dd*2*FFc, m_ff_down + (size_t)FFc*Dd,
        head_w, m_qkv_w, m_ig_w, m_fg_w);
    k_embed<<<Tt, Dd>>>(x, embed);

    for(int i=0;i<2;i++){
        // ---- sLSTM ----
        k_mgemm<false,true,true,false,8><<<dim3(1, Tt/128),256,MG_SMEM>>>(
            h, big, s_bias + i*4*Dd, s_ln1 + i*Dd, W_SGX(i), 4*Dd, Dd);
        k_scan<<<NHs*(Bb/16),256>>>(s_rec + (size_t)i*4*NHs*HDs*HDs, s_gn + i*Dd);

        // ---- FFN 1 ----
        k_mgemm<false,false,true,false,4><<<dim3(1, Tt/128),256,MG_SMEM>>>(
            h, ffn, nullptr, s_ln2 + i*Dd, W_SFU(i), 2*FFc, Dd);
        k_mgemm<true,false,false,true,2><<<dim3(1, Tt/128),256,MG_SMEM>>>(
            ffn, h, nullptr, nullptr, W_SFD(i), Dd, FFc);

        // ---- mLSTM ----
        k_mgemm<false,false,true,false,8><<<dim3(1, Tt/128),256,MG_SMEM>>>(
            h, big, nullptr, m_ln1 + i*Dd, W_MUP(i), 2*INNERc, Dd);
        k_cq<<<Bb*8,256>>>(m_conv_w + (size_t)i*INNERc*Kc, m_conv_b + i*INNERc,
                           m_qkv_w + (size_t)i*3072, gweff + i*4096,
                           m_ig_b + i*NHMc, m_fg_b + i*NHMc);
        k_attn<<<Bb*NHMc,256>>>(m_onorm + i*INNERc, m_skip + i*INNERc);
        k_mgemm<true,false,false,false,1><<<dim3(2, Tt/128),256,MG_SMEM>>>(
            qb, h, nullptr, nullptr, W_MDN(i), Dd, INNERc);

        // ---- FFN 2 ----
        k_mgemm<false,false,true,false,4><<<dim3(1, Tt/128),256,MG_SMEM>>>(
            h, ffn, nullptr, m_ln2 + i*Dd, W_MFU(i), 2*FFc, Dd);
        k_mgemm<true,false,false,true,2><<<dim3(1, Tt/128),256,MG_SMEM>>>(
            ffn, h, nullptr, nullptr, W_MFD(i), Dd, FFc);
    }

    // ---- final LN + head ----
    k_mgemm<false,true,true,false,4><<<dim3(1, Tt/128),256,MG_SMEM>>>(
        h, out, head_b, post_ln, W_HEAD, Vv, Dd);
}

// round 14
// speedup vs baseline: 1.0324x; 1.0052x over previous
#include <cuda_runtime.h>
#include <cuda_bf16.h>
#include <math.h>
#include <stdint.h>

#define Bb     512
#define Ss     64
#define Dd     128
#define Vv     256
#define NHs    4
#define HDs    32
#define INNERc 256
#define NHMc   4
#define DHMc   64
#define NBc    64
#define Kc     4
#define FFc    128
#define Tt     (Bb*Ss)   /* 32768 tokens */

// ---------------- workspaces (static device globals; no allocation) ----------
__device__ float g_h[Tt*Dd];            // residual stream
__device__ float g_big[Tt*2*INNERc];    // slstm gx [t][512]  OR  mlstm up out [t][512]
__device__ float g_ffn[Tt*2*FFc];       // ffn up output
__device__ float g_xconv[Tt*INNERc];
__device__ float g_q[Tt*INNERc];        // q, later reused as mlstm combine buffer
__device__ float g_k[Tt*INNERc];
__device__ float g_v[Tt*INNERc];
__device__ float g_ig[Bb*NHMc*Ss];
__device__ float g_fg[Bb*NHMc*Ss];

// all GEMM weights, transposed+split [N][K]
#define W_SGX(i)  ((i)*262144 + 0)
#define W_SFU(i)  ((i)*262144 + 65536)
#define W_SFD(i)  ((i)*262144 + 98304)
#define W_MUP(i)  ((i)*262144 + 114688)
#define W_MDN(i)  ((i)*262144 + 180224)
#define W_MFU(i)  ((i)*262144 + 212992)
#define W_MFD(i)  ((i)*262144 + 245760)
#define W_HEAD    (524288)
#define W_TOTAL   (557056)
__device__ __nv_bfloat16 g_wt_hi[W_TOTAL];
__device__ __nv_bfloat16 g_wt_lo[W_TOTAL];
__device__ float g_gw_eff[2*4096];      // folded gate weights [L][4][256][4]

// ---------------- device math helpers (fast-math intrinsics) -----------------
__device__ __forceinline__ float sigf(float x){
    return __fdividef(1.0f, 1.0f + __expf(-x));
}
__device__ __forceinline__ float logsigf(float x){
    return fminf(x, 0.0f) - __logf(1.0f + __expf(-fabsf(x)));
}
__device__ __forceinline__ float tanhfast(float x){
    float t = __expf(-2.0f*fabsf(x));
    float r = __fdividef(1.0f - t, 1.0f + t);
    return copysignf(r, x);
}
__device__ __forceinline__ float geluf(float x){
    float x3 = x*x*x;
    return 0.5f*x*(1.0f+tanhfast(0.7978845608028654f*(x+0.044715f*x3)));
}
__device__ __forceinline__ uint32_t smem_u32(const void* p){
    uint32_t a;
    asm("{ .reg .u64 t; cvta.to.shared.u64 t, %1; cvt.u32.u64 %0, t; }" : "=r"(a) : "l"(p));
    return a;
}
__device__ __forceinline__ void split2(float a, float b, uint32_t &hi, uint32_t &lo){
    __nv_bfloat162 h = __floats2bfloat162_rn(a, b);
    float ra = a - __bfloat162float(h.x);
    float rb = b - __bfloat162float(h.y);
    __nv_bfloat162 l = __floats2bfloat162_rn(ra, rb);
    hi = *(uint32_t*)&h; lo = *(uint32_t*)&l;
}

#define LDM4(r0,r1,r2,r3,addr) \
    asm volatile("ldmatrix.sync.aligned.m8n8.x4.shared.b16 {%0,%1,%2,%3}, [%4];" \
        : "=r"(r0),"=r"(r1),"=r"(r2),"=r"(r3) : "r"(addr))

#define MMA16816(d,a,b) \
    asm volatile("mma.sync.aligned.m16n8k16.row.col.f32.bf16.bf16.f32 " \
        "{%0,%1,%2,%3}, {%4,%5,%6,%7}, {%8,%9}, {%0,%1,%2,%3};" \
        : "+f"((d)[0]),"+f"((d)[1]),"+f"((d)[2]),"+f"((d)[3]) \
        : "r"((a)[0]),"r"((a)[1]),"r"((a)[2]),"r"((a)[3]), "r"((b)[0]),"r"((b)[1]))

// smem layout: A tiles 128x136 bf16 (hi/lo), B tiles 64x136 bf16 (hi/lo)
#define MG_STRIDE 136
#define MG_AH 0
#define MG_AL (128*MG_STRIDE*2)
#define MG_BH (2*128*MG_STRIDE*2)
#define MG_BL (MG_BH + 64*MG_STRIDE*2)
#define MG_SMEM (MG_BL + 64*MG_STRIDE*2)   /* 104448 B */

// ---------------- tensor-core GEMM: C[M,N] (+)= f(A)[M,K] @ Wt^T (+bias) -----
// NB>1 (MULTIK=false) requires K==128: A staged once, NB 64-wide B sub-tiles.
// MULTIK=true: K=256, NB=2: persistent acc over k-chunks, A staged once/chunk.
template<bool ADD, bool BIAS, bool LN, bool GLU, int NB, bool MULTIK=false>
__global__ void __launch_bounds__(256,2) k_mgemm(
        const float* __restrict__ A, float* __restrict__ C,
        const float* __restrict__ bias, const float* __restrict__ lnw,
        int woff, int N, int K){
    extern __shared__ char smem[];
    const int tid = threadIdx.x, w = tid>>5, lane = tid&31;
    const int bm = blockIdx.y*128;
    const int wm = w & 3, wn = w >> 2;
    const int gID = lane >> 2, qid = lane & 3;

    const int a_row = lane & 15;
    const int a_koff = (lane >> 4) * 8;
    const int b_noff = (lane & 7) + ((lane >> 4) & 1) * 8;
    const int b_koff = ((lane >> 3) & 1) * 8;

    const uint32_t sb = smem_u32(smem);

    auto stageA = [&](int kc){
        #pragma unroll
        for (int it = 0; it < 8; it++){
            int g4 = tid + it*256;
            int row = g4 >> 4, kg = g4 & 15;
            float4 v0, v1;
            if (GLU){
                const float* ap = A + (size_t)(bm+row)*256 + kg*8;
                float4 gg0 = *(const float4*)ap,      gg1 = *(const float4*)(ap+4);
                float4 uu0 = *(const float4*)(ap+128), uu1 = *(const float4*)(ap+132);
                v0.x = geluf(gg0.x)*uu0.x; v0.y = geluf(gg0.y)*uu0.y;
                v0.z = geluf(gg0.z)*uu0.z; v0.w = geluf(gg0.w)*uu0.w;
                v1.x = geluf(gg1.x)*uu1.x; v1.y = geluf(gg1.y)*uu1.y;
                v1.z = geluf(gg1.z)*uu1.z; v1.w = geluf(gg1.w)*uu1.w;
            } else {
                const float4* ap = (const float4*)(A + (size_t)(bm+row)*K + kc*128 + kg*8);
                v0 = ap[0]; v1 = ap[1];
            }
            if (LN){
                float s  = v0.x+v0.y+v0.z+v0.w + v1.x+v1.y+v1.z+v1.w;
                float ss = v0.x*v0.x+v0.y*v0.y+v0.z*v0.z+v0.w*v0.w
                         + v1.x*v1.x+v1.y*v1.y+v1.z*v1.z+v1.w*v1.w;
                #pragma unroll
                for (int o = 1; o < 16; o <<= 1){
                    s  += __shfl_xor_sync(~0u, s,  o);
                    ss += __shfl_xor_sync(~0u, ss, o);
                }
                float mu  = s*(1.0f/128.0f);
                float var = ss*(1.0f/128.0f) - mu*mu;
                float rr  = rsqrtf(var + 1e-5f);
                float4 w0 = *(const float4*)&lnw[kg*8];
                float4 w1 = *(const float4*)&lnw[kg*8+4];
                v0.x = (v0.x-mu)*rr*w0.x; v0.y = (v0.y-mu)*rr*w0.y;
                v0.z = (v0.z-mu)*rr*w0.z; v0.w = (v0.w-mu)*rr*w0.w;
                v1.x = (v1.x-mu)*rr*w1.x; v1.y = (v1.y-mu)*rr*w1.y;
                v1.z = (v1.z-mu)*rr*w1.z; v1.w = (v1.w-mu)*rr*w1.w;
            }
            uint32_t h0,h1,h2,h3, l0,l1,l2,l3;
            split2(v0.x, v0.y, h0, l0);
            split2(v0.z, v0.w, h1, l1);
            split2(v1.x, v1.y, h2, l2);
            split2(v1.z, v1.w, h3, l3);
            uint32_t off = (uint32_t)(row*(MG_STRIDE*2) + kg*16);
            *(uint4*)(smem + MG_AH + off) = make_uint4(h0,h1,h2,h3);
            *(uint4*)(smem + MG_AL + off) = make_uint4(l0,l1,l2,l3);
        }
    };
    auto stageB = [&](int bn, int kc){
        #pragma unroll
        for (int it = 0; it < 4; it++){
            int g4 = tid + it*256;
            int n = g4 >> 4, kg = g4 & 15;
            size_t gi = (size_t)woff + (size_t)(bn+n)*K + kc*128 + kg*8;
            uint4 hv = *(const uint4*)(g_wt_hi + gi);
            uint4 lv = *(const uint4*)(g_wt_lo + gi);
            uint32_t off = (uint32_t)(n*(MG_STRIDE*2) + kg*16);
            *(uint4*)(smem + MG_BH + off) = hv;
            *(uint4*)(smem + MG_BL + off) = lv;
        }
    };
    auto compute = [&](float (&acc)[2][4][4]){
        #pragma unroll
        for (int ks = 0; ks < 8; ks++){
            uint32_t ah[2][4], al[2][4];
            #pragma unroll
            for (int mt = 0; mt < 2; mt++){
                uint32_t aoff = (uint32_t)((wm*32 + mt*16 + a_row)*(MG_STRIDE*2)
                                           + (ks*16 + a_koff)*2);
                LDM4(ah[mt][0],ah[mt][1],ah[mt][2],ah[mt][3], sb + MG_AH + aoff);
                LDM4(al[mt][0],al[mt][1],al[mt][2],al[mt][3], sb + MG_AL + aoff);
            }
            uint32_t bh[4][2], bl[4][2];
            #pragma unroll
            for (int ng = 0; ng < 2; ng++){
                uint32_t boff = (uint32_t)((wn*32 + ng*16 + b_noff)*(MG_STRIDE*2)
                                           + (ks*16 + b_koff)*2);
                uint32_t r0,r1,r2,r3;
                LDM4(r0,r1,r2,r3, sb + MG_BH + boff);
                bh[ng*2][0]=r0; bh[ng*2][1]=r1; bh[ng*2+1][0]=r2; bh[ng*2+1][1]=r3;
                LDM4(r0,r1,r2,r3, sb + MG_BL + boff);
                bl[ng*2][0]=r0; bl[ng*2][1]=r1; bl[ng*2+1][0]=r2; bl[ng*2+1][1]=r3;
            }
            #pragma unroll
            for (int mt = 0; mt < 2; mt++)
                #pragma unroll
                for (int nt = 0; nt < 4; nt++){
                    MMA16816(acc[mt][nt], ah[mt], bh[nt]);
                    MMA16816(acc[mt][nt], ah[mt], bl[nt]);
                    MMA16816(acc[mt][nt], al[mt], bh[nt]);
                }
        }
    };
    auto epilogue = [&](float (&acc)[2][4][4], int bn){
        #pragma unroll
        for (int mt = 0; mt < 2; mt++){
            #pragma unroll
            for (int nt = 0; nt < 4; nt++){
                int row0 = bm + wm*32 + mt*16 + gID;
                int col  = bn + wn*32 + nt*8 + qid*2;
                float2 v0 = make_float2(acc[mt][nt][0], acc[mt][nt][1]);
                float2 v1 = make_float2(acc[mt][nt][2], acc[mt][nt][3]);
                if (BIAS){
                    float2 bv = *(const float2*)&bias[col];
                    v0.x += bv.x; v0.y += bv.y;
                    v1.x += bv.x; v1.y += bv.y;
                }
                float* p0 = C + (size_t)row0*N + col;
                float* p1 = C + (size_t)(row0+8)*N + col;
                if (ADD){
                    float2 o0 = *(const float2*)p0, o1 = *(const float2*)p1;
                    v0.x += o0.x; v0.y += o0.y;
                    v1.x += o1.x; v1.y += o1.y;
                }
                *(float2*)p0 = v0;
                *(float2*)p1 = v1;
            }
        }
    };

    if constexpr (MULTIK){
        // K=256, NB=2: persistent acc over 2 k-chunks, single wave
        float acc[2][2][4][4] = {};
        const int bn0 = blockIdx.x*64*NB;
        const int nchunk = K >> 7;
        for (int kc = 0; kc < nchunk; kc++){
            stageA(kc);
            #pragma unroll
            for (int sub = 0; sub < NB; sub++){
                stageB(bn0 + sub*64, kc);
                __syncthreads();
                compute(acc[sub]);
                __syncthreads();
            }
        }
        #pragma unroll
        for (int sub = 0; sub < NB; sub++)
            epilogue(acc[sub], bn0 + sub*64);
    } else if constexpr (NB == 1){
        const int bn = blockIdx.x*64;
        float acc[2][4][4] = {};
        const int nchunk = K >> 7;
        for (int kc = 0; kc < nchunk; kc++){
            stageA(kc);
            stageB(bn, kc);
            __syncthreads();
            compute(acc);
            __syncthreads();
        }
        epilogue(acc, bn);
    } else {
        const int bn0 = blockIdx.x*64*NB;
        stageA(0);
        #pragma unroll
        for (int sub = 0; sub < NB; sub++){
            stageB(bn0 + sub*64, 0);
            __syncthreads();
            float acc[2][4][4] = {};
            compute(acc);
            epilogue(acc, bn0 + sub*64);
            __syncthreads();
        }
    }
}

// ---------------- one-shot weight prep: transposes + densify + gate folding --
__global__ void __launch_bounds__(256) k_prep(
    const float* sgw0, const float* sgw1,
    const float* sfu0, const float* sfd0, const float* mup0, const float* mdn0,
    const float* mfu0, const float* mfd0,
    const float* sfu1, const float* sfd1, const float* mup1, const float* mdn1,
    const float* mfu1, const float* mfd1,
    const float* headw,
    const float* qkvw, const float* igw, const float* fgw){
    int bx = blockIdx.x, tid = threadIdx.x;
    if (bx < 416){
        const int cum[13]  = {32,48,112,144,176,192,224,240,304,336,368,384,416};
        const float* srcs[13] = {sfu0,sfd0,mup0,mdn0,mfu0,mfd0,sfu1,sfd1,mup1,mdn1,mfu1,mfd1,headw};
        const int Ks[13]   = {128,128,128,256,128,128,128,128,128,256,128,128,128};
        const int Ns[13]   = {256,128,512,128,256,128,256,128,512,128,256,128,256};
        const int dsts[13] = {W_SFU(0),W_SFD(0),W_MUP(0),W_MDN(0),W_MFU(0),W_MFD(0),
                              W_SFU(1),W_SFD(1),W_MUP(1),W_MDN(1),W_MFU(1),W_MFD(1),W_HEAD};
        int j = 0;
        while (bx >= cum[j]) j++;
        int tile = bx - (j ? cum[j-1] : 0);
        const float* src = srcs[j];
        int K = Ks[j], N = Ns[j], dst = dsts[j];
        int tilesN = N >> 5;
        int bk = (tile / tilesN)*32, bn = (tile % tilesN)*32;
        __shared__ float t[32][33];
        int tx = tid & 31, ty = tid >> 5;
        #pragma unroll
        for (int r = 0; r < 32; r += 8)
            t[ty+r][tx] = src[(size_t)(bk+ty+r)*N + bn+tx];
        __syncthreads();
        #pragma unroll
        for (int r = 0; r < 32; r += 8){
            float v = t[tx][ty+r];
            __nv_bfloat16 h = __float2bfloat16(v);
            size_t o = (size_t)dst + (size_t)(bn+ty+r)*K + bk+tx;
            g_wt_hi[o] = h;
            g_wt_lo[o] = __float2bfloat16(v - __bfloat162float(h));
        }
    } else if (bx < 544){
        int bx2 = bx - 416;
        int L = bx2 >> 6, blk = bx2 & 63;
        const float* gw = L ? sgw1 : sgw0;
        #pragma unroll
        for (int u = 0; u < 4; u++){
            int idx = blk*1024 + u*256 + tid;     // over 128*512
            int d = idx >> 9;
            int o = idx & 511;
            int g = o >> 7;
            int ne = o & 127;
            int n = ne >> 5, e = ne & 31;
            float wv = 0.0f;
            if ((d >> 5) == n) wv = gw[(((g*NHs + n)*HDs + e)*HDs) + (d & 31)];
            __nv_bfloat16 h = __float2bfloat16(wv);
            size_t oo = (size_t)W_SGX(L) + (size_t)o*Dd + d;
            g_wt_hi[oo] = h;
            g_wt_lo[oo] = __float2bfloat16(wv - __bfloat162float(h));
        }
    } else {
        int L = bx - 544;
        const float* qw  = qkvw + L*3072;
        const float* igp = igw  + L*3072;
        const float* fgp = fgw  + L*3072;
        int c = tid, n = c >> 2, i = c & 3;
        float aig[4]={0,0,0,0}, big_[4]={0,0,0,0}, afg[4]={0,0,0,0}, bfg_[4]={0,0,0,0};
        #pragma unroll
        for (int o = 0; o < 4; o++){
            float w0 = qw[n*16+o*4+i];
            float w1 = qw[1024+n*16+o*4+i];
            float w2 = qw[2048+n*16+o*4+i];
            int j0 = (n*4+o)*4, j1 = (256+n*4+o)*4, j2 = (512+n*4+o)*4;
            #pragma unroll
            for (int hm = 0; hm < 4; hm++){
                aig[hm]  += w0*igp[j0+hm] + w1*igp[j1+hm];
                big_[hm] += w2*igp[j2+hm];
                afg[hm]  += w0*fgp[j0+hm] + w1*fgp[j1+hm];
                bfg_[hm] += w2*fgp[j2+hm];
            }
        }
        #pragma unroll
        for (int hm = 0; hm < 4; hm++){
            g_gw_eff[L*4096 + 0*1024 + c*4 + hm] = aig[hm];
            g_gw_eff[L*4096 + 1*1024 + c*4 + hm] = big_[hm];
            g_gw_eff[L*4096 + 2*1024 + c*4 + hm] = afg[hm];
            g_gw_eff[L*4096 + 3*1024 + c*4 + hm] = bfg_[hm];
        }
    }
}

// ---------------- embedding --------------------------------------------------
__global__ void k_embed(const int* __restrict__ x, const float* __restrict__ emb){
    int t = blockIdx.x;
    g_h[t*Dd + threadIdx.x] = emb[x[t]*Dd + threadIdx.x];
}

// ---------------- sLSTM scan: 8 warps/block, 2 batches/warp ------------------
__global__ void __launch_bounds__(256) k_scan(const float* __restrict__ rec,
                                              const float* __restrict__ gn){
    int n  = blockIdx.x & 3;
    int bg = blockIdx.x >> 2;            // 0..31
    int w  = threadIdx.x >> 5;           // 0..7
    int e  = threadIdx.x & 31;
    int b0 = bg*16 + w*2, b1 = b0 + 1;
    __shared__ float rw[4][HDs][36];
    __shared__ float hs[16][HDs];
    for (int idx = threadIdx.x; idx < 4*HDs*HDs; idx += 256){
        int g = idx >> 10, rem = idx & 1023;
        int e2 = rem >> 5, d = rem & 31;
        rw[g][e2][d] = rec[((size_t)(g*NHs+n)*HDs + e2)*HDs + d];
    }
    hs[w*2][e] = 0.0f;
    hs[w*2+1][e] = 0.0f;
    __syncthreads();
    const int gb = n*HDs + e;
    const float gnw = gn[gb];
    const float* gxA = g_big + (size_t)(b0*Ss)*512 + gb;
    const float* gxB = g_big + (size_t)(b1*Ss)*512 + gb;
    float cA=0.f, nnA=0.f, mA=0.f;
    float cB=0.f, nnB=0.f, mB=0.f;
    float r0a = gxA[0], r1a = gxA[Dd], r2a = gxA[2*Dd], r3a = gxA[3*Dd];
    float r0b = gxB[0], r1b = gxB[Dd], r2b = gxB[2*Dd], r3b = gxB[3*Dd];
    for(int s=0;s<Ss;s++){
        float n0a=0.f,n1a=0.f,n2a=0.f,n3a=0.f, n0b=0.f,n1b=0.f,n2b=0.f,n3b=0.f;
        if (s+1 < Ss){
            const float* npA = gxA + (size_t)(s+1)*512;
            const float* npB = gxB + (size_t)(s+1)*512;
            n0a = npA[0]; n1a = npA[Dd]; n2a = npA[2*Dd]; n3a = npA[3*Dd];
            n0b = npB[0]; n1b = npB[Dd]; n2b = npB[2*Dd]; n3b = npB[3*Dd];
        }
        #pragma unroll
        for(int dq=0; dq<8; dq++){
            float4 w0 = *(const float4*)&rw[0][e][dq*4];
            float4 w1 = *(const float4*)&rw[1][e][dq*4];
            float4 w2 = *(const float4*)&rw[2][e][dq*4];
            float4 w3 = *(const float4*)&rw[3][e][dq*4];
            float4 ha = *(const float4*)&hs[w*2][dq*4];
            float4 hb = *(const float4*)&hs[w*2+1][dq*4];
            r0a += ha.x*w0.x + ha.y*w0.y + ha.z*w0.z + ha.w*w0.w;
            r1a += ha.x*w1.x + ha.y*w1.y + ha.z*w1.z + ha.w*w1.w;
            r2a += ha.x*w2.x + ha.y*w2.y + ha.z*w2.z + ha.w*w2.w;
            r3a += ha.x*w3.x + ha.y*w3.y + ha.z*w3.z + ha.w*w3.w;
            r0b += hb.x*w0.x + hb.y*w0.y + hb.z*w0.z + hb.w*w0.w;
            r1b += hb.x*w1.x + hb.y*w1.y + hb.z*w1.z + hb.w*w1.w;
            r2b += hb.x*w2.x + hb.y*w2.y + hb.z*w2.z + hb.w*w2.w;
            r3b += hb.x*w3.x + hb.y*w3.y + hb.z*w3.z + hb.w*w3.w;
        }
        float lfmA = mA + logsigf(r1a);
        float mnA  = fmaxf(r0a, lfmA);
        float iA   = __expf(r0a-mnA);
        float fA   = __expf(lfmA-mnA);
        cA  = fA*cA + iA*tanhfast(r2a);
        nnA = fA*nnA + iA;
        float hA = sigf(r3a) * __fdividef(cA, nnA);
        mA = mnA;

        float lfmB = mB + logsigf(r1b);
        float mnB  = fmaxf(r0b, lfmB);
        float iB   = __expf(r0b-mnB);
        float fB   = __expf(lfmB-mnB);
        cB  = fB*cB + iB*tanhfast(r2b);
        nnB = fB*nnB + iB;
        float hB = sigf(r3b) * __fdividef(cB, nnB);
        mB = mnB;

        __syncwarp();
        hs[w*2][e]   = hA;
        hs[w*2+1][e] = hB;
        __syncwarp();

        float s1 = hA, s2 = hA*hA, t1 = hB, t2 = hB*hB;
        #pragma unroll
        for(int o=16;o;o>>=1){
            s1 += __shfl_xor_sync(~0u,s1,o); s2 += __shfl_xor_sync(~0u,s2,o);
            t1 += __shfl_xor_sync(~0u,t1,o); t2 += __shfl_xor_sync(~0u,t2,o);
        }
        float muA = s1*(1.0f/HDs), varA = s2*(1.0f/HDs)-muA*muA;
        float muB = t1*(1.0f/HDs), varB = t2*(1.0f/HDs)-muB*muB;
        float rrA = rsqrtf(varA + 1e-5f);
        float rrB = rsqrtf(varB + 1e-5f);
        g_h[((size_t)(b0*Ss+s))*Dd + gb] += (hA-muA)*rrA*gnw;
        g_h[((size_t)(b1*Ss+s))*Dd + gb] += (hB-muB)*rrB*gnw;

        r0a = n0a; r1a = n1a; r2a = n2a; r3a = n3a;
        r0b = n0b; r1b = n1b; r2b = n2b; r3b = n3b;
    }
}

// ---------------- fused conv+silu+qkv+gates: 8 tokens per block --------------
__global__ void __launch_bounds__(256) k_cq(
        const float* __restrict__ cw, const float* __restrict__ cb,
        const float* __restrict__ qkvw, const float* __restrict__ gweff,
        const float* __restrict__ igb, const float* __restrict__ fgb){
    __shared__ float xms[11][256];
    __shared__ float xcv[8][256];
    __shared__ float4 Aig[256], Big[256], Afg[256], Bfg[256];
    int blk = blockIdx.x, b = blk>>3, sg = blk&7;
    int tid = threadIdx.x;
    int t0 = b*Ss + sg*8;

    Aig[tid] = *(const float4*)&gweff[0*1024 + tid*4];
    Big[tid] = *(const float4*)&gweff[1*1024 + tid*4];
    Afg[tid] = *(const float4*)&gweff[2*1024 + tid*4];
    Bfg[tid] = *(const float4*)&gweff[3*1024 + tid*4];

    for (int idx = tid; idx < 11*256; idx += 256){
        int r = idx >> 8, c = idx & 255;
        int s = sg*8 + r - 3;
        xms[r][c] = (s >= 0) ? g_big[(size_t)(b*Ss+s)*512 + c] : 0.0f;
    }
    int c = tid, n = c>>2, o = c&3;
    float cwv0=cw[c*4], cwv1=cw[c*4+1], cwv2=cw[c*4+2], cwv3=cw[c*4+3], cbv=cb[c];
    float wq[4], wk[4], wv[4];
    #pragma unroll
    for (int i2 = 0; i2 < 4; i2++){
        wq[i2] = qkvw[       n*16 + o*4 + i2];
        wk[i2] = qkvw[1024 + n*16 + o*4 + i2];
        wv[i2] = qkvw[2048 + n*16 + o*4 + i2];
    }
    __syncthreads();
    #pragma unroll
    for (int s = 0; s < 8; s++){
        float acc = cbv + xms[s][c]*cwv0 + xms[s+1][c]*cwv1 + xms[s+2][c]*cwv2 + xms[s+3][c]*cwv3;
        float xc = acc*sigf(acc);
        xcv[s][c] = xc;
        g_xconv[(size_t)(t0+s)*256 + c] = xc;
    }
    __syncthreads();
    #pragma unroll
    for (int s = 0; s < 8; s++){
        float q=0, k=0, v=0;
        #pragma unroll
        for (int i2 = 0; i2 < 4; i2++){
            float xc = xcv[s][n*4+i2];
            float xm = xms[s+3][n*4+i2];
            q += xc*wq[i2]; k += xc*wk[i2]; v += xm*wv[i2];
        }
        g_q[(size_t)(t0+s)*256 + c] = q;
        g_k[(size_t)(t0+s)*256 + c] = k;
        g_v[(size_t)(t0+s)*256 + c] = v;
    }
    int w = tid >> 5, lane = tid & 31;
    float4 ia = make_float4(0,0,0,0), fa = make_float4(0,0,0,0);
    for (int j = lane; j < 256; j += 32){
        float xc = xcv[w][j], xm = xms[w+3][j];
        float4 A = Aig[j], B = Big[j], A2 = Afg[j], B2 = Bfg[j];
        ia.x += xc*A.x + xm*B.x;  ia.y += xc*A.y + xm*B.y;
        ia.z += xc*A.z + xm*B.z;  ia.w += xc*A.w + xm*B.w;
        fa.x += xc*A2.x + xm*B2.x; fa.y += xc*A2.y + xm*B2.y;
        fa.z += xc*A2.z + xm*B2.z; fa.w += xc*A2.w + xm*B2.w;
    }
    #pragma unroll
    for (int o2=16;o2;o2>>=1){
        ia.x += __shfl_xor_sync(~0u,ia.x,o2); ia.y += __shfl_xor_sync(~0u,ia.y,o2);
        ia.z += __shfl_xor_sync(~0u,ia.z,o2); ia.w += __shfl_xor_sync(~0u,ia.w,o2);
        fa.x += __shfl_xor_sync(~0u,fa.x,o2); fa.y += __shfl_xor_sync(~0u,fa.y,o2);
        fa.z += __shfl_xor_sync(~0u,fa.z,o2); fa.w += __shfl_xor_sync(~0u,fa.w,o2);
    }
    if (lane == 0){
        int s_ = sg*8 + w;
        g_ig[(size_t)(b*NHMc+0)*Ss + s_] = ia.x + igb[0];
        g_ig[(size_t)(b*NHMc+1)*Ss + s_] = ia.y + igb[1];
        g_ig[(size_t)(b*NHMc+2)*Ss + s_] = ia.z + igb[2];
        g_ig[(size_t)(b*NHMc+3)*Ss + s_] = ia.w + igb[3];
        g_fg[(size_t)(b*NHMc+0)*Ss + s_] = fa.x + fgb[0];
        g_fg[(size_t)(b*NHMc+1)*Ss + s_] = fa.y + fgb[1];
        g_fg[(size_t)(b*NHMc+2)*Ss + s_] = fa.z + fgb[2];
        g_fg[(size_t)(b*NHMc+3)*Ss + s_] = fa.w + fgb[3];
    }
}

// ---------------- mLSTM attention + fused groupnorm/skip/silu combine --------
// Row mapping i = r*8 + w balances AV-loop work across warps.
__global__ void __launch_bounds__(256) k_attn(const float* __restrict__ onw,
                                              const float* __restrict__ skip){
    int blk = blockIdx.x; int b = blk >> 2, hm = blk & 3;
    __shared__ float qs[Ss][DHMc+1], ks[Ss][DHMc+1], vs[Ss][DHMc+1];
    __shared__ float cldf[Ss+1], igs[Ss];
    __shared__ float cn[8][Ss];
    int tid = threadIdx.x;
    for(int l=tid; l<Ss*DHMc; l+=256){
        int j = l >> 6, d = l & 63;
        size_t base = ((size_t)(b*Ss+j))*INNERc + hm*DHMc + d;
        qs[j][d] = g_q[base];
        ks[j][d] = g_k[base];
        vs[j][d] = g_v[base];
    }
    if (tid < Ss){
        igs[tid] = g_ig[(size_t)(b*NHMc+hm)*Ss + tid];
        cldf[tid+1] = logsigf(g_fg[(size_t)(b*NHMc+hm)*Ss + tid]);
    }
    if (tid == 0) cldf[0] = 0.0f;
    __syncthreads();
    for (int off = 1; off < Ss; off <<= 1){
        float add = 0.0f;
        if (tid < Ss && tid >= off) add = cldf[tid+1-off];
        __syncthreads();
        if (tid < Ss && tid >= off) cldf[tid+1] += add;
        __syncthreads();
    }
    int w = tid >> 5, lane = tid & 31;
    int cg0 = hm*DHMc + lane, cg1 = cg0 + 32;
    float onw0 = onw[cg0], onw1 = onw[cg1];
    float sk0 = skip[cg0], sk1 = skip[cg1];
    for(int r=0;r<8;r++){
        int i = r*8 + w;                  // strided: balances per-warp work
        int j1 = lane + 32;
        float dot0=0, dot1=0, ld0=-1e30f, ld1=-1e30f;
        if (lane <= i){
            #pragma unroll
            for(int d=0; d<DHMc; d++) dot0 += qs[i][d]*ks[lane][d];
            ld0 = cldf[i+1]-cldf[lane+1] + igs[lane];
        }
        if (j1 <= i){
            #pragma unroll
            for(int d=0; d<DHMc; d++) dot1 += qs[i][d]*ks[j1][d];
            ld1 = cldf[i+1]-cldf[j1+1] + igs[j1];
        }
        float mx = fmaxf(ld0, ld1);
        #pragma unroll
        for(int o=16;o;o>>=1) mx = fmaxf(mx, __shfl_xor_sync(~0u,mx,o));
        float cm0 = (lane <= i) ? dot0*0.125f*__expf(ld0-mx) : 0.0f;
        float cm1 = (j1   <= i) ? dot1*0.125f*__expf(ld1-mx) : 0.0f;
        float sm = cm0 + cm1;
        #pragma unroll
        for(int o=16;o;o>>=1) sm += __shfl_xor_sync(~0u,sm,o);
        float norm = fmaxf(fabsf(sm), __expf(-mx)) + 1e-6f;
        float rnorm = __fdividef(1.0f, norm);
        cn[w][lane] = cm0*rnorm;
        cn[w][j1]   = cm1*rnorm;
        __syncwarp();
        float a0=0, a1=0;
        for(int j=0;j<=i;j++){
            float cc = cn[w][j];
            a0 += cc*vs[j][lane];
            a1 += cc*vs[j][lane+32];
        }
        float s1 = a0+a1, s2 = a0*a0+a1*a1;
        #pragma unroll
        for(int o=16;o;o>>=1){ s1 += __shfl_xor_sync(~0u,s1,o); s2 += __shfl_xor_sync(~0u,s2,o); }
        float mu = s1*(1.0f/DHMc), var = s2*(1.0f/DHMc)-mu*mu;
        float rr = rsqrtf(var + 1e-5f);
        size_t t = (size_t)(b*Ss+i);
        float z0 = g_big[t*512 + 256 + cg0], z1 = g_big[t*512 + 256 + cg1];
        float x0 = g_xconv[t*256 + cg0],     x1 = g_xconv[t*256 + cg1];
        g_q[t*256 + cg0] = ((a0-mu)*rr*onw0 + sk0*x0) * z0*sigf(z0);
        g_q[t*256 + cg1] = ((a1-mu)*rr*onw1 + sk1*x1) * z1*sigf(z1);
        __syncwarp();
    }
}

// ---------------- host-side --------------------------------------------------
static float* symf(const void* s){ void* p=nullptr; cudaGetSymbolAddress(&p, s); return (float*)p; }

extern "C" void kernel_launch(void* const* d_in, const int* in_sizes, int n_in,
                              void* d_out, int out_size){
    const int*   x         = (const int*)  d_in[0];
    const float* embed     = (const float*)d_in[1];
    const float* s_ln1     = (const float*)d_in[2];
    const float* s_gates_w = (const float*)d_in[3];
    const float* s_rec     = (const float*)d_in[4];
    const float* s_bias    = (const float*)d_in[5];
    const float* s_gn      = (const float*)d_in[6];
    const float* s_ln2     = (const float*)d_in[7];
    const float* s_ff_up   = (const float*)d_in[8];
    const float* s_ff_down = (const float*)d_in[9];
    const float* m_ln1     = (const float*)d_in[10];
    const float* m_up      = (const float*)d_in[11];
    const float* m_conv_w  = (const float*)d_in[12];
    const float* m_conv_b  = (const float*)d_in[13];
    const float* m_qkv_w   = (const float*)d_in[14];
    const float* m_ig_w    = (const float*)d_in[15];
    const float* m_ig_b    = (const float*)d_in[16];
    const float* m_fg_w    = (const float*)d_in[17];
    const float* m_fg_b    = (const float*)d_in[18];
    const float* m_skip    = (const float*)d_in[19];
    const float* m_onorm   = (const float*)d_in[20];
    const float* m_down    = (const float*)d_in[21];
    const float* m_ln2     = (const float*)d_in[22];
    const float* m_ff_up   = (const float*)d_in[23];
    const float* m_ff_down = (const float*)d_in[24];
    const float* post_ln   = (const float*)d_in[25];
    const float* head_w    = (const float*)d_in[26];
    const float* head_b    = (const float*)d_in[27];

    float* h    = symf(g_h);
    float* big  = symf(g_big);
    float* ffn  = symf(g_ffn);
    float* qb   = symf(g_q);
    float* gweff= symf(g_gw_eff);

    float* out = (float*)d_out;

    cudaFuncSetAttribute(k_mgemm<false,true ,true ,false,8,false>, cudaFuncAttributeMaxDynamicSharedMemorySize, MG_SMEM);
    cudaFuncSetAttribute(k_mgemm<false,false,true ,false,8,false>, cudaFuncAttributeMaxDynamicSharedMemorySize, MG_SMEM);
    cudaFuncSetAttribute(k_mgemm<false,false,true ,false,4,false>, cudaFuncAttributeMaxDynamicSharedMemorySize, MG_SMEM);
    cudaFuncSetAttribute(k_mgemm<true ,false,false,true ,2,false>, cudaFuncAttributeMaxDynamicSharedMemorySize, MG_SMEM);
    cudaFuncSetAttribute(k_mgemm<true ,false,false,false,2,true >, cudaFuncAttributeMaxDynamicSharedMemorySize, MG_SMEM);
    cudaFuncSetAttribute(k_mgemm<false,true ,true ,false,4,false>, cudaFuncAttributeMaxDynamicSharedMemorySize, MG_SMEM);

    k_prep<<<546,256>>>(
        s_gates_w, s_gates_w + (size_t)4*NHs*HDs*HDs,
        s_ff_up, s_ff_down, m_up, m_down, m_ff_up, m_ff_down,
        s_ff_up + (size_t)Dd*2*FFc, s_ff_down + (size_t)FFc*Dd,
        m_up + (size_t)Dd*2*INNERc, m_down + (size_t)INNERc*Dd,
        m_ff_up + (size_t)Dd*2*FFc, m_ff_down + (size_t)FFc*Dd,
        head_w, m_qkv_w, m_ig_w, m_fg_w);
    k_embed<<<Tt, Dd>>>(x, embed);

    for(int i=0;i<2;i++){
        // ---- sLSTM ----
        k_mgemm<false,true,true,false,8,false><<<dim3(1, Tt/128),256,MG_SMEM>>>(
            h, big, s_bias + i*4*Dd, s_ln1 + i*Dd, W_SGX(i), 4*Dd, Dd);
        k_scan<<<NHs*(Bb/16),256>>>(s_rec + (size_t)i*4*NHs*HDs*HDs, s_gn + i*Dd);

        // ---- FFN 1 ----
        k_mgemm<false,false,true,false,4,false><<<dim3(1, Tt/128),256,MG_SMEM>>>(
            h, ffn, nullptr, s_ln2 + i*Dd, W_SFU(i), 2*FFc, Dd);
        k_mgemm<true,false,false,true,2,false><<<dim3(1, Tt/128),256,MG_SMEM>>>(
            ffn, h, nullptr, nullptr, W_SFD(i), Dd, FFc);

        // ---- mLSTM ----
        k_mgemm<false,false,true,false,8,false><<<dim3(1, Tt/128),256,MG_SMEM>>>(
            h, big, nullptr, m_ln1 + i*Dd, W_MUP(i), 2*INNERc, Dd);
        k_cq<<<Bb*8,256>>>(m_conv_w + (size_t)i*INNERc*Kc, m_conv_b + i*INNERc,
                           m_qkv_w + (size_t)i*3072, gweff + i*4096,
                           m_ig_b + i*NHMc, m_fg_b + i*NHMc);
        k_attn<<<Bb*NHMc,256>>>(m_onorm + i*INNERc, m_skip + i*INNERc);
        k_mgemm<true,false,false,false,2,true><<<dim3(1, Tt/128),256,MG_SMEM>>>(
            qb, h, nullptr, nullptr, W_MDN(i), Dd, INNERc);

        // ---- FFN 2 ----
        k_mgemm<false,false,true,false,4,false><<<dim3(1, Tt/128),256,MG_SMEM>>>(
            h, ffn, nullptr, m_ln2 + i*Dd, W_MFU(i), 2*FFc, Dd);
        k_mgemm<true,false,false,true,2,false><<<dim3(1, Tt/128),256,MG_SMEM>>>(
            ffn, h, nullptr, nullptr, W_MFD(i), Dd, FFc);
    }

    // ---- final LN + head ----
    k_mgemm<false,true,true,false,4,false><<<dim3(1, Tt/128),256,MG_SMEM>>>(
        h, out, head_b, post_ln, W_HEAD, Vv, Dd);
}

// round 15
// speedup vs baseline: 1.0971x; 1.0627x over previous
#include <cuda_runtime.h>
#include <cuda_bf16.h>
#include <math.h>
#include <stdint.h>

#define Bb     512
#define Ss     64
#define Dd     128
#define Vv     256
#define NHs    4
#define HDs    32
#define INNERc 256
#define NHMc   4
#define DHMc   64
#define NBc    64
#define Kc     4
#define FFc    128
#define Tt     (Bb*Ss)   /* 32768 tokens */

// ---------------- workspaces (static device globals; no allocation) ----------
__device__ float g_h[Tt*Dd];            // residual stream
__device__ float g_big[Tt*2*INNERc];    // slstm gx [t][512]  OR  mlstm up out [t][512]
__device__ float g_ffn[Tt*2*FFc];       // ffn up output
__device__ float g_xconv[Tt*INNERc];
__device__ float g_q[Tt*INNERc];        // q, later reused as mlstm combine buffer
__device__ float g_k[Tt*INNERc];
__device__ float g_v[Tt*INNERc];
__device__ float g_ig[Bb*NHMc*Ss];
__device__ float g_fg[Bb*NHMc*Ss];

// all GEMM weights, transposed+split [N][K]
#define W_SGX(i)  ((i)*262144 + 0)
#define W_SFU(i)  ((i)*262144 + 65536)
#define W_SFD(i)  ((i)*262144 + 98304)
#define W_MUP(i)  ((i)*262144 + 114688)
#define W_MDN(i)  ((i)*262144 + 180224)
#define W_MFU(i)  ((i)*262144 + 212992)
#define W_MFD(i)  ((i)*262144 + 245760)
#define W_HEAD    (524288)
#define W_TOTAL   (557056)
__device__ __nv_bfloat16 g_wt_hi[W_TOTAL];
__device__ __nv_bfloat16 g_wt_lo[W_TOTAL];
__device__ float g_gw_eff[2*4096];      // folded gate weights [L][4][256][4]

// ---------------- device math helpers (fast-math intrinsics) -----------------
__device__ __forceinline__ float sigf(float x){
    return __fdividef(1.0f, 1.0f + __expf(-x));
}
__device__ __forceinline__ float logsigf(float x){
    return fminf(x, 0.0f) - __logf(1.0f + __expf(-fabsf(x)));
}
__device__ __forceinline__ float tanhfast(float x){
    float t = __expf(-2.0f*fabsf(x));
    float r = __fdividef(1.0f - t, 1.0f + t);
    return copysignf(r, x);
}
__device__ __forceinline__ float geluf(float x){
    float x3 = x*x*x;
    return 0.5f*x*(1.0f+tanhfast(0.7978845608028654f*(x+0.044715f*x3)));
}
__device__ __forceinline__ uint32_t smem_u32(const void* p){
    uint32_t a;
    asm("{ .reg .u64 t; cvta.to.shared.u64 t, %1; cvt.u32.u64 %0, t; }" : "=r"(a) : "l"(p));
    return a;
}
__device__ __forceinline__ void split2(float a, float b, uint32_t &hi, uint32_t &lo){
    __nv_bfloat162 h = __floats2bfloat162_rn(a, b);
    float ra = a - __bfloat162float(h.x);
    float rb = b - __bfloat162float(h.y);
    __nv_bfloat162 l = __floats2bfloat162_rn(ra, rb);
    hi = *(uint32_t*)&h; lo = *(uint32_t*)&l;
}

#define LDM4(r0,r1,r2,r3,addr) \
    asm volatile("ldmatrix.sync.aligned.m8n8.x4.shared.b16 {%0,%1,%2,%3}, [%4];" \
        : "=r"(r0),"=r"(r1),"=r"(r2),"=r"(r3) : "r"(addr))

#define MMA16816(d,a,b) \
    asm volatile("mma.sync.aligned.m16n8k16.row.col.f32.bf16.bf16.f32 " \
        "{%0,%1,%2,%3}, {%4,%5,%6,%7}, {%8,%9}, {%0,%1,%2,%3};" \
        : "+f"((d)[0]),"+f"((d)[1]),"+f"((d)[2]),"+f"((d)[3]) \
        : "r"((a)[0]),"r"((a)[1]),"r"((a)[2]),"r"((a)[3]), "r"((b)[0]),"r"((b)[1]))

// smem layout: A tiles 128x136 bf16 (hi/lo), B tiles 64x136 bf16 (hi/lo)
#define MG_STRIDE 136
#define MG_AH 0
#define MG_AL (128*MG_STRIDE*2)
#define MG_BH (2*128*MG_STRIDE*2)
#define MG_BL (MG_BH + 64*MG_STRIDE*2)
#define MG_SMEM (MG_BL + 64*MG_STRIDE*2)   /* 104448 B */

// ---------------- tensor-core GEMM: C[M,N] (+)= f(A)[M,K] @ Wt^T (+bias) -----
// NB>1 (MULTIK=false) requires K==128: A staged once, NB 64-wide B sub-tiles.
// MULTIK=true: K=256, NB=2: persistent acc over k-chunks, A staged once/chunk.
template<bool ADD, bool BIAS, bool LN, bool GLU, int NB, bool MULTIK=false>
__global__ void __launch_bounds__(256,2) k_mgemm(
        const float* __restrict__ A, float* __restrict__ C,
        const float* __restrict__ bias, const float* __restrict__ lnw,
        int woff, int N, int K){
    extern __shared__ char smem[];
    const int tid = threadIdx.x, w = tid>>5, lane = tid&31;
    const int bm = blockIdx.y*128;
    const int wm = w & 3, wn = w >> 2;
    const int gID = lane >> 2, qid = lane & 3;

    const int a_row = lane & 15;
    const int a_koff = (lane >> 4) * 8;
    const int b_noff = (lane & 7) + ((lane >> 4) & 1) * 8;
    const int b_koff = ((lane >> 3) & 1) * 8;

    const uint32_t sb = smem_u32(smem);

    auto stageA = [&](int kc){
        #pragma unroll
        for (int it = 0; it < 8; it++){
            int g4 = tid + it*256;
            int row = g4 >> 4, kg = g4 & 15;
            float4 v0, v1;
            if (GLU){
                const float* ap = A + (size_t)(bm+row)*256 + kg*8;
                float4 gg0 = *(const float4*)ap,      gg1 = *(const float4*)(ap+4);
                float4 uu0 = *(const float4*)(ap+128), uu1 = *(const float4*)(ap+132);
                v0.x = geluf(gg0.x)*uu0.x; v0.y = geluf(gg0.y)*uu0.y;
                v0.z = geluf(gg0.z)*uu0.z; v0.w = geluf(gg0.w)*uu0.w;
                v1.x = geluf(gg1.x)*uu1.x; v1.y = geluf(gg1.y)*uu1.y;
                v1.z = geluf(gg1.z)*uu1.z; v1.w = geluf(gg1.w)*uu1.w;
            } else {
                const float4* ap = (const float4*)(A + (size_t)(bm+row)*K + kc*128 + kg*8);
                v0 = ap[0]; v1 = ap[1];
            }
            if (LN){
                float s  = v0.x+v0.y+v0.z+v0.w + v1.x+v1.y+v1.z+v1.w;
                float ss = v0.x*v0.x+v0.y*v0.y+v0.z*v0.z+v0.w*v0.w
                         + v1.x*v1.x+v1.y*v1.y+v1.z*v1.z+v1.w*v1.w;
                #pragma unroll
                for (int o = 1; o < 16; o <<= 1){
                    s  += __shfl_xor_sync(~0u, s,  o);
                    ss += __shfl_xor_sync(~0u, ss, o);
                }
                float mu  = s*(1.0f/128.0f);
                float var = ss*(1.0f/128.0f) - mu*mu;
                float rr  = rsqrtf(var + 1e-5f);
                float4 w0 = *(const float4*)&lnw[kg*8];
                float4 w1 = *(const float4*)&lnw[kg*8+4];
                v0.x = (v0.x-mu)*rr*w0.x; v0.y = (v0.y-mu)*rr*w0.y;
                v0.z = (v0.z-mu)*rr*w0.z; v0.w = (v0.w-mu)*rr*w0.w;
                v1.x = (v1.x-mu)*rr*w1.x; v1.y = (v1.y-mu)*rr*w1.y;
                v1.z = (v1.z-mu)*rr*w1.z; v1.w = (v1.w-mu)*rr*w1.w;
            }
            uint32_t h0,h1,h2,h3, l0,l1,l2,l3;
            split2(v0.x, v0.y, h0, l0);
            split2(v0.z, v0.w, h1, l1);
            split2(v1.x, v1.y, h2, l2);
            split2(v1.z, v1.w, h3, l3);
            uint32_t off = (uint32_t)(row*(MG_STRIDE*2) + kg*16);
            *(uint4*)(smem + MG_AH + off) = make_uint4(h0,h1,h2,h3);
            *(uint4*)(smem + MG_AL + off) = make_uint4(l0,l1,l2,l3);
        }
    };
    auto stageB = [&](int bn, int kc){
        #pragma unroll
        for (int it = 0; it < 4; it++){
            int g4 = tid + it*256;
            int n = g4 >> 4, kg = g4 & 15;
            size_t gi = (size_t)woff + (size_t)(bn+n)*K + kc*128 + kg*8;
            uint4 hv = *(const uint4*)(g_wt_hi + gi);
            uint4 lv = *(const uint4*)(g_wt_lo + gi);
            uint32_t off = (uint32_t)(n*(MG_STRIDE*2) + kg*16);
            *(uint4*)(smem + MG_BH + off) = hv;
            *(uint4*)(smem + MG_BL + off) = lv;
        }
    };
    auto compute = [&](float (&acc)[2][4][4]){
        #pragma unroll
        for (int ks = 0; ks < 8; ks++){
            uint32_t ah[2][4], al[2][4];
            #pragma unroll
            for (int mt = 0; mt < 2; mt++){
                uint32_t aoff = (uint32_t)((wm*32 + mt*16 + a_row)*(MG_STRIDE*2)
                                           + (ks*16 + a_koff)*2);
                LDM4(ah[mt][0],ah[mt][1],ah[mt][2],ah[mt][3], sb + MG_AH + aoff);
                LDM4(al[mt][0],al[mt][1],al[mt][2],al[mt][3], sb + MG_AL + aoff);
            }
            uint32_t bh[4][2], bl[4][2];
            #pragma unroll
            for (int ng = 0; ng < 2; ng++){
                uint32_t boff = (uint32_t)((wn*32 + ng*16 + b_noff)*(MG_STRIDE*2)
                                           + (ks*16 + b_koff)*2);
                uint32_t r0,r1,r2,r3;
                LDM4(r0,r1,r2,r3, sb + MG_BH + boff);
                bh[ng*2][0]=r0; bh[ng*2][1]=r1; bh[ng*2+1][0]=r2; bh[ng*2+1][1]=r3;
                LDM4(r0,r1,r2,r3, sb + MG_BL + boff);
                bl[ng*2][0]=r0; bl[ng*2][1]=r1; bl[ng*2+1][0]=r2; bl[ng*2+1][1]=r3;
            }
            #pragma unroll
            for (int mt = 0; mt < 2; mt++)
                #pragma unroll
                for (int nt = 0; nt < 4; nt++){
                    MMA16816(acc[mt][nt], ah[mt], bh[nt]);
                    MMA16816(acc[mt][nt], ah[mt], bl[nt]);
                    MMA16816(acc[mt][nt], al[mt], bh[nt]);
                }
        }
    };
    auto epilogue = [&](float (&acc)[2][4][4], int bn){
        #pragma unroll
        for (int mt = 0; mt < 2; mt++){
            #pragma unroll
            for (int nt = 0; nt < 4; nt++){
                int row0 = bm + wm*32 + mt*16 + gID;
                int col  = bn + wn*32 + nt*8 + qid*2;
                float2 v0 = make_float2(acc[mt][nt][0], acc[mt][nt][1]);
                float2 v1 = make_float2(acc[mt][nt][2], acc[mt][nt][3]);
                if (BIAS){
                    float2 bv = *(const float2*)&bias[col];
                    v0.x += bv.x; v0.y += bv.y;
                    v1.x += bv.x; v1.y += bv.y;
                }
                float* p0 = C + (size_t)row0*N + col;
                float* p1 = C + (size_t)(row0+8)*N + col;
                if (ADD){
                    float2 o0 = *(const float2*)p0, o1 = *(const float2*)p1;
                    v0.x += o0.x; v0.y += o0.y;
                    v1.x += o1.x; v1.y += o1.y;
                }
                *(float2*)p0 = v0;
                *(float2*)p1 = v1;
            }
        }
    };

    if constexpr (MULTIK){
        float acc[2][2][4][4] = {};
        const int bn0 = blockIdx.x*64*NB;
        const int nchunk = K >> 7;
        for (int kc = 0; kc < nchunk; kc++){
            stageA(kc);
            #pragma unroll
            for (int sub = 0; sub < NB; sub++){
                stageB(bn0 + sub*64, kc);
                __syncthreads();
                compute(acc[sub]);
                __syncthreads();
            }
        }
        #pragma unroll
        for (int sub = 0; sub < NB; sub++)
            epilogue(acc[sub], bn0 + sub*64);
    } else if constexpr (NB == 1){
        const int bn = blockIdx.x*64;
        float acc[2][4][4] = {};
        const int nchunk = K >> 7;
        for (int kc = 0; kc < nchunk; kc++){
            stageA(kc);
            stageB(bn, kc);
            __syncthreads();
            compute(acc);
            __syncthreads();
        }
        epilogue(acc, bn);
    } else {
        const int bn0 = blockIdx.x*64*NB;
        stageA(0);
        #pragma unroll
        for (int sub = 0; sub < NB; sub++){
            stageB(bn0 + sub*64, 0);
            __syncthreads();
            float acc[2][4][4] = {};
            compute(acc);
            epilogue(acc, bn0 + sub*64);
            __syncthreads();
        }
    }
}

// ---------------- one-shot weight prep: transposes + densify + gate folding --
__global__ void __launch_bounds__(256) k_prep(
    const float* sgw0, const float* sgw1,
    const float* sfu0, const float* sfd0, const float* mup0, const float* mdn0,
    const float* mfu0, const float* mfd0,
    const float* sfu1, const float* sfd1, const float* mup1, const float* mdn1,
    const float* mfu1, const float* mfd1,
    const float* headw,
    const float* qkvw, const float* igw, const float* fgw){
    int bx = blockIdx.x, tid = threadIdx.x;
    if (bx < 416){
        const int cum[13]  = {32,48,112,144,176,192,224,240,304,336,368,384,416};
        const float* srcs[13] = {sfu0,sfd0,mup0,mdn0,mfu0,mfd0,sfu1,sfd1,mup1,mdn1,mfu1,mfd1,headw};
        const int Ks[13]   = {128,128,128,256,128,128,128,128,128,256,128,128,128};
        const int Ns[13]   = {256,128,512,128,256,128,256,128,512,128,256,128,256};
        const int dsts[13] = {W_SFU(0),W_SFD(0),W_MUP(0),W_MDN(0),W_MFU(0),W_MFD(0),
                              W_SFU(1),W_SFD(1),W_MUP(1),W_MDN(1),W_MFU(1),W_MFD(1),W_HEAD};
        int j = 0;
        while (bx >= cum[j]) j++;
        int tile = bx - (j ? cum[j-1] : 0);
        const float* src = srcs[j];
        int K = Ks[j], N = Ns[j], dst = dsts[j];
        int tilesN = N >> 5;
        int bk = (tile / tilesN)*32, bn = (tile % tilesN)*32;
        __shared__ float t[32][33];
        int tx = tid & 31, ty = tid >> 5;
        #pragma unroll
        for (int r = 0; r < 32; r += 8)
            t[ty+r][tx] = src[(size_t)(bk+ty+r)*N + bn+tx];
        __syncthreads();
        #pragma unroll
        for (int r = 0; r < 32; r += 8){
            float v = t[tx][ty+r];
            __nv_bfloat16 h = __float2bfloat16(v);
            size_t o = (size_t)dst + (size_t)(bn+ty+r)*K + bk+tx;
            g_wt_hi[o] = h;
            g_wt_lo[o] = __float2bfloat16(v - __bfloat162float(h));
        }
    } else if (bx < 544){
        int bx2 = bx - 416;
        int L = bx2 >> 6, blk = bx2 & 63;
        const float* gw = L ? sgw1 : sgw0;
        #pragma unroll
        for (int u = 0; u < 4; u++){
            int idx = blk*1024 + u*256 + tid;     // over 128*512
            int d = idx >> 9;
            int o = idx & 511;
            int g = o >> 7;
            int ne = o & 127;
            int n = ne >> 5, e = ne & 31;
            float wv = 0.0f;
            if ((d >> 5) == n) wv = gw[(((g*NHs + n)*HDs + e)*HDs) + (d & 31)];
            __nv_bfloat16 h = __float2bfloat16(wv);
            size_t oo = (size_t)W_SGX(L) + (size_t)o*Dd + d;
            g_wt_hi[oo] = h;
            g_wt_lo[oo] = __float2bfloat16(wv - __bfloat162float(h));
        }
    } else {
        int L = bx - 544;
        const float* qw  = qkvw + L*3072;
        const float* igp = igw  + L*3072;
        const float* fgp = fgw  + L*3072;
        int c = tid, n = c >> 2, i = c & 3;
        float aig[4]={0,0,0,0}, big_[4]={0,0,0,0}, afg[4]={0,0,0,0}, bfg_[4]={0,0,0,0};
        #pragma unroll
        for (int o = 0; o < 4; o++){
            float w0 = qw[n*16+o*4+i];
            float w1 = qw[1024+n*16+o*4+i];
            float w2 = qw[2048+n*16+o*4+i];
            int j0 = (n*4+o)*4, j1 = (256+n*4+o)*4, j2 = (512+n*4+o)*4;
            #pragma unroll
            for (int hm = 0; hm < 4; hm++){
                aig[hm]  += w0*igp[j0+hm] + w1*igp[j1+hm];
                big_[hm] += w2*igp[j2+hm];
                afg[hm]  += w0*fgp[j0+hm] + w1*fgp[j1+hm];
                bfg_[hm] += w2*fgp[j2+hm];
            }
        }
        #pragma unroll
        for (int hm = 0; hm < 4; hm++){
            g_gw_eff[L*4096 + 0*1024 + c*4 + hm] = aig[hm];
            g_gw_eff[L*4096 + 1*1024 + c*4 + hm] = big_[hm];
            g_gw_eff[L*4096 + 2*1024 + c*4 + hm] = afg[hm];
            g_gw_eff[L*4096 + 3*1024 + c*4 + hm] = bfg_[hm];
        }
    }
}

// ---------------- embedding --------------------------------------------------
__global__ void k_embed(const int* __restrict__ x, const float* __restrict__ emb){
    int t = blockIdx.x;
    g_h[t*Dd + threadIdx.x] = emb[x[t]*Dd + threadIdx.x];
}

// ---------------- sLSTM scan: 8 warps/block, 2 batches/warp ------------------
__global__ void __launch_bounds__(256) k_scan(const float* __restrict__ rec,
                                              const float* __restrict__ gn){
    int n  = blockIdx.x & 3;
    int bg = blockIdx.x >> 2;            // 0..31
    int w  = threadIdx.x >> 5;           // 0..7
    int e  = threadIdx.x & 31;
    int b0 = bg*16 + w*2, b1 = b0 + 1;
    __shared__ float rw[4][HDs][36];
    __shared__ float hs[16][HDs];
    for (int idx = threadIdx.x; idx < 4*HDs*HDs; idx += 256){
        int g = idx >> 10, rem = idx & 1023;
        int e2 = rem >> 5, d = rem & 31;
        rw[g][e2][d] = rec[((size_t)(g*NHs+n)*HDs + e2)*HDs + d];
    }
    hs[w*2][e] = 0.0f;
    hs[w*2+1][e] = 0.0f;
    __syncthreads();
    const int gb = n*HDs + e;
    const float gnw = gn[gb];
    const float* gxA = g_big + (size_t)(b0*Ss)*512 + gb;
    const float* gxB = g_big + (size_t)(b1*Ss)*512 + gb;
    float cA=0.f, nnA=0.f, mA=0.f;
    float cB=0.f, nnB=0.f, mB=0.f;
    float r0a = gxA[0], r1a = gxA[Dd], r2a = gxA[2*Dd], r3a = gxA[3*Dd];
    float r0b = gxB[0], r1b = gxB[Dd], r2b = gxB[2*Dd], r3b = gxB[3*Dd];
    for(int s=0;s<Ss;s++){
        float n0a=0.f,n1a=0.f,n2a=0.f,n3a=0.f, n0b=0.f,n1b=0.f,n2b=0.f,n3b=0.f;
        if (s+1 < Ss){
            const float* npA = gxA + (size_t)(s+1)*512;
            const float* npB = gxB + (size_t)(s+1)*512;
            n0a = npA[0]; n1a = npA[Dd]; n2a = npA[2*Dd]; n3a = npA[3*Dd];
            n0b = npB[0]; n1b = npB[Dd]; n2b = npB[2*Dd]; n3b = npB[3*Dd];
        }
        #pragma unroll
        for(int dq=0; dq<8; dq++){
            float4 w0 = *(const float4*)&rw[0][e][dq*4];
            float4 w1 = *(const float4*)&rw[1][e][dq*4];
            float4 w2 = *(const float4*)&rw[2][e][dq*4];
            float4 w3 = *(const float4*)&rw[3][e][dq*4];
            float4 ha = *(const float4*)&hs[w*2][dq*4];
            float4 hb = *(const float4*)&hs[w*2+1][dq*4];
            r0a += ha.x*w0.x + ha.y*w0.y + ha.z*w0.z + ha.w*w0.w;
            r1a += ha.x*w1.x + ha.y*w1.y + ha.z*w1.z + ha.w*w1.w;
            r2a += ha.x*w2.x + ha.y*w2.y + ha.z*w2.z + ha.w*w2.w;
            r3a += ha.x*w3.x + ha.y*w3.y + ha.z*w3.z + ha.w*w3.w;
            r0b += hb.x*w0.x + hb.y*w0.y + hb.z*w0.z + hb.w*w0.w;
            r1b += hb.x*w1.x + hb.y*w1.y + hb.z*w1.z + hb.w*w1.w;
            r2b += hb.x*w2.x + hb.y*w2.y + hb.z*w2.z + hb.w*w2.w;
            r3b += hb.x*w3.x + hb.y*w3.y + hb.z*w3.z + hb.w*w3.w;
        }
        float lfmA = mA + logsigf(r1a);
        float mnA  = fmaxf(r0a, lfmA);
        float iA   = __expf(r0a-mnA);
        float fA   = __expf(lfmA-mnA);
        cA  = fA*cA + iA*tanhfast(r2a);
        nnA = fA*nnA + iA;
        float hA = sigf(r3a) * __fdividef(cA, nnA);
        mA = mnA;

        float lfmB = mB + logsigf(r1b);
        float mnB  = fmaxf(r0b, lfmB);
        float iB   = __expf(r0b-mnB);
        float fB   = __expf(lfmB-mnB);
        cB  = fB*cB + iB*tanhfast(r2b);
        nnB = fB*nnB + iB;
        float hB = sigf(r3b) * __fdividef(cB, nnB);
        mB = mnB;

        __syncwarp();
        hs[w*2][e]   = hA;
        hs[w*2+1][e] = hB;
        __syncwarp();

        float s1 = hA, s2 = hA*hA, t1 = hB, t2 = hB*hB;
        #pragma unroll
        for(int o=16;o;o>>=1){
            s1 += __shfl_xor_sync(~0u,s1,o); s2 += __shfl_xor_sync(~0u,s2,o);
            t1 += __shfl_xor_sync(~0u,t1,o); t2 += __shfl_xor_sync(~0u,t2,o);
        }
        float muA = s1*(1.0f/HDs), varA = s2*(1.0f/HDs)-muA*muA;
        float muB = t1*(1.0f/HDs), varB = t2*(1.0f/HDs)-muB*muB;
        float rrA = rsqrtf(varA + 1e-5f);
        float rrB = rsqrtf(varB + 1e-5f);
        g_h[((size_t)(b0*Ss+s))*Dd + gb] += (hA-muA)*rrA*gnw;
        g_h[((size_t)(b1*Ss+s))*Dd + gb] += (hB-muB)*rrB*gnw;

        r0a = n0a; r1a = n1a; r2a = n2a; r3a = n3a;
        r0b = n0b; r1b = n1b; r2b = n2b; r3b = n3b;
    }
}

// ---------------- fused conv+silu+qkv+gates: 8 tokens per block --------------
__global__ void __launch_bounds__(256) k_cq(
        const float* __restrict__ cw, const float* __restrict__ cb,
        const float* __restrict__ qkvw, const float* __restrict__ gweff,
        const float* __restrict__ igb, const float* __restrict__ fgb){
    __shared__ float xms[11][256];
    __shared__ float xcv[8][256];
    __shared__ float4 Aig[256], Big[256], Afg[256], Bfg[256];
    int blk = blockIdx.x, b = blk>>3, sg = blk&7;
    int tid = threadIdx.x;
    int t0 = b*Ss + sg*8;

    Aig[tid] = *(const float4*)&gweff[0*1024 + tid*4];
    Big[tid] = *(const float4*)&gweff[1*1024 + tid*4];
    Afg[tid] = *(const float4*)&gweff[2*1024 + tid*4];
    Bfg[tid] = *(const float4*)&gweff[3*1024 + tid*4];

    for (int idx = tid; idx < 11*256; idx += 256){
        int r = idx >> 8, c = idx & 255;
        int s = sg*8 + r - 3;
        xms[r][c] = (s >= 0) ? g_big[(size_t)(b*Ss+s)*512 + c] : 0.0f;
    }
    int c = tid, n = c>>2, o = c&3;
    float cwv0=cw[c*4], cwv1=cw[c*4+1], cwv2=cw[c*4+2], cwv3=cw[c*4+3], cbv=cb[c];
    float wq[4], wk[4], wv[4];
    #pragma unroll
    for (int i2 = 0; i2 < 4; i2++){
        wq[i2] = qkvw[       n*16 + o*4 + i2];
        wk[i2] = qkvw[1024 + n*16 + o*4 + i2];
        wv[i2] = qkvw[2048 + n*16 + o*4 + i2];
    }
    __syncthreads();
    #pragma unroll
    for (int s = 0; s < 8; s++){
        float acc = cbv + xms[s][c]*cwv0 + xms[s+1][c]*cwv1 + xms[s+2][c]*cwv2 + xms[s+3][c]*cwv3;
        float xc = acc*sigf(acc);
        xcv[s][c] = xc;
        g_xconv[(size_t)(t0+s)*256 + c] = xc;
    }
    __syncthreads();
    #pragma unroll
    for (int s = 0; s < 8; s++){
        float q=0, k=0, v=0;
        #pragma unroll
        for (int i2 = 0; i2 < 4; i2++){
            float xc = xcv[s][n*4+i2];
            float xm = xms[s+3][n*4+i2];
            q += xc*wq[i2]; k += xc*wk[i2]; v += xm*wv[i2];
        }
        g_q[(size_t)(t0+s)*256 + c] = q;
        g_k[(size_t)(t0+s)*256 + c] = k;
        g_v[(size_t)(t0+s)*256 + c] = v;
    }
    int w = tid >> 5, lane = tid & 31;
    float4 ia = make_float4(0,0,0,0), fa = make_float4(0,0,0,0);
    for (int j = lane; j < 256; j += 32){
        float xc = xcv[w][j], xm = xms[w+3][j];
        float4 A = Aig[j], B = Big[j], A2 = Afg[j], B2 = Bfg[j];
        ia.x += xc*A.x + xm*B.x;  ia.y += xc*A.y + xm*B.y;
        ia.z += xc*A.z + xm*B.z;  ia.w += xc*A.w + xm*B.w;
        fa.x += xc*A2.x + xm*B2.x; fa.y += xc*A2.y + xm*B2.y;
        fa.z += xc*A2.z + xm*B2.z; fa.w += xc*A2.w + xm*B2.w;
    }
    #pragma unroll
    for (int o2=16;o2;o2>>=1){
        ia.x += __shfl_xor_sync(~0u,ia.x,o2); ia.y += __shfl_xor_sync(~0u,ia.y,o2);
        ia.z += __shfl_xor_sync(~0u,ia.z,o2); ia.w += __shfl_xor_sync(~0u,ia.w,o2);
        fa.x += __shfl_xor_sync(~0u,fa.x,o2); fa.y += __shfl_xor_sync(~0u,fa.y,o2);
        fa.z += __shfl_xor_sync(~0u,fa.z,o2); fa.w += __shfl_xor_sync(~0u,fa.w,o2);
    }
    if (lane == 0){
        int s_ = sg*8 + w;
        g_ig[(size_t)(b*NHMc+0)*Ss + s_] = ia.x + igb[0];
        g_ig[(size_t)(b*NHMc+1)*Ss + s_] = ia.y + igb[1];
        g_ig[(size_t)(b*NHMc+2)*Ss + s_] = ia.z + igb[2];
        g_ig[(size_t)(b*NHMc+3)*Ss + s_] = ia.w + igb[3];
        g_fg[(size_t)(b*NHMc+0)*Ss + s_] = fa.x + fgb[0];
        g_fg[(size_t)(b*NHMc+1)*Ss + s_] = fa.y + fgb[1];
        g_fg[(size_t)(b*NHMc+2)*Ss + s_] = fa.z + fgb[2];
        g_fg[(size_t)(b*NHMc+3)*Ss + s_] = fa.w + fgb[3];
    }
}

// ---------------- mLSTM attention + fused groupnorm/skip/silu combine --------
// Rows padded to 68 floats: float4-aligned, conflict-free LDS.128.
#define APAD 68
__global__ void __launch_bounds__(256) k_attn(const float* __restrict__ onw,
                                              const float* __restrict__ skip){
    int blk = blockIdx.x; int b = blk >> 2, hm = blk & 3;
    __shared__ float qs[Ss][APAD], ks[Ss][APAD], vs[Ss][APAD];
    __shared__ float cldf[Ss+1], igs[Ss];
    __shared__ float cn[8][Ss];
    int tid = threadIdx.x;
    // float4 staging: Ss*16 float4 slots per tensor
    for (int l = tid; l < Ss*16; l += 256){
        int j = l >> 4, d4 = l & 15;
        size_t base = ((size_t)(b*Ss+j))*INNERc + hm*DHMc + d4*4;
        *(float4*)&qs[j][d4*4] = *(const float4*)&g_q[base];
        *(float4*)&ks[j][d4*4] = *(const float4*)&g_k[base];
        *(float4*)&vs[j][d4*4] = *(const float4*)&g_v[base];
    }
    if (tid < Ss){
        igs[tid] = g_ig[(size_t)(b*NHMc+hm)*Ss + tid];
        cldf[tid+1] = logsigf(g_fg[(size_t)(b*NHMc+hm)*Ss + tid]);
    }
    if (tid == 0) cldf[0] = 0.0f;
    __syncthreads();
    for (int off = 1; off < Ss; off <<= 1){
        float add = 0.0f;
        if (tid < Ss && tid >= off) add = cldf[tid+1-off];
        __syncthreads();
        if (tid < Ss && tid >= off) cldf[tid+1] += add;
        __syncthreads();
    }
    int w = tid >> 5, lane = tid & 31;
    int cg0 = hm*DHMc + lane, cg1 = cg0 + 32;
    float onw0 = onw[cg0], onw1 = onw[cg1];
    float sk0 = skip[cg0], sk1 = skip[cg1];
    for(int r=0;r<8;r++){
        int i = r*8 + w;
        int j1 = lane + 32;
        float dot0=0, dot1=0, ld0=-1e30f, ld1=-1e30f;
        if (lane <= i){
            #pragma unroll
            for(int dq=0; dq<16; dq++){
                float4 qv = *(const float4*)&qs[i][dq*4];
                float4 kv = *(const float4*)&ks[lane][dq*4];
                dot0 += qv.x*kv.x + qv.y*kv.y + qv.z*kv.z + qv.w*kv.w;
            }
            ld0 = cldf[i+1]-cldf[lane+1] + igs[lane];
        }
        if (j1 <= i){
            #pragma unroll
            for(int dq=0; dq<16; dq++){
                float4 qv = *(const float4*)&qs[i][dq*4];
                float4 kv = *(const float4*)&ks[j1][dq*4];
                dot1 += qv.x*kv.x + qv.y*kv.y + qv.z*kv.z + qv.w*kv.w;
            }
            ld1 = cldf[i+1]-cldf[j1+1] + igs[j1];
        }
        float mx = fmaxf(ld0, ld1);
        #pragma unroll
        for(int o=16;o;o>>=1) mx = fmaxf(mx, __shfl_xor_sync(~0u,mx,o));
        float cm0 = (lane <= i) ? dot0*0.125f*__expf(ld0-mx) : 0.0f;
        float cm1 = (j1   <= i) ? dot1*0.125f*__expf(ld1-mx) : 0.0f;
        float sm = cm0 + cm1;
        #pragma unroll
        for(int o=16;o;o>>=1) sm += __shfl_xor_sync(~0u,sm,o);
        float norm = fmaxf(fabsf(sm), __expf(-mx)) + 1e-6f;
        float rnorm = __fdividef(1.0f, norm);
        cn[w][lane] = cm0*rnorm;
        cn[w][j1]   = cm1*rnorm;
        __syncwarp();
        float a0=0, a1=0;
        for(int j=0;j<=i;j++){
            float cc = cn[w][j];
            a0 += cc*vs[j][lane];
            a1 += cc*vs[j][lane+32];
        }
        float s1 = a0+a1, s2 = a0*a0+a1*a1;
        #pragma unroll
        for(int o=16;o;o>>=1){ s1 += __shfl_xor_sync(~0u,s1,o); s2 += __shfl_xor_sync(~0u,s2,o); }
        float mu = s1*(1.0f/DHMc), var = s2*(1.0f/DHMc)-mu*mu;
        float rr = rsqrtf(var + 1e-5f);
        size_t t = (size_t)(b*Ss+i);
        float z0 = g_big[t*512 + 256 + cg0], z1 = g_big[t*512 + 256 + cg1];
        float x0 = g_xconv[t*256 + cg0],     x1 = g_xconv[t*256 + cg1];
        g_q[t*256 + cg0] = ((a0-mu)*rr*onw0 + sk0*x0) * z0*sigf(z0);
        g_q[t*256 + cg1] = ((a1-mu)*rr*onw1 + sk1*x1) * z1*sigf(z1);
        __syncwarp();
    }
}

// ---------------- host-side --------------------------------------------------
static float* symf(const void* s){ void* p=nullptr; cudaGetSymbolAddress(&p, s); return (float*)p; }

extern "C" void kernel_launch(void* const* d_in, const int* in_sizes, int n_in,
                              void* d_out, int out_size){
    const int*   x         = (const int*)  d_in[0];
    const float* embed     = (const float*)d_in[1];
    const float* s_ln1     = (const float*)d_in[2];
    const float* s_gates_w = (const float*)d_in[3];
    const float* s_rec     = (const float*)d_in[4];
    const float* s_bias    = (const float*)d_in[5];
    const float* s_gn      = (const float*)d_in[6];
    const float* s_ln2     = (const float*)d_in[7];
    const float* s_ff_up   = (const float*)d_in[8];
    const float* s_ff_down = (const float*)d_in[9];
    const float* m_ln1     = (const float*)d_in[10];
    const float* m_up      = (const float*)d_in[11];
    const float* m_conv_w  = (const float*)d_in[12];
    const float* m_conv_b  = (const float*)d_in[13];
    const float* m_qkv_w   = (const float*)d_in[14];
    const float* m_ig_w    = (const float*)d_in[15];
    const float* m_ig_b    = (const float*)d_in[16];
    const float* m_fg_w    = (const float*)d_in[17];
    const float* m_fg_b    = (const float*)d_in[18];
    const float* m_skip    = (const float*)d_in[19];
    const float* m_onorm   = (const float*)d_in[20];
    const float* m_down    = (const float*)d_in[21];
    const float* m_ln2     = (const float*)d_in[22];
    const float* m_ff_up   = (const float*)d_in[23];
    const float* m_ff_down = (const float*)d_in[24];
    const float* post_ln   = (const float*)d_in[25];
    const float* head_w    = (const float*)d_in[26];
    const float* head_b    = (const float*)d_in[27];

    float* h    = symf(g_h);
    float* big  = symf(g_big);
    float* ffn  = symf(g_ffn);
    float* qb   = symf(g_q);
    float* gweff= symf(g_gw_eff);

    float* out = (float*)d_out;

    cudaFuncSetAttribute(k_mgemm<false,true ,true ,false,8,false>, cudaFuncAttributeMaxDynamicSharedMemorySize, MG_SMEM);
    cudaFuncSetAttribute(k_mgemm<false,false,true ,false,8,false>, cudaFuncAttributeMaxDynamicSharedMemorySize, MG_SMEM);
    cudaFuncSetAttribute(k_mgemm<false,false,true ,false,4,false>, cudaFuncAttributeMaxDynamicSharedMemorySize, MG_SMEM);
    cudaFuncSetAttribute(k_mgemm<true ,false,false,true ,2,false>, cudaFuncAttributeMaxDynamicSharedMemorySize, MG_SMEM);
    cudaFuncSetAttribute(k_mgemm<true ,false,false,false,2,true >, cudaFuncAttributeMaxDynamicSharedMemorySize, MG_SMEM);
    cudaFuncSetAttribute(k_mgemm<false,true ,true ,false,4,false>, cudaFuncAttributeMaxDynamicSharedMemorySize, MG_SMEM);

    k_prep<<<546,256>>>(
        s_gates_w, s_gates_w + (size_t)4*NHs*HDs*HDs,
        s_ff_up, s_ff_down, m_up, m_down, m_ff_up, m_ff_down,
        s_ff_up + (size_t)Dd*2*FFc, s_ff_down + (size_t)FFc*Dd,
        m_up + (size_t)Dd*2*INNERc, m_down + (size_t)INNERc*Dd,
        m_ff_up + (size_t)Dd*2*FFc, m_ff_down + (size_t)FFc*Dd,
        head_w, m_qkv_w, m_ig_w, m_fg_w);
    k_embed<<<Tt, Dd>>>(x, embed);

    for(int i=0;i<2;i++){
        // ---- sLSTM ----
        k_mgemm<false,true,true,false,8,false><<<dim3(1, Tt/128),256,MG_SMEM>>>(
            h, big, s_bias + i*4*Dd, s_ln1 + i*Dd, W_SGX(i), 4*Dd, Dd);
        k_scan<<<NHs*(Bb/16),256>>>(s_rec + (size_t)i*4*NHs*HDs*HDs, s_gn + i*Dd);

        // ---- FFN 1 ----
        k_mgemm<false,false,true,false,4,false><<<dim3(1, Tt/128),256,MG_SMEM>>>(
            h, ffn, nullptr, s_ln2 + i*Dd, W_SFU(i), 2*FFc, Dd);
        k_mgemm<true,false,false,true,2,false><<<dim3(1, Tt/128),256,MG_SMEM>>>(
            ffn, h, nullptr, nullptr, W_SFD(i), Dd, FFc);

        // ---- mLSTM ----
        k_mgemm<false,false,true,false,8,false><<<dim3(1, Tt/128),256,MG_SMEM>>>(
            h, big, nullptr, m_ln1 + i*Dd, W_MUP(i), 2*INNERc, Dd);
        k_cq<<<Bb*8,256>>>(m_conv_w + (size_t)i*INNERc*Kc, m_conv_b + i*INNERc,
                           m_qkv_w + (size_t)i*3072, gweff + i*4096,
                           m_ig_b + i*NHMc, m_fg_b + i*NHMc);
        k_attn<<<Bb*NHMc,256>>>(m_onorm + i*INNERc, m_skip + i*INNERc);
        k_mgemm<true,false,false,false,2,true><<<dim3(1, Tt/128),256,MG_SMEM>>>(
            qb, h, nullptr, nullptr, W_MDN(i), Dd, INNERc);

        // ---- FFN 2 ----
        k_mgemm<false,false,true,false,4,false><<<dim3(1, Tt/128),256,MG_SMEM>>>(
            h, ffn, nullptr, m_ln2 + i*Dd, W_MFU(i), 2*FFc, Dd);
        k_mgemm<true,false,false,true,2,false><<<dim3(1, Tt/128),256,MG_SMEM>>>(
            ffn, h, nullptr, nullptr, W_MFD(i), Dd, FFc);
    }

    // ---- final LN + head ----
    k_mgemm<false,true,true,false,4,false><<<dim3(1, Tt/128),256,MG_SMEM>>>(
        h, out, head_b, post_ln, W_HEAD, Vv, Dd);
}

// round 16
// speedup vs baseline: 1.1076x; 1.0096x over previous
#include <cuda_runtime.h>
#include <cuda_bf16.h>
#include <math.h>
#include <stdint.h>

#define Bb     512
#define Ss     64
#define Dd     128
#define Vv     256
#define NHs    4
#define HDs    32
#define INNERc 256
#define NHMc   4
#define DHMc   64
#define NBc    64
#define Kc     4
#define FFc    128
#define Tt     (Bb*Ss)   /* 32768 tokens */

// ---------------- workspaces (static device globals; no allocation) ----------
__device__ float g_h[Tt*Dd];            // residual stream
__device__ float g_big[Tt*2*INNERc];    // slstm gx [t][512]  OR  mlstm up out [t][512]
__device__ float g_ffn[Tt*2*FFc];       // ffn up output
__device__ float g_xconv[Tt*INNERc];
__device__ float g_q[Tt*INNERc];        // q, later reused as mlstm combine buffer
__device__ float g_k[Tt*INNERc];
__device__ float g_v[Tt*INNERc];
__device__ float g_ig[Bb*NHMc*Ss];
__device__ float g_fg[Bb*NHMc*Ss];

// all GEMM weights, transposed+split [N][K]
#define W_SGX(i)  ((i)*262144 + 0)
#define W_SFU(i)  ((i)*262144 + 65536)
#define W_SFD(i)  ((i)*262144 + 98304)
#define W_MUP(i)  ((i)*262144 + 114688)
#define W_MDN(i)  ((i)*262144 + 180224)
#define W_MFU(i)  ((i)*262144 + 212992)
#define W_MFD(i)  ((i)*262144 + 245760)
#define W_HEAD    (524288)
#define W_TOTAL   (557056)
__device__ __nv_bfloat16 g_wt_hi[W_TOTAL];
__device__ __nv_bfloat16 g_wt_lo[W_TOTAL];
__device__ float g_gw_eff[2*4096];      // folded gate weights [L][4][256][4]

// ---------------- device math helpers (fast-math intrinsics) -----------------
__device__ __forceinline__ float sigf(float x){
    return __fdividef(1.0f, 1.0f + __expf(-x));
}
__device__ __forceinline__ float logsigf(float x){
    return fminf(x, 0.0f) - __logf(1.0f + __expf(-fabsf(x)));
}
__device__ __forceinline__ float tanhfast(float x){
    float t = __expf(-2.0f*fabsf(x));
    float r = __fdividef(1.0f - t, 1.0f + t);
    return copysignf(r, x);
}
__device__ __forceinline__ float geluf(float x){
    float x3 = x*x*x;
    return 0.5f*x*(1.0f+tanhfast(0.7978845608028654f*(x+0.044715f*x3)));
}
__device__ __forceinline__ uint32_t smem_u32(const void* p){
    uint32_t a;
    asm("{ .reg .u64 t; cvta.to.shared.u64 t, %1; cvt.u32.u64 %0, t; }" : "=r"(a) : "l"(p));
    return a;
}
__device__ __forceinline__ void split2(float a, float b, uint32_t &hi, uint32_t &lo){
    __nv_bfloat162 h = __floats2bfloat162_rn(a, b);
    float ra = a - __bfloat162float(h.x);
    float rb = b - __bfloat162float(h.y);
    __nv_bfloat162 l = __floats2bfloat162_rn(ra, rb);
    hi = *(uint32_t*)&h; lo = *(uint32_t*)&l;
}

#define LDM4(r0,r1,r2,r3,addr) \
    asm volatile("ldmatrix.sync.aligned.m8n8.x4.shared.b16 {%0,%1,%2,%3}, [%4];" \
        : "=r"(r0),"=r"(r1),"=r"(r2),"=r"(r3) : "r"(addr))

#define MMA16816(d,a,b) \
    asm volatile("mma.sync.aligned.m16n8k16.row.col.f32.bf16.bf16.f32 " \
        "{%0,%1,%2,%3}, {%4,%5,%6,%7}, {%8,%9}, {%0,%1,%2,%3};" \
        : "+f"((d)[0]),"+f"((d)[1]),"+f"((d)[2]),"+f"((d)[3]) \
        : "r"((a)[0]),"r"((a)[1]),"r"((a)[2]),"r"((a)[3]), "r"((b)[0]),"r"((b)[1]))

// smem layout: A tiles 128x136 bf16 (hi/lo), B tiles 64x136 bf16 (hi/lo)
#define MG_STRIDE 136
#define MG_AH 0
#define MG_AL (128*MG_STRIDE*2)
#define MG_BH (2*128*MG_STRIDE*2)
#define MG_BL (MG_BH + 64*MG_STRIDE*2)
#define MG_SMEM (MG_BL + 64*MG_STRIDE*2)   /* 104448 B */

// ---------------- tensor-core GEMM: C[M,N] (+)= f(A)[M,K] @ Wt^T (+bias) -----
// NB>1 (MULTIK=false) requires K==128: A staged once; B sub-tiles are
// register-double-buffered (prefetch sub+1 during compute of sub).
// MULTIK=true: K=256, NB=2: persistent acc over k-chunks.
template<bool ADD, bool BIAS, bool LN, bool GLU, int NB, bool MULTIK=false>
__global__ void __launch_bounds__(256,2) k_mgemm(
        const float* __restrict__ A, float* __restrict__ C,
        const float* __restrict__ bias, const float* __restrict__ lnw,
        int woff, int N, int K){
    extern __shared__ char smem[];
    const int tid = threadIdx.x, w = tid>>5, lane = tid&31;
    const int bm = blockIdx.y*128;
    const int wm = w & 3, wn = w >> 2;
    const int gID = lane >> 2, qid = lane & 3;

    const int a_row = lane & 15;
    const int a_koff = (lane >> 4) * 8;
    const int b_noff = (lane & 7) + ((lane >> 4) & 1) * 8;
    const int b_koff = ((lane >> 3) & 1) * 8;

    const uint32_t sb = smem_u32(smem);

    auto stageA = [&](int kc){
        #pragma unroll
        for (int it = 0; it < 8; it++){
            int g4 = tid + it*256;
            int row = g4 >> 4, kg = g4 & 15;
            float4 v0, v1;
            if (GLU){
                const float* ap = A + (size_t)(bm+row)*256 + kg*8;
                float4 gg0 = *(const float4*)ap,      gg1 = *(const float4*)(ap+4);
                float4 uu0 = *(const float4*)(ap+128), uu1 = *(const float4*)(ap+132);
                v0.x = geluf(gg0.x)*uu0.x; v0.y = geluf(gg0.y)*uu0.y;
                v0.z = geluf(gg0.z)*uu0.z; v0.w = geluf(gg0.w)*uu0.w;
                v1.x = geluf(gg1.x)*uu1.x; v1.y = geluf(gg1.y)*uu1.y;
                v1.z = geluf(gg1.z)*uu1.z; v1.w = geluf(gg1.w)*uu1.w;
            } else {
                const float4* ap = (const float4*)(A + (size_t)(bm+row)*K + kc*128 + kg*8);
                v0 = ap[0]; v1 = ap[1];
            }
            if (LN){
                float s  = v0.x+v0.y+v0.z+v0.w + v1.x+v1.y+v1.z+v1.w;
                float ss = v0.x*v0.x+v0.y*v0.y+v0.z*v0.z+v0.w*v0.w
                         + v1.x*v1.x+v1.y*v1.y+v1.z*v1.z+v1.w*v1.w;
                #pragma unroll
                for (int o = 1; o < 16; o <<= 1){
                    s  += __shfl_xor_sync(~0u, s,  o);
                    ss += __shfl_xor_sync(~0u, ss, o);
                }
                float mu  = s*(1.0f/128.0f);
                float var = ss*(1.0f/128.0f) - mu*mu;
                float rr  = rsqrtf(var + 1e-5f);
                float4 w0 = *(const float4*)&lnw[kg*8];
                float4 w1 = *(const float4*)&lnw[kg*8+4];
                v0.x = (v0.x-mu)*rr*w0.x; v0.y = (v0.y-mu)*rr*w0.y;
                v0.z = (v0.z-mu)*rr*w0.z; v0.w = (v0.w-mu)*rr*w0.w;
                v1.x = (v1.x-mu)*rr*w1.x; v1.y = (v1.y-mu)*rr*w1.y;
                v1.z = (v1.z-mu)*rr*w1.z; v1.w = (v1.w-mu)*rr*w1.w;
            }
            uint32_t h0,h1,h2,h3, l0,l1,l2,l3;
            split2(v0.x, v0.y, h0, l0);
            split2(v0.z, v0.w, h1, l1);
            split2(v1.x, v1.y, h2, l2);
            split2(v1.z, v1.w, h3, l3);
            uint32_t off = (uint32_t)(row*(MG_STRIDE*2) + kg*16);
            *(uint4*)(smem + MG_AH + off) = make_uint4(h0,h1,h2,h3);
            *(uint4*)(smem + MG_AL + off) = make_uint4(l0,l1,l2,l3);
        }
    };
    auto loadB = [&](int bn, int kc, uint4 (&rh)[4], uint4 (&rl)[4]){
        #pragma unroll
        for (int it = 0; it < 4; it++){
            int g4 = tid + it*256;
            int n = g4 >> 4, kg = g4 & 15;
            size_t gi = (size_t)woff + (size_t)(bn+n)*K + kc*128 + kg*8;
            rh[it] = *(const uint4*)(g_wt_hi + gi);
            rl[it] = *(const uint4*)(g_wt_lo + gi);
        }
    };
    auto storeB = [&](uint4 (&rh)[4], uint4 (&rl)[4]){
        #pragma unroll
        for (int it = 0; it < 4; it++){
            int g4 = tid + it*256;
            int n = g4 >> 4, kg = g4 & 15;
            uint32_t off = (uint32_t)(n*(MG_STRIDE*2) + kg*16);
            *(uint4*)(smem + MG_BH + off) = rh[it];
            *(uint4*)(smem + MG_BL + off) = rl[it];
        }
    };
    auto compute = [&](float (&acc)[2][4][4]){
        #pragma unroll
        for (int ks = 0; ks < 8; ks++){
            uint32_t ah[2][4], al[2][4];
            #pragma unroll
            for (int mt = 0; mt < 2; mt++){
                uint32_t aoff = (uint32_t)((wm*32 + mt*16 + a_row)*(MG_STRIDE*2)
                                           + (ks*16 + a_koff)*2);
                LDM4(ah[mt][0],ah[mt][1],ah[mt][2],ah[mt][3], sb + MG_AH + aoff);
                LDM4(al[mt][0],al[mt][1],al[mt][2],al[mt][3], sb + MG_AL + aoff);
            }
            uint32_t bh[4][2], bl[4][2];
            #pragma unroll
            for (int ng = 0; ng < 2; ng++){
                uint32_t boff = (uint32_t)((wn*32 + ng*16 + b_noff)*(MG_STRIDE*2)
                                           + (ks*16 + b_koff)*2);
                uint32_t r0,r1,r2,r3;
                LDM4(r0,r1,r2,r3, sb + MG_BH + boff);
                bh[ng*2][0]=r0; bh[ng*2][1]=r1; bh[ng*2+1][0]=r2; bh[ng*2+1][1]=r3;
                LDM4(r0,r1,r2,r3, sb + MG_BL + boff);
                bl[ng*2][0]=r0; bl[ng*2][1]=r1; bl[ng*2+1][0]=r2; bl[ng*2+1][1]=r3;
            }
            #pragma unroll
            for (int mt = 0; mt < 2; mt++)
                #pragma unroll
                for (int nt = 0; nt < 4; nt++){
                    MMA16816(acc[mt][nt], ah[mt], bh[nt]);
                    MMA16816(acc[mt][nt], ah[mt], bl[nt]);
                    MMA16816(acc[mt][nt], al[mt], bh[nt]);
                }
        }
    };
    auto epilogue = [&](float (&acc)[2][4][4], int bn){
        #pragma unroll
        for (int mt = 0; mt < 2; mt++){
            #pragma unroll
            for (int nt = 0; nt < 4; nt++){
                int row0 = bm + wm*32 + mt*16 + gID;
                int col  = bn + wn*32 + nt*8 + qid*2;
                float2 v0 = make_float2(acc[mt][nt][0], acc[mt][nt][1]);
                float2 v1 = make_float2(acc[mt][nt][2], acc[mt][nt][3]);
                if (BIAS){
                    float2 bv = *(const float2*)&bias[col];
                    v0.x += bv.x; v0.y += bv.y;
                    v1.x += bv.x; v1.y += bv.y;
                }
                float* p0 = C + (size_t)row0*N + col;
                float* p1 = C + (size_t)(row0+8)*N + col;
                if (ADD){
                    float2 o0 = *(const float2*)p0, o1 = *(const float2*)p1;
                    v0.x += o0.x; v0.y += o0.y;
                    v1.x += o1.x; v1.y += o1.y;
                }
                *(float2*)p0 = v0;
                *(float2*)p1 = v1;
            }
        }
    };

    if constexpr (MULTIK){
        float acc[2][2][4][4] = {};
        const int bn0 = blockIdx.x*64*NB;
        const int nchunk = K >> 7;
        for (int kc = 0; kc < nchunk; kc++){
            stageA(kc);
            #pragma unroll
            for (int sub = 0; sub < NB; sub++){
                uint4 rh[4], rl[4];
                loadB(bn0 + sub*64, kc, rh, rl);
                storeB(rh, rl);
                __syncthreads();
                compute(acc[sub]);
                __syncthreads();
            }
        }
        #pragma unroll
        for (int sub = 0; sub < NB; sub++)
            epilogue(acc[sub], bn0 + sub*64);
    } else if constexpr (NB == 1){
        const int bn = blockIdx.x*64;
        float acc[2][4][4] = {};
        const int nchunk = K >> 7;
        for (int kc = 0; kc < nchunk; kc++){
            stageA(kc);
            uint4 rh[4], rl[4];
            loadB(bn, kc, rh, rl);
            storeB(rh, rl);
            __syncthreads();
            compute(acc);
            __syncthreads();
        }
        epilogue(acc, bn);
    } else {
        const int bn0 = blockIdx.x*64*NB;
        uint4 rh[4], rl[4];
        loadB(bn0, 0, rh, rl);       // first B load overlaps A staging
        stageA(0);
        #pragma unroll
        for (int sub = 0; sub < NB; sub++){
            storeB(rh, rl);
            __syncthreads();
            if (sub+1 < NB) loadB(bn0 + (sub+1)*64, 0, rh, rl);  // prefetch next B
            float acc[2][4][4] = {};
            compute(acc);
            epilogue(acc, bn0 + sub*64);
            __syncthreads();
        }
    }
}

// ---------------- one-shot weight prep: transposes + densify + gate folding --
__global__ void __launch_bounds__(256) k_prep(
    const float* sgw0, const float* sgw1,
    const float* sfu0, const float* sfd0, const float* mup0, const float* mdn0,
    const float* mfu0, const float* mfd0,
    const float* sfu1, const float* sfd1, const float* mup1, const float* mdn1,
    const float* mfu1, const float* mfd1,
    const float* headw,
    const float* qkvw, const float* igw, const float* fgw){
    int bx = blockIdx.x, tid = threadIdx.x;
    if (bx < 416){
        const int cum[13]  = {32,48,112,144,176,192,224,240,304,336,368,384,416};
        const float* srcs[13] = {sfu0,sfd0,mup0,mdn0,mfu0,mfd0,sfu1,sfd1,mup1,mdn1,mfu1,mfd1,headw};
        const int Ks[13]   = {128,128,128,256,128,128,128,128,128,256,128,128,128};
        const int Ns[13]   = {256,128,512,128,256,128,256,128,512,128,256,128,256};
        const int dsts[13] = {W_SFU(0),W_SFD(0),W_MUP(0),W_MDN(0),W_MFU(0),W_MFD(0),
                              W_SFU(1),W_SFD(1),W_MUP(1),W_MDN(1),W_MFU(1),W_MFD(1),W_HEAD};
        int j = 0;
        while (bx >= cum[j]) j++;
        int tile = bx - (j ? cum[j-1] : 0);
        const float* src = srcs[j];
        int K = Ks[j], N = Ns[j], dst = dsts[j];
        int tilesN = N >> 5;
        int bk = (tile / tilesN)*32, bn = (tile % tilesN)*32;
        __shared__ float t[32][33];
        int tx = tid & 31, ty = tid >> 5;
        #pragma unroll
        for (int r = 0; r < 32; r += 8)
            t[ty+r][tx] = src[(size_t)(bk+ty+r)*N + bn+tx];
        __syncthreads();
        #pragma unroll
        for (int r = 0; r < 32; r += 8){
            float v = t[tx][ty+r];
            __nv_bfloat16 h = __float2bfloat16(v);
            size_t o = (size_t)dst + (size_t)(bn+ty+r)*K + bk+tx;
            g_wt_hi[o] = h;
            g_wt_lo[o] = __float2bfloat16(v - __bfloat162float(h));
        }
    } else if (bx < 544){
        int bx2 = bx - 416;
        int L = bx2 >> 6, blk = bx2 & 63;
        const float* gw = L ? sgw1 : sgw0;
        #pragma unroll
        for (int u = 0; u < 4; u++){
            int idx = blk*1024 + u*256 + tid;     // over 128*512
            int d = idx >> 9;
            int o = idx & 511;
            int g = o >> 7;
            int ne = o & 127;
            int n = ne >> 5, e = ne & 31;
            float wv = 0.0f;
            if ((d >> 5) == n) wv = gw[(((g*NHs + n)*HDs + e)*HDs) + (d & 31)];
            __nv_bfloat16 h = __float2bfloat16(wv);
            size_t oo = (size_t)W_SGX(L) + (size_t)o*Dd + d;
            g_wt_hi[oo] = h;
            g_wt_lo[oo] = __float2bfloat16(wv - __bfloat162float(h));
        }
    } else {
        int L = bx - 544;
        const float* qw  = qkvw + L*3072;
        const float* igp = igw  + L*3072;
        const float* fgp = fgw  + L*3072;
        int c = tid, n = c >> 2, i = c & 3;
        float aig[4]={0,0,0,0}, big_[4]={0,0,0,0}, afg[4]={0,0,0,0}, bfg_[4]={0,0,0,0};
        #pragma unroll
        for (int o = 0; o < 4; o++){
            float w0 = qw[n*16+o*4+i];
            float w1 = qw[1024+n*16+o*4+i];
            float w2 = qw[2048+n*16+o*4+i];
            int j0 = (n*4+o)*4, j1 = (256+n*4+o)*4, j2 = (512+n*4+o)*4;
            #pragma unroll
            for (int hm = 0; hm < 4; hm++){
                aig[hm]  += w0*igp[j0+hm] + w1*igp[j1+hm];
                big_[hm] += w2*igp[j2+hm];
                afg[hm]  += w0*fgp[j0+hm] + w1*fgp[j1+hm];
                bfg_[hm] += w2*fgp[j2+hm];
            }
        }
        #pragma unroll
        for (int hm = 0; hm < 4; hm++){
            g_gw_eff[L*4096 + 0*1024 + c*4 + hm] = aig[hm];
            g_gw_eff[L*4096 + 1*1024 + c*4 + hm] = big_[hm];
            g_gw_eff[L*4096 + 2*1024 + c*4 + hm] = afg[hm];
            g_gw_eff[L*4096 + 3*1024 + c*4 + hm] = bfg_[hm];
        }
    }
}

// ---------------- embedding --------------------------------------------------
__global__ void k_embed(const int* __restrict__ x, const float* __restrict__ emb){
    int t = blockIdx.x;
    g_h[t*Dd + threadIdx.x] = emb[x[t]*Dd + threadIdx.x];
}

// ---------------- sLSTM scan: 8 warps/block, 2 batches/warp ------------------
__global__ void __launch_bounds__(256) k_scan(const float* __restrict__ rec,
                                              const float* __restrict__ gn){
    int n  = blockIdx.x & 3;
    int bg = blockIdx.x >> 2;            // 0..31
    int w  = threadIdx.x >> 5;           // 0..7
    int e  = threadIdx.x & 31;
    int b0 = bg*16 + w*2, b1 = b0 + 1;
    __shared__ float rw[4][HDs][36];
    __shared__ float hs[16][HDs];
    for (int idx = threadIdx.x; idx < 4*HDs*HDs; idx += 256){
        int g = idx >> 10, rem = idx & 1023;
        int e2 = rem >> 5, d = rem & 31;
        rw[g][e2][d] = rec[((size_t)(g*NHs+n)*HDs + e2)*HDs + d];
    }
    hs[w*2][e] = 0.0f;
    hs[w*2+1][e] = 0.0f;
    __syncthreads();
    const int gb = n*HDs + e;
    const float gnw = gn[gb];
    const float* gxA = g_big + (size_t)(b0*Ss)*512 + gb;
    const float* gxB = g_big + (size_t)(b1*Ss)*512 + gb;
    float cA=0.f, nnA=0.f, mA=0.f;
    float cB=0.f, nnB=0.f, mB=0.f;
    float r0a = gxA[0], r1a = gxA[Dd], r2a = gxA[2*Dd], r3a = gxA[3*Dd];
    float r0b = gxB[0], r1b = gxB[Dd], r2b = gxB[2*Dd], r3b = gxB[3*Dd];
    for(int s=0;s<Ss;s++){
        float n0a=0.f,n1a=0.f,n2a=0.f,n3a=0.f, n0b=0.f,n1b=0.f,n2b=0.f,n3b=0.f;
        if (s+1 < Ss){
            const float* npA = gxA + (size_t)(s+1)*512;
            const float* npB = gxB + (size_t)(s+1)*512;
            n0a = npA[0]; n1a = npA[Dd]; n2a = npA[2*Dd]; n3a = npA[3*Dd];
            n0b = npB[0]; n1b = npB[Dd]; n2b = npB[2*Dd]; n3b = npB[3*Dd];
        }
        #pragma unroll
        for(int dq=0; dq<8; dq++){
            float4 w0 = *(const float4*)&rw[0][e][dq*4];
            float4 w1 = *(const float4*)&rw[1][e][dq*4];
            float4 w2 = *(const float4*)&rw[2][e][dq*4];
            float4 w3 = *(const float4*)&rw[3][e][dq*4];
            float4 ha = *(const float4*)&hs[w*2][dq*4];
            float4 hb = *(const float4*)&hs[w*2+1][dq*4];
            r0a += ha.x*w0.x + ha.y*w0.y + ha.z*w0.z + ha.w*w0.w;
            r1a += ha.x*w1.x + ha.y*w1.y + ha.z*w1.z + ha.w*w1.w;
            r2a += ha.x*w2.x + ha.y*w2.y + ha.z*w2.z + ha.w*w2.w;
            r3a += ha.x*w3.x + ha.y*w3.y + ha.z*w3.z + ha.w*w3.w;
            r0b += hb.x*w0.x + hb.y*w0.y + hb.z*w0.z + hb.w*w0.w;
            r1b += hb.x*w1.x + hb.y*w1.y + hb.z*w1.z + hb.w*w1.w;
            r2b += hb.x*w2.x + hb.y*w2.y + hb.z*w2.z + hb.w*w2.w;
            r3b += hb.x*w3.x + hb.y*w3.y + hb.z*w3.z + hb.w*w3.w;
        }
        float lfmA = mA + logsigf(r1a);
        float mnA  = fmaxf(r0a, lfmA);
        float iA   = __expf(r0a-mnA);
        float fA   = __expf(lfmA-mnA);
        cA  = fA*cA + iA*tanhfast(r2a);
        nnA = fA*nnA + iA;
        float hA = sigf(r3a) * __fdividef(cA, nnA);
        mA = mnA;

        float lfmB = mB + logsigf(r1b);
        float mnB  = fmaxf(r0b, lfmB);
        float iB   = __expf(r0b-mnB);
        float fB   = __expf(lfmB-mnB);
        cB  = fB*cB + iB*tanhfast(r2b);
        nnB = fB*nnB + iB;
        float hB = sigf(r3b) * __fdividef(cB, nnB);
        mB = mnB;

        __syncwarp();
        hs[w*2][e]   = hA;
        hs[w*2+1][e] = hB;
        __syncwarp();

        float s1 = hA, s2 = hA*hA, t1 = hB, t2 = hB*hB;
        #pragma unroll
        for(int o=16;o;o>>=1){
            s1 += __shfl_xor_sync(~0u,s1,o); s2 += __shfl_xor_sync(~0u,s2,o);
            t1 += __shfl_xor_sync(~0u,t1,o); t2 += __shfl_xor_sync(~0u,t2,o);
        }
        float muA = s1*(1.0f/HDs), varA = s2*(1.0f/HDs)-muA*muA;
        float muB = t1*(1.0f/HDs), varB = t2*(1.0f/HDs)-muB*muB;
        float rrA = rsqrtf(varA + 1e-5f);
        float rrB = rsqrtf(varB + 1e-5f);
        g_h[((size_t)(b0*Ss+s))*Dd + gb] += (hA-muA)*rrA*gnw;
        g_h[((size_t)(b1*Ss+s))*Dd + gb] += (hB-muB)*rrB*gnw;

        r0a = n0a; r1a = n1a; r2a = n2a; r3a = n3a;
        r0b = n0b; r1b = n1b; r2b = n2b; r3b = n3b;
    }
}

// ---------------- fused conv+silu+qkv+gates: 8 tokens per block --------------
__global__ void __launch_bounds__(256) k_cq(
        const float* __restrict__ cw, const float* __restrict__ cb,
        const float* __restrict__ qkvw, const float* __restrict__ gweff,
        const float* __restrict__ igb, const float* __restrict__ fgb){
    __shared__ float xms[11][256];
    __shared__ float xcv[8][256];
    __shared__ float4 Aig[256], Big[256], Afg[256], Bfg[256];
    int blk = blockIdx.x, b = blk>>3, sg = blk&7;
    int tid = threadIdx.x;
    int t0 = b*Ss + sg*8;

    Aig[tid] = *(const float4*)&gweff[0*1024 + tid*4];
    Big[tid] = *(const float4*)&gweff[1*1024 + tid*4];
    Afg[tid] = *(const float4*)&gweff[2*1024 + tid*4];
    Bfg[tid] = *(const float4*)&gweff[3*1024 + tid*4];

    for (int idx = tid; idx < 11*256; idx += 256){
        int r = idx >> 8, c = idx & 255;
        int s = sg*8 + r - 3;
        xms[r][c] = (s >= 0) ? g_big[(size_t)(b*Ss+s)*512 + c] : 0.0f;
    }
    int c = tid, n = c>>2, o = c&3;
    float cwv0=cw[c*4], cwv1=cw[c*4+1], cwv2=cw[c*4+2], cwv3=cw[c*4+3], cbv=cb[c];
    float wq[4], wk[4], wv[4];
    #pragma unroll
    for (int i2 = 0; i2 < 4; i2++){
        wq[i2] = qkvw[       n*16 + o*4 + i2];
        wk[i2] = qkvw[1024 + n*16 + o*4 + i2];
        wv[i2] = qkvw[2048 + n*16 + o*4 + i2];
    }
    __syncthreads();
    #pragma unroll
    for (int s = 0; s < 8; s++){
        float acc = cbv + xms[s][c]*cwv0 + xms[s+1][c]*cwv1 + xms[s+2][c]*cwv2 + xms[s+3][c]*cwv3;
        float xc = acc*sigf(acc);
        xcv[s][c] = xc;
        g_xconv[(size_t)(t0+s)*256 + c] = xc;
    }
    __syncthreads();
    #pragma unroll
    for (int s = 0; s < 8; s++){
        float q=0, k=0, v=0;
        #pragma unroll
        for (int i2 = 0; i2 < 4; i2++){
            float xc = xcv[s][n*4+i2];
            float xm = xms[s+3][n*4+i2];
            q += xc*wq[i2]; k += xc*wk[i2]; v += xm*wv[i2];
        }
        g_q[(size_t)(t0+s)*256 + c] = q;
        g_k[(size_t)(t0+s)*256 + c] = k;
        g_v[(size_t)(t0+s)*256 + c] = v;
    }
    int w = tid >> 5, lane = tid & 31;
    float4 ia = make_float4(0,0,0,0), fa = make_float4(0,0,0,0);
    for (int j = lane; j < 256; j += 32){
        float xc = xcv[w][j], xm = xms[w+3][j];
        float4 A = Aig[j], B = Big[j], A2 = Afg[j], B2 = Bfg[j];
        ia.x += xc*A.x + xm*B.x;  ia.y += xc*A.y + xm*B.y;
        ia.z += xc*A.z + xm*B.z;  ia.w += xc*A.w + xm*B.w;
        fa.x += xc*A2.x + xm*B2.x; fa.y += xc*A2.y + xm*B2.y;
        fa.z += xc*A2.z + xm*B2.z; fa.w += xc*A2.w + xm*B2.w;
    }
    #pragma unroll
    for (int o2=16;o2;o2>>=1){
        ia.x += __shfl_xor_sync(~0u,ia.x,o2); ia.y += __shfl_xor_sync(~0u,ia.y,o2);
        ia.z += __shfl_xor_sync(~0u,ia.z,o2); ia.w += __shfl_xor_sync(~0u,ia.w,o2);
        fa.x += __shfl_xor_sync(~0u,fa.x,o2); fa.y += __shfl_xor_sync(~0u,fa.y,o2);
        fa.z += __shfl_xor_sync(~0u,fa.z,o2); fa.w += __shfl_xor_sync(~0u,fa.w,o2);
    }
    if (lane == 0){
        int s_ = sg*8 + w;
        g_ig[(size_t)(b*NHMc+0)*Ss + s_] = ia.x + igb[0];
        g_ig[(size_t)(b*NHMc+1)*Ss + s_] = ia.y + igb[1];
        g_ig[(size_t)(b*NHMc+2)*Ss + s_] = ia.z + igb[2];
        g_ig[(size_t)(b*NHMc+3)*Ss + s_] = ia.w + igb[3];
        g_fg[(size_t)(b*NHMc+0)*Ss + s_] = fa.x + fgb[0];
        g_fg[(size_t)(b*NHMc+1)*Ss + s_] = fa.y + fgb[1];
        g_fg[(size_t)(b*NHMc+2)*Ss + s_] = fa.z + fgb[2];
        g_fg[(size_t)(b*NHMc+3)*Ss + s_] = fa.w + fgb[3];
    }
}

// ---------------- mLSTM attention + fused groupnorm/skip/silu combine --------
// q/k rows padded to 68 floats (float4 LDS); V stored TRANSPOSED vt[d][j] so
// the AV loop is float4 over contiguous j (cn is zero-padded past row i).
#define APAD 68
__global__ void __launch_bounds__(256) k_attn(const float* __restrict__ onw,
                                              const float* __restrict__ skip){
    int blk = blockIdx.x; int b = blk >> 2, hm = blk & 3;
    __shared__ __align__(16) float qs[Ss][APAD], ks[Ss][APAD];
    __shared__ __align__(16) float vt[DHMc][APAD];
    __shared__ __align__(16) float cn[8][Ss];
    __shared__ float cldf[Ss+1], igs[Ss];
    int tid = threadIdx.x;
    for (int l = tid; l < Ss*16; l += 256){
        int j = l >> 4, d4 = l & 15;
        size_t base = ((size_t)(b*Ss+j))*INNERc + hm*DHMc + d4*4;
        *(float4*)&qs[j][d4*4] = *(const float4*)&g_q[base];
        *(float4*)&ks[j][d4*4] = *(const float4*)&g_k[base];
        float4 vv = *(const float4*)&g_v[base];
        vt[d4*4+0][j] = vv.x;
        vt[d4*4+1][j] = vv.y;
        vt[d4*4+2][j] = vv.z;
        vt[d4*4+3][j] = vv.w;
    }
    if (tid < Ss){
        igs[tid] = g_ig[(size_t)(b*NHMc+hm)*Ss + tid];
        cldf[tid+1] = logsigf(g_fg[(size_t)(b*NHMc+hm)*Ss + tid]);
    }
    if (tid == 0) cldf[0] = 0.0f;
    __syncthreads();
    for (int off = 1; off < Ss; off <<= 1){
        float add = 0.0f;
        if (tid < Ss && tid >= off) add = cldf[tid+1-off];
        __syncthreads();
        if (tid < Ss && tid >= off) cldf[tid+1] += add;
        __syncthreads();
    }
    int w = tid >> 5, lane = tid & 31;
    int cg0 = hm*DHMc + lane, cg1 = cg0 + 32;
    float onw0 = onw[cg0], onw1 = onw[cg1];
    float sk0 = skip[cg0], sk1 = skip[cg1];
    for(int r=0;r<8;r++){
        int i = r*8 + w;
        int j1 = lane + 32;
        float dot0=0, dot1=0, ld0=-1e30f, ld1=-1e30f;
        if (lane <= i){
            #pragma unroll
            for(int dq=0; dq<16; dq++){
                float4 qv = *(const float4*)&qs[i][dq*4];
                float4 kv = *(const float4*)&ks[lane][dq*4];
                dot0 += qv.x*kv.x + qv.y*kv.y + qv.z*kv.z + qv.w*kv.w;
            }
            ld0 = cldf[i+1]-cldf[lane+1] + igs[lane];
        }
        if (j1 <= i){
            #pragma unroll
            for(int dq=0; dq<16; dq++){
                float4 qv = *(const float4*)&qs[i][dq*4];
                float4 kv = *(const float4*)&ks[j1][dq*4];
                dot1 += qv.x*kv.x + qv.y*kv.y + qv.z*kv.z + qv.w*kv.w;
            }
            ld1 = cldf[i+1]-cldf[j1+1] + igs[j1];
        }
        float mx = fmaxf(ld0, ld1);
        #pragma unroll
        for(int o=16;o;o>>=1) mx = fmaxf(mx, __shfl_xor_sync(~0u,mx,o));
        float cm0 = (lane <= i) ? dot0*0.125f*__expf(ld0-mx) : 0.0f;
        float cm1 = (j1   <= i) ? dot1*0.125f*__expf(ld1-mx) : 0.0f;
        float sm = cm0 + cm1;
        #pragma unroll
        for(int o=16;o;o>>=1) sm += __shfl_xor_sync(~0u,sm,o);
        float norm = fmaxf(fabsf(sm), __expf(-mx)) + 1e-6f;
        float rnorm = __fdividef(1.0f, norm);
        cn[w][lane] = cm0*rnorm;
        cn[w][j1]   = cm1*rnorm;
        __syncwarp();
        float a0=0, a1=0;
        int jend = (i & ~3) + 4;          // cn[j>i] == 0, tail is safe
        for(int j4=0; j4<jend; j4+=4){
            float4 cc = *(const float4*)&cn[w][j4];
            float4 va = *(const float4*)&vt[lane][j4];
            float4 vb = *(const float4*)&vt[lane+32][j4];
            a0 += cc.x*va.x + cc.y*va.y + cc.z*va.z + cc.w*va.w;
            a1 += cc.x*vb.x + cc.y*vb.y + cc.z*vb.z + cc.w*vb.w;
        }
        float s1 = a0+a1, s2 = a0*a0+a1*a1;
        #pragma unroll
        for(int o=16;o;o>>=1){ s1 += __shfl_xor_sync(~0u,s1,o); s2 += __shfl_xor_sync(~0u,s2,o); }
        float mu = s1*(1.0f/DHMc), var = s2*(1.0f/DHMc)-mu*mu;
        float rr = rsqrtf(var + 1e-5f);
        size_t t = (size_t)(b*Ss+i);
        float z0 = g_big[t*512 + 256 + cg0], z1 = g_big[t*512 + 256 + cg1];
        float x0 = g_xconv[t*256 + cg0],     x1 = g_xconv[t*256 + cg1];
        g_q[t*256 + cg0] = ((a0-mu)*rr*onw0 + sk0*x0) * z0*sigf(z0);
        g_q[t*256 + cg1] = ((a1-mu)*rr*onw1 + sk1*x1) * z1*sigf(z1);
        __syncwarp();
    }
}

// ---------------- host-side --------------------------------------------------
static float* symf(const void* s){ void* p=nullptr; cudaGetSymbolAddress(&p, s); return (float*)p; }

extern "C" void kernel_launch(void* const* d_in, const int* in_sizes, int n_in,
                              void* d_out, int out_size){
    const int*   x         = (const int*)  d_in[0];
    const float* embed     = (const float*)d_in[1];
    const float* s_ln1     = (const float*)d_in[2];
    const float* s_gates_w = (const float*)d_in[3];
    const float* s_rec     = (const float*)d_in[4];
    const float* s_bias    = (const float*)d_in[5];
    const float* s_gn      = (const float*)d_in[6];
    const float* s_ln2     = (const float*)d_in[7];
    const float* s_ff_up   = (const float*)d_in[8];
    const float* s_ff_down = (const float*)d_in[9];
    const float* m_ln1     = (const float*)d_in[10];
    const float* m_up      = (const float*)d_in[11];
    const float* m_conv_w  = (const float*)d_in[12];
    const float* m_conv_b  = (const float*)d_in[13];
    const float* m_qkv_w   = (const float*)d_in[14];
    const float* m_ig_w    = (const float*)d_in[15];
    const float* m_ig_b    = (const float*)d_in[16];
    const float* m_fg_w    = (const float*)d_in[17];
    const float* m_fg_b    = (const float*)d_in[18];
    const float* m_skip    = (const float*)d_in[19];
    const float* m_onorm   = (const float*)d_in[20];
    const float* m_down    = (const float*)d_in[21];
    const float* m_ln2     = (const float*)d_in[22];
    const float* m_ff_up   = (const float*)d_in[23];
    const float* m_ff_down = (const float*)d_in[24];
    const float* post_ln   = (const float*)d_in[25];
    const float* head_w    = (const float*)d_in[26];
    const float* head_b    = (const float*)d_in[27];

    float* h    = symf(g_h);
    float* big  = symf(g_big);
    float* ffn  = symf(g_ffn);
    float* qb   = symf(g_q);
    float* gweff= symf(g_gw_eff);

    float* out = (float*)d_out;

    cudaFuncSetAttribute(k_mgemm<false,true ,true ,false,8,false>, cudaFuncAttributeMaxDynamicSharedMemorySize, MG_SMEM);
    cudaFuncSetAttribute(k_mgemm<false,false,true ,false,8,false>, cudaFuncAttributeMaxDynamicSharedMemorySize, MG_SMEM);
    cudaFuncSetAttribute(k_mgemm<false,false,true ,false,4,false>, cudaFuncAttributeMaxDynamicSharedMemorySize, MG_SMEM);
    cudaFuncSetAttribute(k_mgemm<true ,false,false,true ,2,false>, cudaFuncAttributeMaxDynamicSharedMemorySize, MG_SMEM);
    cudaFuncSetAttribute(k_mgemm<true ,false,false,false,2,true >, cudaFuncAttributeMaxDynamicSharedMemorySize, MG_SMEM);
    cudaFuncSetAttribute(k_mgemm<false,true ,true ,false,4,false>, cudaFuncAttributeMaxDynamicSharedMemorySize, MG_SMEM);

    k_prep<<<546,256>>>(
        s_gates_w, s_gates_w + (size_t)4*NHs*HDs*HDs,
        s_ff_up, s_ff_down, m_up, m_down, m_ff_up, m_ff_down,
        s_ff_up + (size_t)Dd*2*FFc, s_ff_down + (size_t)FFc*Dd,
        m_up + (size_t)Dd*2*INNERc, m_down + (size_t)INNERc*Dd,
        m_ff_up + (size_t)Dd*2*FFc, m_ff_down + (size_t)FFc*Dd,
        head_w, m_qkv_w, m_ig_w, m_fg_w);
    k_embed<<<Tt, Dd>>>(x, embed);

    for(int i=0;i<2;i++){
        // ---- sLSTM ----
        k_mgemm<false,true,true,false,8,false><<<dim3(1, Tt/128),256,MG_SMEM>>>(
            h, big, s_bias + i*4*Dd, s_ln1 + i*Dd, W_SGX(i), 4*Dd, Dd);
        k_scan<<<NHs*(Bb/16),256>>>(s_rec + (size_t)i*4*NHs*HDs*HDs, s_gn + i*Dd);

        // ---- FFN 1 ----
        k_mgemm<false,false,true,false,4,false><<<dim3(1, Tt/128),256,MG_SMEM>>>(
            h, ffn, nullptr, s_ln2 + i*Dd, W_SFU(i), 2*FFc, Dd);
        k_mgemm<true,false,false,true,2,false><<<dim3(1, Tt/128),256,MG_SMEM>>>(
            ffn, h, nullptr, nullptr, W_SFD(i), Dd, FFc);

        // ---- mLSTM ----
        k_mgemm<false,false,true,false,8,false><<<dim3(1, Tt/128),256,MG_SMEM>>>(
            h, big, nullptr, m_ln1 + i*Dd, W_MUP(i), 2*INNERc, Dd);
        k_cq<<<Bb*8,256>>>(m_conv_w + (size_t)i*INNERc*Kc, m_conv_b + i*INNERc,
                           m_qkv_w + (size_t)i*3072, gweff + i*4096,
                           m_ig_b + i*NHMc, m_fg_b + i*NHMc);
        k_attn<<<Bb*NHMc,256>>>(m_onorm + i*INNERc, m_skip + i*INNERc);
        k_mgemm<true,false,false,false,2,true><<<dim3(1, Tt/128),256,MG_SMEM>>>(
            qb, h, nullptr, nullptr, W_MDN(i), Dd, INNERc);

        // ---- FFN 2 ----
        k_mgemm<false,false,true,false,4,false><<<dim3(1, Tt/128),256,MG_SMEM>>>(
            h, ffn, nullptr, m_ln2 + i*Dd, W_MFU(i), 2*FFc, Dd);
        k_mgemm<true,false,false,true,2,false><<<dim3(1, Tt/128),256,MG_SMEM>>>(
            ffn, h, nullptr, nullptr, W_MFD(i), Dd, FFc);
    }

    // ---- final LN + head ----
    k_mgemm<false,true,true,false,4,false><<<dim3(1, Tt/128),256,MG_SMEM>>>(
        h, out, head_b, post_ln, W_HEAD, Vv, Dd);
}

// round 17
// speedup vs baseline: 1.1628x; 1.0498x over previous
#include <cuda_runtime.h>
#include <cuda_bf16.h>
#include <math.h>
#include <stdint.h>

#define Bb     512
#define Ss     64
#define Dd     128
#define Vv     256
#define NHs    4
#define HDs    32
#define INNERc 256
#define NHMc   4
#define DHMc   64
#define NBc    64
#define Kc     4
#define FFc    128
#define Tt     (Bb*Ss)   /* 32768 tokens */

// ---------------- workspaces (static device globals; no allocation) ----------
__device__ float g_h[Tt*Dd];            // residual stream
__device__ float g_big[Tt*2*INNERc];    // slstm gx [t][512]  OR  mlstm up out [t][512]
__device__ float g_ffn[Tt*2*FFc];       // ffn up output
__device__ float g_xconv[Tt*INNERc];
__device__ float g_q[Tt*INNERc];        // q, later reused as mlstm combine buffer
__device__ float g_k[Tt*INNERc];
__device__ float g_v[Tt*INNERc];
__device__ float g_ig[Bb*NHMc*Ss];
__device__ float g_fg[Bb*NHMc*Ss];

// all GEMM weights, transposed+split [N][K]
#define W_SGX(i)  ((i)*262144 + 0)
#define W_SFU(i)  ((i)*262144 + 65536)
#define W_SFD(i)  ((i)*262144 + 98304)
#define W_MUP(i)  ((i)*262144 + 114688)
#define W_MDN(i)  ((i)*262144 + 180224)
#define W_MFU(i)  ((i)*262144 + 212992)
#define W_MFD(i)  ((i)*262144 + 245760)
#define W_HEAD    (524288)
#define W_TOTAL   (557056)
__device__ __nv_bfloat16 g_wt_hi[W_TOTAL];
__device__ __nv_bfloat16 g_wt_lo[W_TOTAL];
__device__ float g_gw_eff[2*4096];      // folded gate weights [L][4][256][4]

// ---------------- device math helpers (fast-math intrinsics) -----------------
__device__ __forceinline__ float sigf(float x){
    return __fdividef(1.0f, 1.0f + __expf(-x));
}
__device__ __forceinline__ float logsigf(float x){
    return fminf(x, 0.0f) - __logf(1.0f + __expf(-fabsf(x)));
}
__device__ __forceinline__ float tanhfast(float x){
    float t = __expf(-2.0f*fabsf(x));
    float r = __fdividef(1.0f - t, 1.0f + t);
    return copysignf(r, x);
}
__device__ __forceinline__ float geluf(float x){
    float x3 = x*x*x;
    return 0.5f*x*(1.0f+tanhfast(0.7978845608028654f*(x+0.044715f*x3)));
}
__device__ __forceinline__ uint32_t smem_u32(const void* p){
    uint32_t a;
    asm("{ .reg .u64 t; cvta.to.shared.u64 t, %1; cvt.u32.u64 %0, t; }" : "=r"(a) : "l"(p));
    return a;
}
__device__ __forceinline__ void split2(float a, float b, uint32_t &hi, uint32_t &lo){
    __nv_bfloat162 h = __floats2bfloat162_rn(a, b);
    float ra = a - __bfloat162float(h.x);
    float rb = b - __bfloat162float(h.y);
    __nv_bfloat162 l = __floats2bfloat162_rn(ra, rb);
    hi = *(uint32_t*)&h; lo = *(uint32_t*)&l;
}

#define LDM4(r0,r1,r2,r3,addr) \
    asm volatile("ldmatrix.sync.aligned.m8n8.x4.shared.b16 {%0,%1,%2,%3}, [%4];" \
        : "=r"(r0),"=r"(r1),"=r"(r2),"=r"(r3) : "r"(addr))

#define MMA16816(d,a,b) \
    asm volatile("mma.sync.aligned.m16n8k16.row.col.f32.bf16.bf16.f32 " \
        "{%0,%1,%2,%3}, {%4,%5,%6,%7}, {%8,%9}, {%0,%1,%2,%3};" \
        : "+f"((d)[0]),"+f"((d)[1]),"+f"((d)[2]),"+f"((d)[3]) \
        : "r"((a)[0]),"r"((a)[1]),"r"((a)[2]),"r"((a)[3]), "r"((b)[0]),"r"((b)[1]))

// smem layout: A tiles 128x136 bf16 (hi/lo), B tiles 64x136 bf16 (hi/lo)
#define MG_STRIDE 136
#define MG_AH 0
#define MG_AL (128*MG_STRIDE*2)
#define MG_BH (2*128*MG_STRIDE*2)
#define MG_BL (MG_BH + 64*MG_STRIDE*2)
#define MG_SMEM (MG_BL + 64*MG_STRIDE*2)   /* 104448 B */

// ---------------- tensor-core GEMM: C[M,N] (+)= f(A)[M,K] @ Wt^T (+bias) -----
template<bool ADD, bool BIAS, bool LN, bool GLU, int NB, bool MULTIK=false>
__global__ void __launch_bounds__(256,2) k_mgemm(
        const float* __restrict__ A, float* __restrict__ C,
        const float* __restrict__ bias, const float* __restrict__ lnw,
        int woff, int N, int K){
    extern __shared__ char smem[];
    const int tid = threadIdx.x, w = tid>>5, lane = tid&31;
    const int bm = blockIdx.y*128;
    const int wm = w & 3, wn = w >> 2;
    const int gID = lane >> 2, qid = lane & 3;

    const int a_row = lane & 15;
    const int a_koff = (lane >> 4) * 8;
    const int b_noff = (lane & 7) + ((lane >> 4) & 1) * 8;
    const int b_koff = ((lane >> 3) & 1) * 8;

    const uint32_t sb = smem_u32(smem);

    auto stageA = [&](int kc){
        #pragma unroll
        for (int it = 0; it < 8; it++){
            int g4 = tid + it*256;
            int row = g4 >> 4, kg = g4 & 15;
            float4 v0, v1;
            if (GLU){
                const float* ap = A + (size_t)(bm+row)*256 + kg*8;
                float4 gg0 = *(const float4*)ap,      gg1 = *(const float4*)(ap+4);
                float4 uu0 = *(const float4*)(ap+128), uu1 = *(const float4*)(ap+132);
                v0.x = geluf(gg0.x)*uu0.x; v0.y = geluf(gg0.y)*uu0.y;
                v0.z = geluf(gg0.z)*uu0.z; v0.w = geluf(gg0.w)*uu0.w;
                v1.x = geluf(gg1.x)*uu1.x; v1.y = geluf(gg1.y)*uu1.y;
                v1.z = geluf(gg1.z)*uu1.z; v1.w = geluf(gg1.w)*uu1.w;
            } else {
                const float4* ap = (const float4*)(A + (size_t)(bm+row)*K + kc*128 + kg*8);
                v0 = ap[0]; v1 = ap[1];
            }
            if (LN){
                float s  = v0.x+v0.y+v0.z+v0.w + v1.x+v1.y+v1.z+v1.w;
                float ss = v0.x*v0.x+v0.y*v0.y+v0.z*v0.z+v0.w*v0.w
                         + v1.x*v1.x+v1.y*v1.y+v1.z*v1.z+v1.w*v1.w;
                #pragma unroll
                for (int o = 1; o < 16; o <<= 1){
                    s  += __shfl_xor_sync(~0u, s,  o);
                    ss += __shfl_xor_sync(~0u, ss, o);
                }
                float mu  = s*(1.0f/128.0f);
                float var = ss*(1.0f/128.0f) - mu*mu;
                float rr  = rsqrtf(var + 1e-5f);
                float4 w0 = *(const float4*)&lnw[kg*8];
                float4 w1 = *(const float4*)&lnw[kg*8+4];
                v0.x = (v0.x-mu)*rr*w0.x; v0.y = (v0.y-mu)*rr*w0.y;
                v0.z = (v0.z-mu)*rr*w0.z; v0.w = (v0.w-mu)*rr*w0.w;
                v1.x = (v1.x-mu)*rr*w1.x; v1.y = (v1.y-mu)*rr*w1.y;
                v1.z = (v1.z-mu)*rr*w1.z; v1.w = (v1.w-mu)*rr*w1.w;
            }
            uint32_t h0,h1,h2,h3, l0,l1,l2,l3;
            split2(v0.x, v0.y, h0, l0);
            split2(v0.z, v0.w, h1, l1);
            split2(v1.x, v1.y, h2, l2);
            split2(v1.z, v1.w, h3, l3);
            uint32_t off = (uint32_t)(row*(MG_STRIDE*2) + kg*16);
            *(uint4*)(smem + MG_AH + off) = make_uint4(h0,h1,h2,h3);
            *(uint4*)(smem + MG_AL + off) = make_uint4(l0,l1,l2,l3);
        }
    };
    auto loadB = [&](int bn, int kc, uint4 (&rh)[4], uint4 (&rl)[4]){
        #pragma unroll
        for (int it = 0; it < 4; it++){
            int g4 = tid + it*256;
            int n = g4 >> 4, kg = g4 & 15;
            size_t gi = (size_t)woff + (size_t)(bn+n)*K + kc*128 + kg*8;
            rh[it] = *(const uint4*)(g_wt_hi + gi);
            rl[it] = *(const uint4*)(g_wt_lo + gi);
        }
    };
    auto storeB = [&](uint4 (&rh)[4], uint4 (&rl)[4]){
        #pragma unroll
        for (int it = 0; it < 4; it++){
            int g4 = tid + it*256;
            int n = g4 >> 4, kg = g4 & 15;
            uint32_t off = (uint32_t)(n*(MG_STRIDE*2) + kg*16);
            *(uint4*)(smem + MG_BH + off) = rh[it];
            *(uint4*)(smem + MG_BL + off) = rl[it];
        }
    };
    auto compute = [&](float (&acc)[2][4][4]){
        #pragma unroll
        for (int ks = 0; ks < 8; ks++){
            uint32_t ah[2][4], al[2][4];
            #pragma unroll
            for (int mt = 0; mt < 2; mt++){
                uint32_t aoff = (uint32_t)((wm*32 + mt*16 + a_row)*(MG_STRIDE*2)
                                           + (ks*16 + a_koff)*2);
                LDM4(ah[mt][0],ah[mt][1],ah[mt][2],ah[mt][3], sb + MG_AH + aoff);
                LDM4(al[mt][0],al[mt][1],al[mt][2],al[mt][3], sb + MG_AL + aoff);
            }
            uint32_t bh[4][2], bl[4][2];
            #pragma unroll
            for (int ng = 0; ng < 2; ng++){
                uint32_t boff = (uint32_t)((wn*32 + ng*16 + b_noff)*(MG_STRIDE*2)
                                           + (ks*16 + b_koff)*2);
                uint32_t r0,r1,r2,r3;
                LDM4(r0,r1,r2,r3, sb + MG_BH + boff);
                bh[ng*2][0]=r0; bh[ng*2][1]=r1; bh[ng*2+1][0]=r2; bh[ng*2+1][1]=r3;
                LDM4(r0,r1,r2,r3, sb + MG_BL + boff);
                bl[ng*2][0]=r0; bl[ng*2][1]=r1; bl[ng*2+1][0]=r2; bl[ng*2+1][1]=r3;
            }
            #pragma unroll
            for (int mt = 0; mt < 2; mt++)
                #pragma unroll
                for (int nt = 0; nt < 4; nt++){
                    MMA16816(acc[mt][nt], ah[mt], bh[nt]);
                    MMA16816(acc[mt][nt], ah[mt], bl[nt]);
                    MMA16816(acc[mt][nt], al[mt], bh[nt]);
                }
        }
    };
    auto epilogue = [&](float (&acc)[2][4][4], int bn){
        #pragma unroll
        for (int mt = 0; mt < 2; mt++){
            #pragma unroll
            for (int nt = 0; nt < 4; nt++){
                int row0 = bm + wm*32 + mt*16 + gID;
                int col  = bn + wn*32 + nt*8 + qid*2;
                float2 v0 = make_float2(acc[mt][nt][0], acc[mt][nt][1]);
                float2 v1 = make_float2(acc[mt][nt][2], acc[mt][nt][3]);
                if (BIAS){
                    float2 bv = *(const float2*)&bias[col];
                    v0.x += bv.x; v0.y += bv.y;
                    v1.x += bv.x; v1.y += bv.y;
                }
                float* p0 = C + (size_t)row0*N + col;
                float* p1 = C + (size_t)(row0+8)*N + col;
                if (ADD){
                    float2 o0 = *(const float2*)p0, o1 = *(const float2*)p1;
                    v0.x += o0.x; v0.y += o0.y;
                    v1.x += o1.x; v1.y += o1.y;
                }
                *(float2*)p0 = v0;
                *(float2*)p1 = v1;
            }
        }
    };

    if constexpr (MULTIK){
        float acc[2][2][4][4] = {};
        const int bn0 = blockIdx.x*64*NB;
        const int nchunk = K >> 7;
        for (int kc = 0; kc < nchunk; kc++){
            stageA(kc);
            #pragma unroll
            for (int sub = 0; sub < NB; sub++){
                uint4 rh[4], rl[4];
                loadB(bn0 + sub*64, kc, rh, rl);
                storeB(rh, rl);
                __syncthreads();
                compute(acc[sub]);
                __syncthreads();
            }
        }
        #pragma unroll
        for (int sub = 0; sub < NB; sub++)
            epilogue(acc[sub], bn0 + sub*64);
    } else if constexpr (NB == 1){
        const int bn = blockIdx.x*64;
        float acc[2][4][4] = {};
        const int nchunk = K >> 7;
        for (int kc = 0; kc < nchunk; kc++){
            stageA(kc);
            uint4 rh[4], rl[4];
            loadB(bn, kc, rh, rl);
            storeB(rh, rl);
            __syncthreads();
            compute(acc);
            __syncthreads();
        }
        epilogue(acc, bn);
    } else {
        const int bn0 = blockIdx.x*64*NB;
        uint4 rh[4], rl[4];
        loadB(bn0, 0, rh, rl);
        stageA(0);
        #pragma unroll
        for (int sub = 0; sub < NB; sub++){
            storeB(rh, rl);
            __syncthreads();
            if (sub+1 < NB) loadB(bn0 + (sub+1)*64, 0, rh, rl);
            float acc[2][4][4] = {};
            compute(acc);
            epilogue(acc, bn0 + sub*64);
            __syncthreads();
        }
    }
}

// ---------------- one-shot weight prep: transposes + densify + gate folding --
__global__ void __launch_bounds__(256) k_prep(
    const float* sgw0, const float* sgw1,
    const float* sfu0, const float* sfd0, const float* mup0, const float* mdn0,
    const float* mfu0, const float* mfd0,
    const float* sfu1, const float* sfd1, const float* mup1, const float* mdn1,
    const float* mfu1, const float* mfd1,
    const float* headw,
    const float* qkvw, const float* igw, const float* fgw){
    int bx = blockIdx.x, tid = threadIdx.x;
    if (bx < 416){
        const int cum[13]  = {32,48,112,144,176,192,224,240,304,336,368,384,416};
        const float* srcs[13] = {sfu0,sfd0,mup0,mdn0,mfu0,mfd0,sfu1,sfd1,mup1,mdn1,mfu1,mfd1,headw};
        const int Ks[13]   = {128,128,128,256,128,128,128,128,128,256,128,128,128};
        const int Ns[13]   = {256,128,512,128,256,128,256,128,512,128,256,128,256};
        const int dsts[13] = {W_SFU(0),W_SFD(0),W_MUP(0),W_MDN(0),W_MFU(0),W_MFD(0),
                              W_SFU(1),W_SFD(1),W_MUP(1),W_MDN(1),W_MFU(1),W_MFD(1),W_HEAD};
        int j = 0;
        while (bx >= cum[j]) j++;
        int tile = bx - (j ? cum[j-1] : 0);
        const float* src = srcs[j];
        int K = Ks[j], N = Ns[j], dst = dsts[j];
        int tilesN = N >> 5;
        int bk = (tile / tilesN)*32, bn = (tile % tilesN)*32;
        __shared__ float t[32][33];
        int tx = tid & 31, ty = tid >> 5;
        #pragma unroll
        for (int r = 0; r < 32; r += 8)
            t[ty+r][tx] = src[(size_t)(bk+ty+r)*N + bn+tx];
        __syncthreads();
        #pragma unroll
        for (int r = 0; r < 32; r += 8){
            float v = t[tx][ty+r];
            __nv_bfloat16 h = __float2bfloat16(v);
            size_t o = (size_t)dst + (size_t)(bn+ty+r)*K + bk+tx;
            g_wt_hi[o] = h;
            g_wt_lo[o] = __float2bfloat16(v - __bfloat162float(h));
        }
    } else if (bx < 544){
        int bx2 = bx - 416;
        int L = bx2 >> 6, blk = bx2 & 63;
        const float* gw = L ? sgw1 : sgw0;
        #pragma unroll
        for (int u = 0; u < 4; u++){
            int idx = blk*1024 + u*256 + tid;     // over 128*512
            int d = idx >> 9;
            int o = idx & 511;
            int g = o >> 7;
            int ne = o & 127;
            int n = ne >> 5, e = ne & 31;
            float wv = 0.0f;
            if ((d >> 5) == n) wv = gw[(((g*NHs + n)*HDs + e)*HDs) + (d & 31)];
            __nv_bfloat16 h = __float2bfloat16(wv);
            size_t oo = (size_t)W_SGX(L) + (size_t)o*Dd + d;
            g_wt_hi[oo] = h;
            g_wt_lo[oo] = __float2bfloat16(wv - __bfloat162float(h));
        }
    } else {
        int L = bx - 544;
        const float* qw  = qkvw + L*3072;
        const float* igp = igw  + L*3072;
        const float* fgp = fgw  + L*3072;
        int c = tid, n = c >> 2, i = c & 3;
        float aig[4]={0,0,0,0}, big_[4]={0,0,0,0}, afg[4]={0,0,0,0}, bfg_[4]={0,0,0,0};
        #pragma unroll
        for (int o = 0; o < 4; o++){
            float w0 = qw[n*16+o*4+i];
            float w1 = qw[1024+n*16+o*4+i];
            float w2 = qw[2048+n*16+o*4+i];
            int j0 = (n*4+o)*4, j1 = (256+n*4+o)*4, j2 = (512+n*4+o)*4;
            #pragma unroll
            for (int hm = 0; hm < 4; hm++){
                aig[hm]  += w0*igp[j0+hm] + w1*igp[j1+hm];
                big_[hm] += w2*igp[j2+hm];
                afg[hm]  += w0*fgp[j0+hm] + w1*fgp[j1+hm];
                bfg_[hm] += w2*fgp[j2+hm];
            }
        }
        #pragma unroll
        for (int hm = 0; hm < 4; hm++){
            g_gw_eff[L*4096 + 0*1024 + c*4 + hm] = aig[hm];
            g_gw_eff[L*4096 + 1*1024 + c*4 + hm] = big_[hm];
            g_gw_eff[L*4096 + 2*1024 + c*4 + hm] = afg[hm];
            g_gw_eff[L*4096 + 3*1024 + c*4 + hm] = bfg_[hm];
        }
    }
}

// ---------------- embedding: warp per token, float4 --------------------------
__global__ void __launch_bounds__(256) k_embed(const int* __restrict__ x,
                                               const float* __restrict__ emb){
    int t = blockIdx.x*8 + (threadIdx.x >> 5);
    int lane = threadIdx.x & 31;
    const float4* src = (const float4*)(emb + (size_t)x[t]*Dd);
    float4* dst = (float4*)(g_h + (size_t)t*Dd);
    dst[lane] = src[lane];
}

// ---------------- sLSTM scan: 8 warps/block, 2 batches/warp ------------------
__global__ void __launch_bounds__(256) k_scan(const float* __restrict__ rec,
                                              const float* __restrict__ gn){
    int n  = blockIdx.x & 3;
    int bg = blockIdx.x >> 2;            // 0..31
    int w  = threadIdx.x >> 5;           // 0..7
    int e  = threadIdx.x & 31;
    int b0 = bg*16 + w*2, b1 = b0 + 1;
    __shared__ float rw[4][HDs][36];
    __shared__ float hs[16][HDs];
    for (int idx = threadIdx.x; idx < 4*HDs*HDs; idx += 256){
        int g = idx >> 10, rem = idx & 1023;
        int e2 = rem >> 5, d = rem & 31;
        rw[g][e2][d] = rec[((size_t)(g*NHs+n)*HDs + e2)*HDs + d];
    }
    hs[w*2][e] = 0.0f;
    hs[w*2+1][e] = 0.0f;
    __syncthreads();
    const int gb = n*HDs + e;
    const float gnw = gn[gb];
    const float* gxA = g_big + (size_t)(b0*Ss)*512 + gb;
    const float* gxB = g_big + (size_t)(b1*Ss)*512 + gb;
    float cA=0.f, nnA=0.f, mA=0.f;
    float cB=0.f, nnB=0.f, mB=0.f;
    float r0a = gxA[0], r1a = gxA[Dd], r2a = gxA[2*Dd], r3a = gxA[3*Dd];
    float r0b = gxB[0], r1b = gxB[Dd], r2b = gxB[2*Dd], r3b = gxB[3*Dd];
    for(int s=0;s<Ss;s++){
        float n0a=0.f,n1a=0.f,n2a=0.f,n3a=0.f, n0b=0.f,n1b=0.f,n2b=0.f,n3b=0.f;
        if (s+1 < Ss){
            const float* npA = gxA + (size_t)(s+1)*512;
            const float* npB = gxB + (size_t)(s+1)*512;
            n0a = npA[0]; n1a = npA[Dd]; n2a = npA[2*Dd]; n3a = npA[3*Dd];
            n0b = npB[0]; n1b = npB[Dd]; n2b = npB[2*Dd]; n3b = npB[3*Dd];
        }
        #pragma unroll
        for(int dq=0; dq<8; dq++){
            float4 w0 = *(const float4*)&rw[0][e][dq*4];
            float4 w1 = *(const float4*)&rw[1][e][dq*4];
            float4 w2 = *(const float4*)&rw[2][e][dq*4];
            float4 w3 = *(const float4*)&rw[3][e][dq*4];
            float4 ha = *(const float4*)&hs[w*2][dq*4];
            float4 hb = *(const float4*)&hs[w*2+1][dq*4];
            r0a += ha.x*w0.x + ha.y*w0.y + ha.z*w0.z + ha.w*w0.w;
            r1a += ha.x*w1.x + ha.y*w1.y + ha.z*w1.z + ha.w*w1.w;
            r2a += ha.x*w2.x + ha.y*w2.y + ha.z*w2.z + ha.w*w2.w;
            r3a += ha.x*w3.x + ha.y*w3.y + ha.z*w3.z + ha.w*w3.w;
            r0b += hb.x*w0.x + hb.y*w0.y + hb.z*w0.z + hb.w*w0.w;
            r1b += hb.x*w1.x + hb.y*w1.y + hb.z*w1.z + hb.w*w1.w;
            r2b += hb.x*w2.x + hb.y*w2.y + hb.z*w2.z + hb.w*w2.w;
            r3b += hb.x*w3.x + hb.y*w3.y + hb.z*w3.z + hb.w*w3.w;
        }
        float lfmA = mA + logsigf(r1a);
        float mnA  = fmaxf(r0a, lfmA);
        float iA   = __expf(r0a-mnA);
        float fA   = __expf(lfmA-mnA);
        cA  = fA*cA + iA*tanhfast(r2a);
        nnA = fA*nnA + iA;
        float hA = sigf(r3a) * __fdividef(cA, nnA);
        mA = mnA;

        float lfmB = mB + logsigf(r1b);
        float mnB  = fmaxf(r0b, lfmB);
        float iB   = __expf(r0b-mnB);
        float fB   = __expf(lfmB-mnB);
        cB  = fB*cB + iB*tanhfast(r2b);
        nnB = fB*nnB + iB;
        float hB = sigf(r3b) * __fdividef(cB, nnB);
        mB = mnB;

        __syncwarp();
        hs[w*2][e]   = hA;
        hs[w*2+1][e] = hB;
        __syncwarp();

        float s1 = hA, s2 = hA*hA, t1 = hB, t2 = hB*hB;
        #pragma unroll
        for(int o=16;o;o>>=1){
            s1 += __shfl_xor_sync(~0u,s1,o); s2 += __shfl_xor_sync(~0u,s2,o);
            t1 += __shfl_xor_sync(~0u,t1,o); t2 += __shfl_xor_sync(~0u,t2,o);
        }
        float muA = s1*(1.0f/HDs), varA = s2*(1.0f/HDs)-muA*muA;
        float muB = t1*(1.0f/HDs), varB = t2*(1.0f/HDs)-muB*muB;
        float rrA = rsqrtf(varA + 1e-5f);
        float rrB = rsqrtf(varB + 1e-5f);
        g_h[((size_t)(b0*Ss+s))*Dd + gb] += (hA-muA)*rrA*gnw;
        g_h[((size_t)(b1*Ss+s))*Dd + gb] += (hB-muB)*rrB*gnw;

        r0a = n0a; r1a = n1a; r2a = n2a; r3a = n3a;
        r0b = n0b; r1b = n1b; r2b = n2b; r3b = n3b;
    }
}

// ---------------- fused conv+silu+qkv+gates: 8 tokens per block --------------
__global__ void __launch_bounds__(256) k_cq(
        const float* __restrict__ cw, const float* __restrict__ cb,
        const float* __restrict__ qkvw, const float* __restrict__ gweff,
        const float* __restrict__ igb, const float* __restrict__ fgb){
    __shared__ __align__(16) float xms[11][256];
    __shared__ __align__(16) float xcv[8][256];
    __shared__ float4 Aig[256], Big[256], Afg[256], Bfg[256];
    int blk = blockIdx.x, b = blk>>3, sg = blk&7;
    int tid = threadIdx.x;
    int t0 = b*Ss + sg*8;

    Aig[tid] = *(const float4*)&gweff[0*1024 + tid*4];
    Big[tid] = *(const float4*)&gweff[1*1024 + tid*4];
    Afg[tid] = *(const float4*)&gweff[2*1024 + tid*4];
    Bfg[tid] = *(const float4*)&gweff[3*1024 + tid*4];

    // float4 staging of xms (11 rows x 64 float4)
    for (int idx = tid; idx < 11*64; idx += 256){
        int r = idx >> 6, c4 = idx & 63;
        int s = sg*8 + r - 3;
        float4 v = (s >= 0) ? *(const float4*)&g_big[(size_t)(b*Ss+s)*512 + c4*4]
                            : make_float4(0.f,0.f,0.f,0.f);
        *(float4*)&xms[r][c4*4] = v;
    }
    int c = tid, n = c>>2, o = c&3;
    float cwv0=cw[c*4], cwv1=cw[c*4+1], cwv2=cw[c*4+2], cwv3=cw[c*4+3], cbv=cb[c];
    float wq[4], wk[4], wv[4];
    #pragma unroll
    for (int i2 = 0; i2 < 4; i2++){
        wq[i2] = qkvw[       n*16 + o*4 + i2];
        wk[i2] = qkvw[1024 + n*16 + o*4 + i2];
        wv[i2] = qkvw[2048 + n*16 + o*4 + i2];
    }
    __syncthreads();
    #pragma unroll
    for (int s = 0; s < 8; s++){
        float acc = cbv + xms[s][c]*cwv0 + xms[s+1][c]*cwv1 + xms[s+2][c]*cwv2 + xms[s+3][c]*cwv3;
        float xc = acc*sigf(acc);
        xcv[s][c] = xc;
        g_xconv[(size_t)(t0+s)*256 + c] = xc;
    }
    __syncthreads();
    #pragma unroll
    for (int s = 0; s < 8; s++){
        float4 xc4 = *(const float4*)&xcv[s][n*4];
        float4 xm4 = *(const float4*)&xms[s+3][n*4];
        float q = xc4.x*wq[0] + xc4.y*wq[1] + xc4.z*wq[2] + xc4.w*wq[3];
        float k = xc4.x*wk[0] + xc4.y*wk[1] + xc4.z*wk[2] + xc4.w*wk[3];
        float v = xm4.x*wv[0] + xm4.y*wv[1] + xm4.z*wv[2] + xm4.w*wv[3];
        g_q[(size_t)(t0+s)*256 + c] = q;
        g_k[(size_t)(t0+s)*256 + c] = k;
        g_v[(size_t)(t0+s)*256 + c] = v;
    }
    int w = tid >> 5, lane = tid & 31;
    float4 ia = make_float4(0,0,0,0), fa = make_float4(0,0,0,0);
    for (int j = lane; j < 256; j += 32){
        float xc = xcv[w][j], xm = xms[w+3][j];
        float4 A = Aig[j], B = Big[j], A2 = Afg[j], B2 = Bfg[j];
        ia.x += xc*A.x + xm*B.x;  ia.y += xc*A.y + xm*B.y;
        ia.z += xc*A.z + xm*B.z;  ia.w += xc*A.w + xm*B.w;
        fa.x += xc*A2.x + xm*B2.x; fa.y += xc*A2.y + xm*B2.y;
        fa.z += xc*A2.z + xm*B2.z; fa.w += xc*A2.w + xm*B2.w;
    }
    #pragma unroll
    for (int o2=16;o2;o2>>=1){
        ia.x += __shfl_xor_sync(~0u,ia.x,o2); ia.y += __shfl_xor_sync(~0u,ia.y,o2);
        ia.z += __shfl_xor_sync(~0u,ia.z,o2); ia.w += __shfl_xor_sync(~0u,ia.w,o2);
        fa.x += __shfl_xor_sync(~0u,fa.x,o2); fa.y += __shfl_xor_sync(~0u,fa.y,o2);
        fa.z += __shfl_xor_sync(~0u,fa.z,o2); fa.w += __shfl_xor_sync(~0u,fa.w,o2);
    }
    if (lane == 0){
        int s_ = sg*8 + w;
        g_ig[(size_t)(b*NHMc+0)*Ss + s_] = ia.x + igb[0];
        g_ig[(size_t)(b*NHMc+1)*Ss + s_] = ia.y + igb[1];
        g_ig[(size_t)(b*NHMc+2)*Ss + s_] = ia.z + igb[2];
        g_ig[(size_t)(b*NHMc+3)*Ss + s_] = ia.w + igb[3];
        g_fg[(size_t)(b*NHMc+0)*Ss + s_] = fa.x + fgb[0];
        g_fg[(size_t)(b*NHMc+1)*Ss + s_] = fa.y + fgb[1];
        g_fg[(size_t)(b*NHMc+2)*Ss + s_] = fa.z + fgb[2];
        g_fg[(size_t)(b*NHMc+3)*Ss + s_] = fa.w + fgb[3];
    }
}

// ---------------- mLSTM attention + fused groupnorm/skip/silu combine --------
#define APAD 68
__global__ void __launch_bounds__(256) k_attn(const float* __restrict__ onw,
                                              const float* __restrict__ skip){
    int blk = blockIdx.x; int b = blk >> 2, hm = blk & 3;
    __shared__ __align__(16) float qs[Ss][APAD], ks[Ss][APAD];
    __shared__ __align__(16) float vt[DHMc][APAD];
    __shared__ __align__(16) float cn[8][Ss];
    __shared__ float cldf[Ss+1], igs[Ss];
    int tid = threadIdx.x;
    for (int l = tid; l < Ss*16; l += 256){
        int j = l >> 4, d4 = l & 15;
        size_t base = ((size_t)(b*Ss+j))*INNERc + hm*DHMc + d4*4;
        *(float4*)&qs[j][d4*4] = *(const float4*)&g_q[base];
        *(float4*)&ks[j][d4*4] = *(const float4*)&g_k[base];
        float4 vv = *(const float4*)&g_v[base];
        vt[d4*4+0][j] = vv.x;
        vt[d4*4+1][j] = vv.y;
        vt[d4*4+2][j] = vv.z;
        vt[d4*4+3][j] = vv.w;
    }
    if (tid < Ss){
        igs[tid] = g_ig[(size_t)(b*NHMc+hm)*Ss + tid];
        cldf[tid+1] = logsigf(g_fg[(size_t)(b*NHMc+hm)*Ss + tid]);
    }
    if (tid == 0) cldf[0] = 0.0f;
    __syncthreads();
    for (int off = 1; off < Ss; off <<= 1){
        float add = 0.0f;
        if (tid < Ss && tid >= off) add = cldf[tid+1-off];
        __syncthreads();
        if (tid < Ss && tid >= off) cldf[tid+1] += add;
        __syncthreads();
    }
    int w = tid >> 5, lane = tid & 31;
    int cg0 = hm*DHMc + lane, cg1 = cg0 + 32;
    float onw0 = onw[cg0], onw1 = onw[cg1];
    float sk0 = skip[cg0], sk1 = skip[cg1];
    for(int r=0;r<8;r++){
        int i = r*8 + w;
        int j1 = lane + 32;
        float dot0=0, dot1=0, ld0=-1e30f, ld1=-1e30f;
        if (lane <= i){
            #pragma unroll
            for(int dq=0; dq<16; dq++){
                float4 qv = *(const float4*)&qs[i][dq*4];
                float4 kv = *(const float4*)&ks[lane][dq*4];
                dot0 += qv.x*kv.x + qv.y*kv.y + qv.z*kv.z + qv.w*kv.w;
            }
            ld0 = cldf[i+1]-cldf[lane+1] + igs[lane];
        }
        if (j1 <= i){
            #pragma unroll
            for(int dq=0; dq<16; dq++){
                float4 qv = *(const float4*)&qs[i][dq*4];
                float4 kv = *(const float4*)&ks[j1][dq*4];
                dot1 += qv.x*kv.x + qv.y*kv.y + qv.z*kv.z + qv.w*kv.w;
            }
            ld1 = cldf[i+1]-cldf[j1+1] + igs[j1];
        }
        float mx = fmaxf(ld0, ld1);
        #pragma unroll
        for(int o=16;o;o>>=1) mx = fmaxf(mx, __shfl_xor_sync(~0u,mx,o));
        float cm0 = (lane <= i) ? dot0*0.125f*__expf(ld0-mx) : 0.0f;
        float cm1 = (j1   <= i) ? dot1*0.125f*__expf(ld1-mx) : 0.0f;
        float sm = cm0 + cm1;
        #pragma unroll
        for(int o=16;o;o>>=1) sm += __shfl_xor_sync(~0u,sm,o);
        float norm = fmaxf(fabsf(sm), __expf(-mx)) + 1e-6f;
        float rnorm = __fdividef(1.0f, norm);
        cn[w][lane] = cm0*rnorm;
        cn[w][j1]   = cm1*rnorm;
        __syncwarp();
        float a0=0, a1=0;
        int jend = (i & ~3) + 4;
        for(int j4=0; j4<jend; j4+=4){
            float4 cc = *(const float4*)&cn[w][j4];
            float4 va = *(const float4*)&vt[lane][j4];
            float4 vb = *(const float4*)&vt[lane+32][j4];
            a0 += cc.x*va.x + cc.y*va.y + cc.z*va.z + cc.w*va.w;
            a1 += cc.x*vb.x + cc.y*vb.y + cc.z*vb.z + cc.w*vb.w;
        }
        float s1 = a0+a1, s2 = a0*a0+a1*a1;
        #pragma unroll
        for(int o=16;o;o>>=1){ s1 += __shfl_xor_sync(~0u,s1,o); s2 += __shfl_xor_sync(~0u,s2,o); }
        float mu = s1*(1.0f/DHMc), var = s2*(1.0f/DHMc)-mu*mu;
        float rr = rsqrtf(var + 1e-5f);
        size_t t = (size_t)(b*Ss+i);
        float z0 = g_big[t*512 + 256 + cg0], z1 = g_big[t*512 + 256 + cg1];
        float x0 = g_xconv[t*256 + cg0],     x1 = g_xconv[t*256 + cg1];
        g_q[t*256 + cg0] = ((a0-mu)*rr*onw0 + sk0*x0) * z0*sigf(z0);
        g_q[t*256 + cg1] = ((a1-mu)*rr*onw1 + sk1*x1) * z1*sigf(z1);
        __syncwarp();
    }
}

// ---------------- host-side --------------------------------------------------
static float* symf(const void* s){ void* p=nullptr; cudaGetSymbolAddress(&p, s); return (float*)p; }

extern "C" void kernel_launch(void* const* d_in, const int* in_sizes, int n_in,
                              void* d_out, int out_size){
    const int*   x         = (const int*)  d_in[0];
    const float* embed     = (const float*)d_in[1];
    const float* s_ln1     = (const float*)d_in[2];
    const float* s_gates_w = (const float*)d_in[3];
    const float* s_rec     = (const float*)d_in[4];
    const float* s_bias    = (const float*)d_in[5];
    const float* s_gn      = (const float*)d_in[6];
    const float* s_ln2     = (const float*)d_in[7];
    const float* s_ff_up   = (const float*)d_in[8];
    const float* s_ff_down = (const float*)d_in[9];
    const float* m_ln1     = (const float*)d_in[10];
    const float* m_up      = (const float*)d_in[11];
    const float* m_conv_w  = (const float*)d_in[12];
    const float* m_conv_b  = (const float*)d_in[13];
    const float* m_qkv_w   = (const float*)d_in[14];
    const float* m_ig_w    = (const float*)d_in[15];
    const float* m_ig_b    = (const float*)d_in[16];
    const float* m_fg_w    = (const float*)d_in[17];
    const float* m_fg_b    = (const float*)d_in[18];
    const float* m_skip    = (const float*)d_in[19];
    const float* m_onorm   = (const float*)d_in[20];
    const float* m_down    = (const float*)d_in[21];
    const float* m_ln2     = (const float*)d_in[22];
    const float* m_ff_up   = (const float*)d_in[23];
    const float* m_ff_down = (const float*)d_in[24];
    const float* post_ln   = (const float*)d_in[25];
    const float* head_w    = (const float*)d_in[26];
    const float* head_b    = (const float*)d_in[27];

    float* h    = symf(g_h);
    float* big  = symf(g_big);
    float* ffn  = symf(g_ffn);
    float* qb   = symf(g_q);
    float* gweff= symf(g_gw_eff);

    float* out = (float*)d_out;

    cudaFuncSetAttribute(k_mgemm<false,true ,true ,false,8,false>, cudaFuncAttributeMaxDynamicSharedMemorySize, MG_SMEM);
    cudaFuncSetAttribute(k_mgemm<false,false,true ,false,8,false>, cudaFuncAttributeMaxDynamicSharedMemorySize, MG_SMEM);
    cudaFuncSetAttribute(k_mgemm<false,false,true ,false,4,false>, cudaFuncAttributeMaxDynamicSharedMemorySize, MG_SMEM);
    cudaFuncSetAttribute(k_mgemm<true ,false,false,true ,2,false>, cudaFuncAttributeMaxDynamicSharedMemorySize, MG_SMEM);
    cudaFuncSetAttribute(k_mgemm<true ,false,false,false,2,true >, cudaFuncAttributeMaxDynamicSharedMemorySize, MG_SMEM);
    cudaFuncSetAttribute(k_mgemm<false,true ,true ,false,4,false>, cudaFuncAttributeMaxDynamicSharedMemorySize, MG_SMEM);

    k_prep<<<546,256>>>(
        s_gates_w, s_gates_w + (size_t)4*NHs*HDs*HDs,
        s_ff_up, s_ff_down, m_up, m_down, m_ff_up, m_ff_down,
        s_ff_up + (size_t)Dd*2*FFc, s_ff_down + (size_t)FFc*Dd,
        m_up + (size_t)Dd*2*INNERc, m_down + (size_t)INNERc*Dd,
        m_ff_up + (size_t)Dd*2*FFc, m_ff_down + (size_t)FFc*Dd,
        head_w, m_qkv_w, m_ig_w, m_fg_w);
    k_embed<<<Tt/8, 256>>>(x, embed);

    for(int i=0;i<2;i++){
        // ---- sLSTM ----
        k_mgemm<false,true,true,false,8,false><<<dim3(1, Tt/128),256,MG_SMEM>>>(
            h, big, s_bias + i*4*Dd, s_ln1 + i*Dd, W_SGX(i), 4*Dd, Dd);
        k_scan<<<NHs*(Bb/16),256>>>(s_rec + (size_t)i*4*NHs*HDs*HDs, s_gn + i*Dd);

        // ---- FFN 1 ----
        k_mgemm<false,false,true,false,4,false><<<dim3(1, Tt/128),256,MG_SMEM>>>(
            h, ffn, nullptr, s_ln2 + i*Dd, W_SFU(i), 2*FFc, Dd);
        k_mgemm<true,false,false,true,2,false><<<dim3(1, Tt/128),256,MG_SMEM>>>(
            ffn, h, nullptr, nullptr, W_SFD(i), Dd, FFc);

        // ---- mLSTM ----
        k_mgemm<false,false,true,false,8,false><<<dim3(1, Tt/128),256,MG_SMEM>>>(
            h, big, nullptr, m_ln1 + i*Dd, W_MUP(i), 2*INNERc, Dd);
        k_cq<<<Bb*8,256>>>(m_conv_w + (size_t)i*INNERc*Kc, m_conv_b + i*INNERc,
                           m_qkv_w + (size_t)i*3072, gweff + i*4096,
                           m_ig_b + i*NHMc, m_fg_b + i*NHMc);
        k_attn<<<Bb*NHMc,256>>>(m_onorm + i*INNERc, m_skip + i*INNERc);
        k_mgemm<true,false,false,false,2,true><<<dim3(1, Tt/128),256,MG_SMEM>>>(
            qb, h, nullptr, nullptr, W_MDN(i), Dd, INNERc);

        // ---- FFN 2 ----
        k_mgemm<false,false,true,false,4,false><<<dim3(1, Tt/128),256,MG_SMEM>>>(
            h, ffn, nullptr, m_ln2 + i*Dd, W_MFU(i), 2*FFc, Dd);
        k_mgemm<true,false,false,true,2,false><<<dim3(1, Tt/128),256,MG_SMEM>>>(
            ffn, h, nullptr, nullptr, W_MFD(i), Dd, FFc);
    }

    // ---- final LN + head ----
    k_mgemm<false,true,true,false,4,false><<<dim3(1, Tt/128),256,MG_SMEM>>>(
        h, out, head_b, post_ln, W_HEAD, Vv, Dd);
}